// round 2
// baseline (speedup 1.0000x reference)
#include <cuda_runtime.h>
#include <math.h>

// Problem constants
#define LNUM 4
#define DM   1024
#define HN   16
#define DH   64
#define FFN  4096
#define VN   8192
#define BN   4
#define QN   512
#define MN   512
#define EN   512
#define KLEN 1024   // M + Q

// ---------------- scratch (device globals; no allocation) ----------------
__device__ float g_x   [BN*QN*DM];     // residual stream [B*Q, D]
__device__ float g_mem [BN*KLEN*DM];   // concat(mems[l], x) [B*klen, D]
__device__ float g_q   [BN*QN*DM];
__device__ float g_k   [BN*KLEN*DM];
__device__ float g_v   [BN*KLEN*DM];
__device__ float g_r   [KLEN*DM];
__device__ float g_remb[KLEN*DM];
__device__ float g_att [BN*QN*DM];
__device__ float g_tmp [BN*QN*DM];
__device__ float g_ff  [BN*QN*FFN];

// ---------------- elementwise kernels ----------------
__global__ void embed_kernel(const int* __restrict__ ids,
                             const float* __restrict__ emb,
                             float* __restrict__ x) {
    int idx = blockIdx.x * blockDim.x + threadIdx.x;   // over B*Q*D
    if (idx >= BN*QN*DM) return;
    int row = idx / DM;
    int d   = idx - row * DM;
    int tok = ids[row];
    x[idx] = emb[tok * DM + d] * 32.0f;                // sqrt(D) = 32
}

__global__ void remb_kernel(float* __restrict__ remb) {
    int idx = blockIdx.x * blockDim.x + threadIdx.x;   // over KLEN*D
    if (idx >= KLEN*DM) return;
    int p = idx / DM;
    int d = idx - p * DM;
    float pos = (float)(KLEN - 1 - p);
    int k = (d < DM/2) ? d : d - DM/2;
    float invf = powf(10000.0f, -(float)k / (float)(DM/2));
    float a = pos * invf;
    remb[idx] = (d < DM/2) ? sinf(a) : cosf(a);
}

__global__ void concat_kernel(const float* __restrict__ mems_l,
                              const float* __restrict__ x,
                              float* __restrict__ mem) {
    int idx = blockIdx.x * blockDim.x + threadIdx.x;   // over B*KLEN*D
    if (idx >= BN*KLEN*DM) return;
    int d   = idx % DM;
    int rem = idx / DM;
    int j   = rem % KLEN;
    int b   = rem / KLEN;
    float val;
    if (j < MN) val = mems_l[(b*MN + j)*DM + d];
    else        val = x[(b*QN + (j - MN))*DM + d];
    mem[idx] = val;
}

// ---------------- SGEMM: C[N,K] = A[N,D] @ B[D,K] (+bias, optional GELU) ----
// All dims: N,K multiples of 128, D multiple of 8.
template<bool GELU>
__global__ __launch_bounds__(256)
void sgemm_kernel(const float* __restrict__ A, const float* __restrict__ B,
                  const float* __restrict__ bias, float* __restrict__ C,
                  int N, int D, int K) {
    __shared__ float As[8][128];
    __shared__ float Bs[8][128];
    const int tid = threadIdx.x;
    const int row0 = blockIdx.y * 128;
    const int col0 = blockIdx.x * 128;
    const int tx = tid & 15;        // 16 cols of threads
    const int ty = tid >> 4;        // 16 rows of threads

    // A tile load mapping: 128 rows x 8 k = 256 float4
    const int a_row = tid >> 1;
    const int a_k   = (tid & 1) * 4;
    // B tile load mapping: 8 rows x 128 cols = 256 float4
    const int b_row = tid >> 5;
    const int b_col = (tid & 31) * 4;

    const float* Ap = A + (size_t)(row0 + a_row) * D + a_k;
    const float* Bp = B + (size_t)b_row * K + col0 + b_col;

    float acc[8][8];
    #pragma unroll
    for (int i = 0; i < 8; i++)
        #pragma unroll
        for (int j = 0; j < 8; j++) acc[i][j] = 0.0f;

    for (int k0 = 0; k0 < D; k0 += 8) {
        float4 av = *(const float4*)(Ap + k0);
        As[a_k+0][a_row] = av.x;
        As[a_k+1][a_row] = av.y;
        As[a_k+2][a_row] = av.z;
        As[a_k+3][a_row] = av.w;
        *(float4*)&Bs[b_row][b_col] = *(const float4*)(Bp + (size_t)k0 * K);
        __syncthreads();

        #pragma unroll
        for (int kk = 0; kk < 8; kk++) {
            float a[8], b[8];
            const float4* av0 = (const float4*)&As[kk][ty*8];
            const float4* bv0 = (const float4*)&Bs[kk][tx*8];
            float4 a0 = av0[0], a1 = av0[1];
            float4 b0 = bv0[0], b1 = bv0[1];
            a[0]=a0.x; a[1]=a0.y; a[2]=a0.z; a[3]=a0.w;
            a[4]=a1.x; a[5]=a1.y; a[6]=a1.z; a[7]=a1.w;
            b[0]=b0.x; b[1]=b0.y; b[2]=b0.z; b[3]=b0.w;
            b[4]=b1.x; b[5]=b1.y; b[6]=b1.z; b[7]=b1.w;
            #pragma unroll
            for (int i = 0; i < 8; i++)
                #pragma unroll
                for (int j = 0; j < 8; j++)
                    acc[i][j] = fmaf(a[i], b[j], acc[i][j]);
        }
        __syncthreads();
    }

    #pragma unroll
    for (int i = 0; i < 8; i++) {
        int r = row0 + ty*8 + i;
        #pragma unroll
        for (int j = 0; j < 8; j++) {
            int c = col0 + tx*8 + j;
            float val = acc[i][j];
            if (bias) val += bias[c];
            if (GELU) val = 0.5f * val * (1.0f + erff(val * 0.70710678118654752f));
            C[(size_t)r * K + c] = val;
        }
    }
}

// ---------------- fused attention ----------------
// One block per (query i, head h, batch b).  256 threads.
// Computes score row (AC + relative-shifted BD), softmax, PV product.
// r == nullptr -> no relative term (cross-attention); maskM < 0 -> no causal mask.
__global__ __launch_bounds__(256)
void attn_kernel(const float* __restrict__ q,   // [B*Q, D]
                 const float* __restrict__ k,   // [B*klen, D]
                 const float* __restrict__ v,   // [B*klen, D]
                 const float* __restrict__ r,   // [klen, D] or null
                 const float* __restrict__ uvec,// [H*DH] or null
                 const float* __restrict__ vvec,// [H*DH] or null
                 float* __restrict__ out,       // [B*Q, D]
                 int klen, int maskM) {
    const int i = blockIdx.x;         // query index (gridDim.x == Q)
    const int h = blockIdx.y;
    const int b = blockIdx.z;
    const int tid = threadIdx.x;

    __shared__ float qu[DH];
    __shared__ float qv[DH];
    __shared__ float sc[KLEN];
    __shared__ float red[256];
    __shared__ float part[4][DH];

    const float* qrow = q + ((size_t)(b*QN + i))*DM + h*DH;
    if (tid < DH) {
        float qd = qrow[tid];
        qu[tid] = qd + (uvec ? uvec[h*DH + tid] : 0.0f);
        qv[tid] = r ? (qd + vvec[h*DH + tid]) : 0.0f;
    }
    __syncthreads();

    const int len = (maskM >= 0) ? min(klen, i + maskM + 1) : klen;
    const float scale = 0.125f;      // DH^-0.5

    for (int j = tid; j < klen; j += 256) {
        float s;
        if (j < len) {
            const float4* k4 = (const float4*)(k + ((size_t)(b*klen + j))*DM + h*DH);
            float acc = 0.0f;
            #pragma unroll
            for (int d4 = 0; d4 < DH/4; d4++) {
                float4 kv = k4[d4];
                acc += qu[d4*4+0]*kv.x + qu[d4*4+1]*kv.y
                     + qu[d4*4+2]*kv.z + qu[d4*4+3]*kv.w;
            }
            if (r) {
                int jr = j - i + (QN - 1);          // rel_shift gather, always in [0,klen)
                const float4* r4 = (const float4*)(r + (size_t)jr*DM + h*DH);
                #pragma unroll
                for (int d4 = 0; d4 < DH/4; d4++) {
                    float4 rv = r4[d4];
                    acc += qv[d4*4+0]*rv.x + qv[d4*4+1]*rv.y
                         + qv[d4*4+2]*rv.z + qv[d4*4+3]*rv.w;
                }
            }
            s = acc * scale;
        } else {
            s = -INFINITY;
        }
        sc[j] = s;
    }
    __syncthreads();

    // max reduce
    float m = -INFINITY;
    for (int j = tid; j < klen; j += 256) m = fmaxf(m, sc[j]);
    red[tid] = m;
    __syncthreads();
    for (int s = 128; s > 0; s >>= 1) {
        if (tid < s) red[tid] = fmaxf(red[tid], red[tid+s]);
        __syncthreads();
    }
    m = red[0];
    __syncthreads();

    // exp + sum reduce
    float sum = 0.0f;
    for (int j = tid; j < klen; j += 256) {
        float e = __expf(sc[j] - m);
        sc[j] = e;
        sum += e;
    }
    red[tid] = sum;
    __syncthreads();
    for (int s = 128; s > 0; s >>= 1) {
        if (tid < s) red[tid] += red[tid+s];
        __syncthreads();
    }
    const float inv = 1.0f / red[0];
    __syncthreads();

    // PV: 4 groups of 64 threads split the j range; lane d within group
    const int g = tid >> 6;
    const int d = tid & 63;
    const int chunk = klen >> 2;
    const int j0 = g * chunk, j1 = j0 + chunk;
    float acc = 0.0f;
    for (int j = j0; j < j1; j++)
        acc += sc[j] * v[((size_t)(b*klen + j))*DM + h*DH + d];
    part[g][d] = acc;
    __syncthreads();
    if (g == 0) {
        float o = (part[0][d] + part[1][d] + part[2][d] + part[3][d]) * inv;
        out[((size_t)(b*QN + i))*DM + h*DH + d] = o;
    }
}

// ---------------- residual add + LayerNorm ----------------
// x = LN(x + y) * gamma + beta ; one block per row (D = 1024), 256 threads.
__global__ __launch_bounds__(256)
void ln_kernel(float* __restrict__ x, const float* __restrict__ y,
               const float* __restrict__ gamma, const float* __restrict__ beta) {
    const int row = blockIdx.x;
    const int tid = threadIdx.x;
    __shared__ float red[256];

    float s[4];
    float local = 0.0f;
    #pragma unroll
    for (int kk = 0; kk < 4; kk++) {
        int c = tid + kk*256;
        float val = x[(size_t)row*DM + c] + y[(size_t)row*DM + c];
        s[kk] = val;
        local += val;
    }
    red[tid] = local;
    __syncthreads();
    for (int t = 128; t > 0; t >>= 1) {
        if (tid < t) red[tid] += red[tid+t];
        __syncthreads();
    }
    const float mu = red[0] * (1.0f / DM);
    __syncthreads();

    local = 0.0f;
    #pragma unroll
    for (int kk = 0; kk < 4; kk++) {
        float dlt = s[kk] - mu;
        local += dlt * dlt;
    }
    red[tid] = local;
    __syncthreads();
    for (int t = 128; t > 0; t >>= 1) {
        if (tid < t) red[tid] += red[tid+t];
        __syncthreads();
    }
    const float rstd = rsqrtf(red[0] * (1.0f / DM) + 1e-5f);
    __syncthreads();

    #pragma unroll
    for (int kk = 0; kk < 4; kk++) {
        int c = tid + kk*256;
        x[(size_t)row*DM + c] = (s[kk] - mu) * rstd * gamma[c] + beta[c];
    }
}

// ---------------- host orchestration ----------------
static inline void run_gemm(const float* A, const float* B, const float* bias,
                            float* C, int N, int D, int K, bool gelu) {
    dim3 grid(K/128, N/128);
    if (gelu) sgemm_kernel<true ><<<grid, 256>>>(A, B, bias, C, N, D, K);
    else      sgemm_kernel<false><<<grid, 256>>>(A, B, bias, C, N, D, K);
}

extern "C" void kernel_launch(void* const* d_in, const int* in_sizes, int n_in,
                              void* d_out, int out_size) {
    const float* enc    = (const float*)d_in[0];    // [B,E,D]
    const float* mems   = (const float*)d_in[1];    // [L,B,M,D]
    const float* emb    = (const float*)d_in[2];    // [V,D]
    const float* u      = (const float*)d_in[3];    // [H,DH]
    const float* vpar   = (const float*)d_in[4];    // [H,DH]
    const float* saWq   = (const float*)d_in[5];
    const float* saWk   = (const float*)d_in[6];
    const float* saWv   = (const float*)d_in[7];
    const float* saWr   = (const float*)d_in[8];
    const float* safcW  = (const float*)d_in[9];
    const float* safcB  = (const float*)d_in[10];
    const float* ln1g   = (const float*)d_in[11];
    const float* ln1b   = (const float*)d_in[12];
    const float* caWq   = (const float*)d_in[13];
    const float* caWk   = (const float*)d_in[14];
    const float* caWv   = (const float*)d_in[15];
    const float* cafcW  = (const float*)d_in[16];
    const float* cafcB  = (const float*)d_in[17];
    const float* ln2g   = (const float*)d_in[18];
    const float* ln2b   = (const float*)d_in[19];
    const float* ffW1   = (const float*)d_in[20];
    const float* ffb1   = (const float*)d_in[21];
    const float* ffW2   = (const float*)d_in[22];
    const float* ffb2   = (const float*)d_in[23];
    const float* ln3g   = (const float*)d_in[24];
    const float* ln3b   = (const float*)d_in[25];
    const float* outW   = (const float*)d_in[26];   // [D,V]
    const int*   ids    = (const int*)  d_in[27];   // [B,Q]
    float* out = (float*)d_out;

    float *x, *memb, *qb, *kb, *vb, *rb, *remb, *att, *tmp, *ff;
    cudaGetSymbolAddress((void**)&x,    g_x);
    cudaGetSymbolAddress((void**)&memb, g_mem);
    cudaGetSymbolAddress((void**)&qb,   g_q);
    cudaGetSymbolAddress((void**)&kb,   g_k);
    cudaGetSymbolAddress((void**)&vb,   g_v);
    cudaGetSymbolAddress((void**)&rb,   g_r);
    cudaGetSymbolAddress((void**)&remb, g_remb);
    cudaGetSymbolAddress((void**)&att,  g_att);
    cudaGetSymbolAddress((void**)&tmp,  g_tmp);
    cudaGetSymbolAddress((void**)&ff,   g_ff);

    // embedding + positional encodings
    embed_kernel<<<(BN*QN*DM + 255)/256, 256>>>(ids, emb, x);
    remb_kernel <<<(KLEN*DM + 255)/256, 256>>>(remb);

    dim3 attn_grid(QN, HN, BN);

    for (int l = 0; l < LNUM; l++) {
        // ---- self-attention (TransformerXL relative) ----
        concat_kernel<<<(BN*KLEN*DM + 255)/256, 256>>>(
            mems + (size_t)l*BN*MN*DM, x, memb);

        run_gemm(x,    saWq + (size_t)l*DM*DM, nullptr, qb, BN*QN,  DM, DM, false);
        run_gemm(memb, saWk + (size_t)l*DM*DM, nullptr, kb, BN*KLEN,DM, DM, false);
        run_gemm(memb, saWv + (size_t)l*DM*DM, nullptr, vb, BN*KLEN,DM, DM, false);
        run_gemm(remb, saWr + (size_t)l*DM*DM, nullptr, rb, KLEN,   DM, DM, false);

        attn_kernel<<<attn_grid, 256>>>(qb, kb, vb, rb, u, vpar, att, KLEN, MN);

        run_gemm(att, safcW + (size_t)l*DM*DM, safcB + (size_t)l*DM,
                 tmp, BN*QN, DM, DM, false);
        ln_kernel<<<BN*QN, 256>>>(x, tmp, ln1g + (size_t)l*DM, ln1b + (size_t)l*DM);

        // ---- cross-attention ----
        run_gemm(x,   caWq + (size_t)l*DM*DM, nullptr, qb, BN*QN, DM, DM, false);
        run_gemm(enc, caWk + (size_t)l*DM*DM, nullptr, kb, BN*EN, DM, DM, false);
        run_gemm(enc, caWv + (size_t)l*DM*DM, nullptr, vb, BN*EN, DM, DM, false);

        attn_kernel<<<attn_grid, 256>>>(qb, kb, vb, nullptr, nullptr, nullptr,
                                        att, EN, -1);

        run_gemm(att, cafcW + (size_t)l*DM*DM, cafcB + (size_t)l*DM,
                 tmp, BN*QN, DM, DM, false);
        ln_kernel<<<BN*QN, 256>>>(x, tmp, ln2g + (size_t)l*DM, ln2b + (size_t)l*DM);

        // ---- feed-forward ----
        run_gemm(x,  ffW1 + (size_t)l*DM*FFN, ffb1 + (size_t)l*FFN,
                 ff, BN*QN, DM, FFN, true);                       // fused exact GELU
        run_gemm(ff, ffW2 + (size_t)l*FFN*DM, ffb2 + (size_t)l*DM,
                 tmp, BN*QN, FFN, DM, false);
        ln_kernel<<<BN*QN, 256>>>(x, tmp, ln3g + (size_t)l*DM, ln3b + (size_t)l*DM);
    }

    // ---- output projection [B*Q, D] @ [D, V] ----
    run_gemm(x, outW, nullptr, out, BN*QN, DM, VN, false);
}

// round 4
// speedup vs baseline: 5.6762x; 5.6762x over previous
#include <cuda_runtime.h>
#include <math.h>

// Problem constants
#define LNUM 4
#define DM   1024
#define HN   16
#define DH   64
#define FFN  4096
#define VN   8192
#define BN   4
#define QN   512
#define MN   512
#define EN   512
#define KLEN 1024   // M + Q

// ---------------- scratch (device globals; no allocation) ----------------
__device__ float g_x   [BN*QN*DM];
__device__ float g_mem [BN*KLEN*DM];
__device__ float g_q   [BN*QN*DM];
__device__ float g_k   [BN*KLEN*DM];
__device__ float g_v   [BN*KLEN*DM];
__device__ float g_r   [KLEN*DM];
__device__ float g_remb[KLEN*DM];
__device__ float g_att [BN*QN*DM];
__device__ float g_tmp [BN*QN*DM];
__device__ float g_ff  [BN*QN*FFN];
__device__ float g_bd  [BN*HN*QN*KLEN];   // relative-position BD_raw, 128MB

// ---------------- elementwise kernels ----------------
__global__ void embed_kernel(const int* __restrict__ ids,
                             const float* __restrict__ emb,
                             float* __restrict__ x) {
    int idx = blockIdx.x * blockDim.x + threadIdx.x;
    if (idx >= BN*QN*DM) return;
    int row = idx / DM;
    int d   = idx - row * DM;
    int tok = ids[row];
    x[idx] = emb[tok * DM + d] * 32.0f;
}

__global__ void remb_kernel(float* __restrict__ remb) {
    int idx = blockIdx.x * blockDim.x + threadIdx.x;
    if (idx >= KLEN*DM) return;
    int p = idx / DM;
    int d = idx - p * DM;
    float pos = (float)(KLEN - 1 - p);
    int k = (d < DM/2) ? d : d - DM/2;
    float invf = powf(10000.0f, -(float)k / (float)(DM/2));
    float a = pos * invf;
    remb[idx] = (d < DM/2) ? sinf(a) : cosf(a);
}

__global__ void concat_kernel(const float* __restrict__ mems_l,
                              const float* __restrict__ x,
                              float* __restrict__ mem) {
    int idx = blockIdx.x * blockDim.x + threadIdx.x;
    if (idx >= BN*KLEN*DM) return;
    int d   = idx % DM;
    int rem = idx / DM;
    int j   = rem % KLEN;
    int b   = rem / KLEN;
    float val;
    if (j < MN) val = mems_l[(b*MN + j)*DM + d];
    else        val = x[(b*QN + (j - MN))*DM + d];
    mem[idx] = val;
}

// ---------------- tf32 tensor-core GEMM ----------------
// C[N,K] = A[N,D] @ B[D,K] (+bias, optional GELU). N,K mult of 128, D mult 16.
__device__ __forceinline__ unsigned f2tf(float x) {
    unsigned u; asm("cvt.rna.tf32.f32 %0, %1;" : "=r"(u) : "f"(x)); return u;
}
__device__ __forceinline__ float tfv(float x) { return __uint_as_float(f2tf(x)); }

template<bool GELU>
__global__ __launch_bounds__(256)
void mm_tf32(const float* __restrict__ A, const float* __restrict__ B,
             const float* __restrict__ bias, float* __restrict__ C,
             int N, int D, int K) {
    __shared__ float As[2][128][20];   // [m][k] pad 20 -> conflict-free frags
    __shared__ float Bs[2][16][136];   // [k][n] pad 136 -> conflict-free frags
    const int tid  = threadIdx.x;
    const int row0 = blockIdx.y * 128, col0 = blockIdx.x * 128;
    const int lane = tid & 31, wid = tid >> 5;
    const int grp  = lane >> 2, t4 = lane & 3;
    const int wm   = (wid & 3) * 32, wn = (wid >> 2) * 64;

    const int ar = tid >> 2, ak = (tid & 3) * 4;   // A loader: rows ar, ar+64
    const int bk = tid >> 5, bc = (tid & 31) * 4;  // B loader: k rows bk, bk+8

    float c[2][8][4];
    #pragma unroll
    for (int i = 0; i < 2; i++)
        #pragma unroll
        for (int j = 0; j < 8; j++)
            #pragma unroll
            for (int t = 0; t < 4; t++) c[i][j][t] = 0.0f;

    // initial fill of buffer 0
    {
        float4 a0 = *(const float4*)&A[(size_t)(row0+ar)*D + ak];
        float4 a1 = *(const float4*)&A[(size_t)(row0+ar+64)*D + ak];
        float4 b0 = *(const float4*)&B[(size_t)bk*K + col0 + bc];
        float4 b1 = *(const float4*)&B[(size_t)(bk+8)*K + col0 + bc];
        *(float4*)&As[0][ar][ak]    = make_float4(tfv(a0.x),tfv(a0.y),tfv(a0.z),tfv(a0.w));
        *(float4*)&As[0][ar+64][ak] = make_float4(tfv(a1.x),tfv(a1.y),tfv(a1.z),tfv(a1.w));
        *(float4*)&Bs[0][bk][bc]    = make_float4(tfv(b0.x),tfv(b0.y),tfv(b0.z),tfv(b0.w));
        *(float4*)&Bs[0][bk+8][bc]  = make_float4(tfv(b1.x),tfv(b1.y),tfv(b1.z),tfv(b1.w));
    }
    __syncthreads();

    const int KT = D >> 4;
    int cur = 0;
    for (int kt = 0; kt < KT; kt++) {
        float4 pa0, pa1, pb0, pb1;
        const bool more = (kt + 1 < KT);
        if (more) {
            int k0 = (kt + 1) * 16;
            pa0 = *(const float4*)&A[(size_t)(row0+ar)*D + k0 + ak];
            pa1 = *(const float4*)&A[(size_t)(row0+ar+64)*D + k0 + ak];
            pb0 = *(const float4*)&B[(size_t)(k0+bk)*K + col0 + bc];
            pb1 = *(const float4*)&B[(size_t)(k0+bk+8)*K + col0 + bc];
        }
        #pragma unroll
        for (int kk = 0; kk < 16; kk += 8) {
            unsigned a[2][4], bf[8][2];
            #pragma unroll
            for (int mt = 0; mt < 2; mt++) {
                int m = wm + mt*16 + grp;
                a[mt][0] = __float_as_uint(As[cur][m  ][kk+t4  ]);
                a[mt][1] = __float_as_uint(As[cur][m+8][kk+t4  ]);
                a[mt][2] = __float_as_uint(As[cur][m  ][kk+t4+4]);
                a[mt][3] = __float_as_uint(As[cur][m+8][kk+t4+4]);
            }
            #pragma unroll
            for (int nt = 0; nt < 8; nt++) {
                int n = wn + nt*8 + grp;
                bf[nt][0] = __float_as_uint(Bs[cur][kk+t4  ][n]);
                bf[nt][1] = __float_as_uint(Bs[cur][kk+t4+4][n]);
            }
            #pragma unroll
            for (int mt = 0; mt < 2; mt++)
                #pragma unroll
                for (int nt = 0; nt < 8; nt++)
                    asm volatile(
                        "mma.sync.aligned.m16n8k8.row.col.f32.tf32.tf32.f32 "
                        "{%0,%1,%2,%3}, {%4,%5,%6,%7}, {%8,%9}, {%0,%1,%2,%3};"
                        : "+f"(c[mt][nt][0]), "+f"(c[mt][nt][1]),
                          "+f"(c[mt][nt][2]), "+f"(c[mt][nt][3])
                        : "r"(a[mt][0]), "r"(a[mt][1]), "r"(a[mt][2]), "r"(a[mt][3]),
                          "r"(bf[nt][0]), "r"(bf[nt][1]));
        }
        if (more) {
            int nxt = cur ^ 1;
            *(float4*)&As[nxt][ar][ak]    = make_float4(tfv(pa0.x),tfv(pa0.y),tfv(pa0.z),tfv(pa0.w));
            *(float4*)&As[nxt][ar+64][ak] = make_float4(tfv(pa1.x),tfv(pa1.y),tfv(pa1.z),tfv(pa1.w));
            *(float4*)&Bs[nxt][bk][bc]    = make_float4(tfv(pb0.x),tfv(pb0.y),tfv(pb0.z),tfv(pb0.w));
            *(float4*)&Bs[nxt][bk+8][bc]  = make_float4(tfv(pb1.x),tfv(pb1.y),tfv(pb1.z),tfv(pb1.w));
        }
        __syncthreads();
        cur ^= 1;
    }

    #pragma unroll
    for (int mt = 0; mt < 2; mt++)
        #pragma unroll
        for (int nt = 0; nt < 8; nt++) {
            int r  = row0 + wm + mt*16 + grp;
            int cc = col0 + wn + nt*8 + t4*2;
            #pragma unroll
            for (int half = 0; half < 2; half++) {
                int rr = r + half*8;
                #pragma unroll
                for (int e = 0; e < 2; e++) {
                    float val = c[mt][nt][half*2 + e];
                    int col = cc + e;
                    if (bias) val += bias[col];
                    if (GELU) val = 0.5f*val*(1.0f + erff(val*0.70710678118654752f));
                    C[(size_t)rr*K + col] = val;
                }
            }
        }
}

// ---------------- BD_raw batched GEMM (scalar fp32, NT) ----------------
// bdout[b,h,i,t] = sum_d (q[b,i,h,d] + vvec[h,d]) * r[t,h,d]
__global__ __launch_bounds__(256)
void bd_kernel(const float* __restrict__ q, const float* __restrict__ r,
               const float* __restrict__ vvec, float* __restrict__ bdout) {
    __shared__ float Qv[64][65];
    __shared__ float Rs[64][65];
    const int t0 = blockIdx.x*64, i0 = blockIdx.y*64;
    const int h = blockIdx.z & (HN-1), b = blockIdx.z >> 4;
    const int tid = threadIdx.x;

    #pragma unroll
    for (int t = 0; t < 4; t++) {
        int idx = tid + 256*t;
        int row = idx >> 4, c4 = (idx & 15)*4;
        float4 qq = *(const float4*)&q[((size_t)(b*QN + i0 + row))*DM + h*DH + c4];
        qq.x += vvec[h*DH + c4 + 0];
        qq.y += vvec[h*DH + c4 + 1];
        qq.z += vvec[h*DH + c4 + 2];
        qq.w += vvec[h*DH + c4 + 3];
        Qv[row][c4+0]=qq.x; Qv[row][c4+1]=qq.y; Qv[row][c4+2]=qq.z; Qv[row][c4+3]=qq.w;
        float4 rr = *(const float4*)&r[((size_t)(t0 + row))*DM + h*DH + c4];
        Rs[row][c4+0]=rr.x; Rs[row][c4+1]=rr.y; Rs[row][c4+2]=rr.z; Rs[row][c4+3]=rr.w;
    }
    __syncthreads();

    const int tr = tid >> 4, tc = tid & 15;
    float acc[4][4];
    #pragma unroll
    for (int i = 0; i < 4; i++)
        #pragma unroll
        for (int j = 0; j < 4; j++) acc[i][j] = 0.0f;

    for (int d = 0; d < 64; d++) {
        float qv0 = Qv[4*tr+0][d], qv1 = Qv[4*tr+1][d];
        float qv2 = Qv[4*tr+2][d], qv3 = Qv[4*tr+3][d];
        float rv0 = Rs[4*tc+0][d], rv1 = Rs[4*tc+1][d];
        float rv2 = Rs[4*tc+2][d], rv3 = Rs[4*tc+3][d];
        acc[0][0]=fmaf(qv0,rv0,acc[0][0]); acc[0][1]=fmaf(qv0,rv1,acc[0][1]);
        acc[0][2]=fmaf(qv0,rv2,acc[0][2]); acc[0][3]=fmaf(qv0,rv3,acc[0][3]);
        acc[1][0]=fmaf(qv1,rv0,acc[1][0]); acc[1][1]=fmaf(qv1,rv1,acc[1][1]);
        acc[1][2]=fmaf(qv1,rv2,acc[1][2]); acc[1][3]=fmaf(qv1,rv3,acc[1][3]);
        acc[2][0]=fmaf(qv2,rv0,acc[2][0]); acc[2][1]=fmaf(qv2,rv1,acc[2][1]);
        acc[2][2]=fmaf(qv2,rv2,acc[2][2]); acc[2][3]=fmaf(qv2,rv3,acc[2][3]);
        acc[3][0]=fmaf(qv3,rv0,acc[3][0]); acc[3][1]=fmaf(qv3,rv1,acc[3][1]);
        acc[3][2]=fmaf(qv3,rv2,acc[3][2]); acc[3][3]=fmaf(qv3,rv3,acc[3][3]);
    }
    #pragma unroll
    for (int ri = 0; ri < 4; ri++) {
        float4 o = make_float4(acc[ri][0], acc[ri][1], acc[ri][2], acc[ri][3]);
        *(float4*)&bdout[(((size_t)(b*HN + h))*QN + i0 + 4*tr + ri)*KLEN + t0 + 4*tc] = o;
    }
}

// ---------------- flash attention (online softmax, K/V tiled) ----------------
// block = (i-tile of 32, h, b). 256 threads: thread (iown=tid/8, t8=tid%8)
// owns row i0+iown, j's 8*t8..+7 per chunk, output dims 8*t8..+7.
__global__ __launch_bounds__(256)
void flash_kernel(const float* __restrict__ q, const float* __restrict__ k,
                  const float* __restrict__ v, const float* __restrict__ bd,
                  const float* __restrict__ uvec, float* __restrict__ out,
                  int klen, int useMask) {
    __shared__ float Qs[32][65];
    __shared__ float Ks[64][65];
    __shared__ float Vs[64][64];
    const int i0 = blockIdx.x * 32;
    const int h = blockIdx.y, b = blockIdx.z;
    const int tid = threadIdx.x;
    const int iown = tid >> 3, t8 = tid & 7;
    const int laneBase = (tid & 31) & 24;

    // load Q tile (+u)
    #pragma unroll
    for (int t = 0; t < 2; t++) {
        int idx = tid + 256*t;
        int row = idx >> 4, c4 = (idx & 15)*4;
        float4 qq = *(const float4*)&q[((size_t)(b*QN + i0 + row))*DM + h*DH + c4];
        if (uvec) {
            qq.x += uvec[h*DH + c4 + 0];
            qq.y += uvec[h*DH + c4 + 1];
            qq.z += uvec[h*DH + c4 + 2];
            qq.w += uvec[h*DH + c4 + 3];
        }
        Qs[row][c4+0]=qq.x; Qs[row][c4+1]=qq.y; Qs[row][c4+2]=qq.z; Qs[row][c4+3]=qq.w;
    }

    float m = -INFINITY, l = 0.0f;
    float O[8];
    #pragma unroll
    for (int dd = 0; dd < 8; dd++) O[dd] = 0.0f;

    const int ia = i0 + iown;
    const int lastj = useMask ? ((klen-1) < (i0+31+MN) ? (klen-1) : (i0+31+MN)) : (klen-1);

    for (int j0 = 0; j0 <= lastj; j0 += 64) {
        __syncthreads();   // prev chunk consumers done (also orders Qs fill on 1st iter)
        #pragma unroll
        for (int t = 0; t < 4; t++) {
            int idx = tid + 256*t;
            int row = idx >> 4, c4 = (idx & 15)*4;
            size_t gb = ((size_t)(b*klen + j0 + row))*DM + h*DH + c4;
            float4 kk4 = *(const float4*)&k[gb];
            Ks[row][c4+0]=kk4.x; Ks[row][c4+1]=kk4.y; Ks[row][c4+2]=kk4.z; Ks[row][c4+3]=kk4.w;
            *(float4*)&Vs[row][c4] = *(const float4*)&v[gb];
        }
        __syncthreads();

        // scores for j = j0 + 8*t8 + jj
        float s[8];
        #pragma unroll
        for (int jj = 0; jj < 8; jj++) s[jj] = 0.0f;
        #pragma unroll 4
        for (int d = 0; d < 64; d++) {
            float qd = Qs[iown][d];
            #pragma unroll
            for (int jj = 0; jj < 8; jj++)
                s[jj] = fmaf(qd, Ks[8*t8 + jj][d], s[jj]);
        }
        #pragma unroll
        for (int jj = 0; jj < 8; jj++) {
            int ja = j0 + 8*t8 + jj;
            if (useMask && (ja > ia + MN)) {
                s[jj] = -INFINITY;
            } else {
                float sv = s[jj];
                if (bd) sv += bd[(((size_t)(b*HN + h))*QN + ia)*KLEN + (ja - ia + (QN-1))];
                s[jj] = sv * 0.125f;
            }
        }

        // online softmax within the 8-lane row group
        float mc = s[0];
        #pragma unroll
        for (int jj = 1; jj < 8; jj++) mc = fmaxf(mc, s[jj]);
        mc = fmaxf(mc, __shfl_xor_sync(0xffffffffu, mc, 4));
        mc = fmaxf(mc, __shfl_xor_sync(0xffffffffu, mc, 2));
        mc = fmaxf(mc, __shfl_xor_sync(0xffffffffu, mc, 1));
        float nm = fmaxf(m, mc);
        float corr = __expf(m - nm);
        float p[8];
        float psum = 0.0f;
        #pragma unroll
        for (int jj = 0; jj < 8; jj++) { p[jj] = __expf(s[jj] - nm); psum += p[jj]; }
        psum += __shfl_xor_sync(0xffffffffu, psum, 4);
        psum += __shfl_xor_sync(0xffffffffu, psum, 2);
        psum += __shfl_xor_sync(0xffffffffu, psum, 1);
        l = l * corr + psum;
        m = nm;
        #pragma unroll
        for (int dd = 0; dd < 8; dd++) O[dd] *= corr;

        // PV accumulate: broadcast p across the 8-lane group via shfl
        #pragma unroll
        for (int src = 0; src < 8; src++) {
            #pragma unroll
            for (int jj = 0; jj < 8; jj++) {
                float pb = __shfl_sync(0xffffffffu, p[jj], laneBase + src, 32);
                int j = 8*src + jj;
                #pragma unroll
                for (int dd = 0; dd < 8; dd++)
                    O[dd] = fmaf(pb, Vs[j][8*t8 + dd], O[dd]);
            }
        }
    }

    float invl = 1.0f / l;
    #pragma unroll
    for (int dd = 0; dd < 8; dd++)
        out[((size_t)(b*QN + ia))*DM + h*DH + 8*t8 + dd] = O[dd] * invl;
}

// ---------------- residual add + LayerNorm ----------------
__global__ __launch_bounds__(256)
void ln_kernel(float* __restrict__ x, const float* __restrict__ y,
               const float* __restrict__ gamma, const float* __restrict__ beta) {
    const int row = blockIdx.x;
    const int tid = threadIdx.x;
    __shared__ float red[256];

    float s[4];
    float local = 0.0f;
    #pragma unroll
    for (int kk = 0; kk < 4; kk++) {
        int c = tid + kk*256;
        float val = x[(size_t)row*DM + c] + y[(size_t)row*DM + c];
        s[kk] = val;
        local += val;
    }
    red[tid] = local;
    __syncthreads();
    for (int t = 128; t > 0; t >>= 1) {
        if (tid < t) red[tid] += red[tid+t];
        __syncthreads();
    }
    const float mu = red[0] * (1.0f / DM);
    __syncthreads();

    local = 0.0f;
    #pragma unroll
    for (int kk = 0; kk < 4; kk++) {
        float dlt = s[kk] - mu;
        local += dlt * dlt;
    }
    red[tid] = local;
    __syncthreads();
    for (int t = 128; t > 0; t >>= 1) {
        if (tid < t) red[tid] += red[tid+t];
        __syncthreads();
    }
    const float rstd = rsqrtf(red[0] * (1.0f / DM) + 1e-5f);
    __syncthreads();

    #pragma unroll
    for (int kk = 0; kk < 4; kk++) {
        int c = tid + kk*256;
        x[(size_t)row*DM + c] = (s[kk] - mu) * rstd * gamma[c] + beta[c];
    }
}

// ---------------- host orchestration ----------------
static inline void run_gemm(const float* A, const float* B, const float* bias,
                            float* C, int N, int D, int K, bool gelu) {
    dim3 grid(K/128, N/128);
    if (gelu) mm_tf32<true ><<<grid, 256>>>(A, B, bias, C, N, D, K);
    else      mm_tf32<false><<<grid, 256>>>(A, B, bias, C, N, D, K);
}

extern "C" void kernel_launch(void* const* d_in, const int* in_sizes, int n_in,
                              void* d_out, int out_size) {
    const float* enc    = (const float*)d_in[0];
    const float* mems   = (const float*)d_in[1];
    const float* emb    = (const float*)d_in[2];
    const float* u      = (const float*)d_in[3];
    const float* vpar   = (const float*)d_in[4];
    const float* saWq   = (const float*)d_in[5];
    const float* saWk   = (const float*)d_in[6];
    const float* saWv   = (const float*)d_in[7];
    const float* saWr   = (const float*)d_in[8];
    const float* safcW  = (const float*)d_in[9];
    const float* safcB  = (const float*)d_in[10];
    const float* ln1g   = (const float*)d_in[11];
    const float* ln1b   = (const float*)d_in[12];
    const float* caWq   = (const float*)d_in[13];
    const float* caWk   = (const float*)d_in[14];
    const float* caWv   = (const float*)d_in[15];
    const float* cafcW  = (const float*)d_in[16];
    const float* cafcB  = (const float*)d_in[17];
    const float* ln2g   = (const float*)d_in[18];
    const float* ln2b   = (const float*)d_in[19];
    const float* ffW1   = (const float*)d_in[20];
    const float* ffb1   = (const float*)d_in[21];
    const float* ffW2   = (const float*)d_in[22];
    const float* ffb2   = (const float*)d_in[23];
    const float* ln3g   = (const float*)d_in[24];
    const float* ln3b   = (const float*)d_in[25];
    const float* outW   = (const float*)d_in[26];
    const int*   ids    = (const int*)  d_in[27];
    float* out = (float*)d_out;

    float *x, *memb, *qb, *kb, *vb, *rb, *remb, *att, *tmp, *ff, *bdb;
    cudaGetSymbolAddress((void**)&x,    g_x);
    cudaGetSymbolAddress((void**)&memb, g_mem);
    cudaGetSymbolAddress((void**)&qb,   g_q);
    cudaGetSymbolAddress((void**)&kb,   g_k);
    cudaGetSymbolAddress((void**)&vb,   g_v);
    cudaGetSymbolAddress((void**)&rb,   g_r);
    cudaGetSymbolAddress((void**)&remb, g_remb);
    cudaGetSymbolAddress((void**)&att,  g_att);
    cudaGetSymbolAddress((void**)&tmp,  g_tmp);
    cudaGetSymbolAddress((void**)&ff,   g_ff);
    cudaGetSymbolAddress((void**)&bdb,  g_bd);

    embed_kernel<<<(BN*QN*DM + 255)/256, 256>>>(ids, emb, x);
    remb_kernel <<<(KLEN*DM + 255)/256, 256>>>(remb);

    dim3 flash_grid(QN/32, HN, BN);
    dim3 bd_grid(KLEN/64, QN/64, BN*HN);

    for (int l = 0; l < LNUM; l++) {
        // ---- self-attention (TransformerXL relative) ----
        concat_kernel<<<(BN*KLEN*DM + 255)/256, 256>>>(
            mems + (size_t)l*BN*MN*DM, x, memb);

        run_gemm(x,    saWq + (size_t)l*DM*DM, nullptr, qb, BN*QN,  DM, DM, false);
        run_gemm(memb, saWk + (size_t)l*DM*DM, nullptr, kb, BN*KLEN,DM, DM, false);
        run_gemm(memb, saWv + (size_t)l*DM*DM, nullptr, vb, BN*KLEN,DM, DM, false);
        run_gemm(remb, saWr + (size_t)l*DM*DM, nullptr, rb, KLEN,   DM, DM, false);

        bd_kernel<<<bd_grid, 256>>>(qb, rb, vpar, bdb);
        flash_kernel<<<flash_grid, 256>>>(qb, kb, vb, bdb, u, att, KLEN, 1);

        run_gemm(att, safcW + (size_t)l*DM*DM, safcB + (size_t)l*DM,
                 tmp, BN*QN, DM, DM, false);
        ln_kernel<<<BN*QN, 256>>>(x, tmp, ln1g + (size_t)l*DM, ln1b + (size_t)l*DM);

        // ---- cross-attention ----
        run_gemm(x,   caWq + (size_t)l*DM*DM, nullptr, qb, BN*QN, DM, DM, false);
        run_gemm(enc, caWk + (size_t)l*DM*DM, nullptr, kb, BN*EN, DM, DM, false);
        run_gemm(enc, caWv + (size_t)l*DM*DM, nullptr, vb, BN*EN, DM, DM, false);

        flash_kernel<<<flash_grid, 256>>>(qb, kb, vb, nullptr, nullptr, att, EN, 0);

        run_gemm(att, cafcW + (size_t)l*DM*DM, cafcB + (size_t)l*DM,
                 tmp, BN*QN, DM, DM, false);
        ln_kernel<<<BN*QN, 256>>>(x, tmp, ln2g + (size_t)l*DM, ln2b + (size_t)l*DM);

        // ---- feed-forward ----
        run_gemm(x,  ffW1 + (size_t)l*DM*FFN, ffb1 + (size_t)l*FFN,
                 ff, BN*QN, DM, FFN, true);
        run_gemm(ff, ffW2 + (size_t)l*FFN*DM, ffb2 + (size_t)l*DM,
                 tmp, BN*QN, FFN, DM, false);
        ln_kernel<<<BN*QN, 256>>>(x, tmp, ln3g + (size_t)l*DM, ln3b + (size_t)l*DM);
    }

    // ---- output projection ----
    run_gemm(x, outW, nullptr, out, BN*QN, DM, VN, false);
}

// round 5
// speedup vs baseline: 11.1379x; 1.9622x over previous
#include <cuda_runtime.h>
#include <math.h>

// Problem constants
#define LNUM 4
#define DM   1024
#define HN   16
#define DH   64
#define FFN  4096
#define VN   8192
#define BN   4
#define QN   512
#define MN   512
#define EN   512
#define KLEN 1024   // M + Q

// ---------------- scratch (device globals; no allocation) ----------------
__device__ float g_x   [BN*QN*DM];
__device__ float g_mem [BN*KLEN*DM];
__device__ float g_q   [BN*QN*DM];
__device__ float g_k   [BN*KLEN*DM];
__device__ float g_v   [BN*KLEN*DM];
__device__ float g_remb[KLEN*DM];
__device__ float g_r   [KLEN*DM];
__device__ float g_att [BN*QN*DM];
__device__ float g_tmp [BN*QN*DM];
__device__ float g_ff  [BN*QN*FFN];
__device__ float g_bd  [BN*HN*QN*KLEN];   // relative-position BD_raw

// ---------------- tf32 helpers ----------------
__device__ __forceinline__ unsigned f2tf(float x) {
    unsigned u; asm("cvt.rna.tf32.f32 %0, %1;" : "=r"(u) : "f"(x)); return u;
}
__device__ __forceinline__ float tfv(float x) { return __uint_as_float(f2tf(x)); }

#define MMA_TF32(C, A, B0, B1)                                                \
    asm volatile(                                                             \
        "mma.sync.aligned.m16n8k8.row.col.f32.tf32.tf32.f32 "                 \
        "{%0,%1,%2,%3}, {%4,%5,%6,%7}, {%8,%9}, {%0,%1,%2,%3};"               \
        : "+f"((C)[0]), "+f"((C)[1]), "+f"((C)[2]), "+f"((C)[3])              \
        : "r"((A)[0]), "r"((A)[1]), "r"((A)[2]), "r"((A)[3]),                 \
          "r"(B0), "r"(B1))

// ---------------- elementwise kernels ----------------
__global__ void embed_kernel(const int* __restrict__ ids,
                             const float* __restrict__ emb,
                             float* __restrict__ x) {
    int idx = blockIdx.x * blockDim.x + threadIdx.x;
    if (idx >= BN*QN*DM) return;
    int row = idx / DM;
    int d   = idx - row * DM;
    int tok = ids[row];
    x[idx] = emb[tok * DM + d] * 32.0f;
}

__global__ void remb_kernel(float* __restrict__ remb) {
    int idx = blockIdx.x * blockDim.x + threadIdx.x;
    if (idx >= KLEN*DM) return;
    int p = idx / DM;
    int d = idx - p * DM;
    float pos = (float)(KLEN - 1 - p);
    int k = (d < DM/2) ? d : d - DM/2;
    float invf = powf(10000.0f, -(float)k / (float)(DM/2));
    float a = pos * invf;
    remb[idx] = (d < DM/2) ? sinf(a) : cosf(a);
}

__global__ void concat_kernel(const float* __restrict__ mems_l,
                              const float* __restrict__ x,
                              float* __restrict__ mem) {
    int idx = blockIdx.x * blockDim.x + threadIdx.x;
    if (idx >= BN*KLEN*DM) return;
    int d   = idx % DM;
    int rem = idx / DM;
    int j   = rem % KLEN;
    int b   = rem / KLEN;
    float val;
    if (j < MN) val = mems_l[(b*MN + j)*DM + d];
    else        val = x[(b*QN + (j - MN))*DM + d];
    mem[idx] = val;
}

// ---------------- tf32 tensor-core GEMM ----------------
// C[N,K] = A[N,D] @ B[D,K] (+bias, optional GELU). N,K mult of 128, D mult 16.
template<bool GELU>
__global__ __launch_bounds__(256)
void mm_tf32(const float* __restrict__ A, const float* __restrict__ B,
             const float* __restrict__ bias, float* __restrict__ C,
             int N, int D, int K) {
    __shared__ float As[2][128][20];   // conflict-free frag loads (pad 20)
    __shared__ float Bs[2][16][136];   // conflict-free frag loads (pad 136)
    const int tid  = threadIdx.x;
    const int row0 = blockIdx.y * 128, col0 = blockIdx.x * 128;
    const int lane = tid & 31, wid = tid >> 5;
    const int grp  = lane >> 2, t4 = lane & 3;
    const int wm   = (wid & 3) * 32, wn = (wid >> 2) * 64;

    const int ar = tid >> 2, ak = (tid & 3) * 4;
    const int bk = tid >> 5, bc = (tid & 31) * 4;

    float c[2][8][4];
    #pragma unroll
    for (int i = 0; i < 2; i++)
        #pragma unroll
        for (int j = 0; j < 8; j++)
            #pragma unroll
            for (int t = 0; t < 4; t++) c[i][j][t] = 0.0f;

    {
        float4 a0 = *(const float4*)&A[(size_t)(row0+ar)*D + ak];
        float4 a1 = *(const float4*)&A[(size_t)(row0+ar+64)*D + ak];
        float4 b0 = *(const float4*)&B[(size_t)bk*K + col0 + bc];
        float4 b1 = *(const float4*)&B[(size_t)(bk+8)*K + col0 + bc];
        *(float4*)&As[0][ar][ak]    = make_float4(tfv(a0.x),tfv(a0.y),tfv(a0.z),tfv(a0.w));
        *(float4*)&As[0][ar+64][ak] = make_float4(tfv(a1.x),tfv(a1.y),tfv(a1.z),tfv(a1.w));
        *(float4*)&Bs[0][bk][bc]    = make_float4(tfv(b0.x),tfv(b0.y),tfv(b0.z),tfv(b0.w));
        *(float4*)&Bs[0][bk+8][bc]  = make_float4(tfv(b1.x),tfv(b1.y),tfv(b1.z),tfv(b1.w));
    }
    __syncthreads();

    const int KT = D >> 4;
    int cur = 0;
    for (int kt = 0; kt < KT; kt++) {
        float4 pa0, pa1, pb0, pb1;
        const bool more = (kt + 1 < KT);
        if (more) {
            int k0 = (kt + 1) * 16;
            pa0 = *(const float4*)&A[(size_t)(row0+ar)*D + k0 + ak];
            pa1 = *(const float4*)&A[(size_t)(row0+ar+64)*D + k0 + ak];
            pb0 = *(const float4*)&B[(size_t)(k0+bk)*K + col0 + bc];
            pb1 = *(const float4*)&B[(size_t)(k0+bk+8)*K + col0 + bc];
        }
        // load BOTH k8 fragment sets up front (register double-buffer)
        unsigned af[2][2][4], bf[2][8][2];
        #pragma unroll
        for (int half = 0; half < 2; half++) {
            const int kk = half * 8;
            #pragma unroll
            for (int mt = 0; mt < 2; mt++) {
                int m = wm + mt*16 + grp;
                af[half][mt][0] = __float_as_uint(As[cur][m  ][kk+t4  ]);
                af[half][mt][1] = __float_as_uint(As[cur][m+8][kk+t4  ]);
                af[half][mt][2] = __float_as_uint(As[cur][m  ][kk+t4+4]);
                af[half][mt][3] = __float_as_uint(As[cur][m+8][kk+t4+4]);
            }
            #pragma unroll
            for (int nt = 0; nt < 8; nt++) {
                int n = wn + nt*8 + grp;
                bf[half][nt][0] = __float_as_uint(Bs[cur][kk+t4  ][n]);
                bf[half][nt][1] = __float_as_uint(Bs[cur][kk+t4+4][n]);
            }
        }
        // first MMA batch
        #pragma unroll
        for (int mt = 0; mt < 2; mt++)
            #pragma unroll
            for (int nt = 0; nt < 8; nt++)
                MMA_TF32(c[mt][nt], af[0][mt], bf[0][nt][0], bf[0][nt][1]);
        // overlap next-stage smem stores with second MMA batch
        if (more) {
            int nxt = cur ^ 1;
            *(float4*)&As[nxt][ar][ak]    = make_float4(tfv(pa0.x),tfv(pa0.y),tfv(pa0.z),tfv(pa0.w));
            *(float4*)&As[nxt][ar+64][ak] = make_float4(tfv(pa1.x),tfv(pa1.y),tfv(pa1.z),tfv(pa1.w));
            *(float4*)&Bs[nxt][bk][bc]    = make_float4(tfv(pb0.x),tfv(pb0.y),tfv(pb0.z),tfv(pb0.w));
            *(float4*)&Bs[nxt][bk+8][bc]  = make_float4(tfv(pb1.x),tfv(pb1.y),tfv(pb1.z),tfv(pb1.w));
        }
        #pragma unroll
        for (int mt = 0; mt < 2; mt++)
            #pragma unroll
            for (int nt = 0; nt < 8; nt++)
                MMA_TF32(c[mt][nt], af[1][mt], bf[1][nt][0], bf[1][nt][1]);
        __syncthreads();
        cur ^= 1;
    }

    #pragma unroll
    for (int mt = 0; mt < 2; mt++)
        #pragma unroll
        for (int nt = 0; nt < 8; nt++) {
            int r  = row0 + wm + mt*16 + grp;
            int cc = col0 + wn + nt*8 + t4*2;
            #pragma unroll
            for (int half = 0; half < 2; half++) {
                int rr = r + half*8;
                #pragma unroll
                for (int e = 0; e < 2; e++) {
                    float val = c[mt][nt][half*2 + e];
                    int col = cc + e;
                    if (bias) val += bias[col];
                    if (GELU) val = 0.5f*val*(1.0f + erff(val*0.70710678118654752f));
                    C[(size_t)rr*K + col] = val;
                }
            }
        }
}

// ---------------- BD_raw via tensor cores ----------------
// bdout[b,h,i,t] = sum_d (q[b,i,h,d] + vvec[h,d]) * r[t,h,d]
// block: 8 warps (m16 each -> 128 i rows), one 64-wide t chunk. grid (16,4,64)
#define RS_STRIDE 68
__global__ __launch_bounds__(256)
void bd_mma(const float* __restrict__ q, const float* __restrict__ r,
            const float* __restrict__ vvec, float* __restrict__ bdout) {
    __shared__ float Rs[64*RS_STRIDE];
    const int t0 = blockIdx.x * 64;
    const int i0 = blockIdx.y * 128;
    const int h = blockIdx.z & (HN-1), b = blockIdx.z >> 4;
    const int tid = threadIdx.x;
    const int lane = tid & 31, wid = tid >> 5;
    const int grp = lane >> 2, t4 = lane & 3;
    const int i_r0 = i0 + wid*16 + grp, i_r1 = i_r0 + 8;

    // Q(+v) fragments in registers
    unsigned qf[8][4];
    {
        const float* qp0 = q + ((size_t)(b*QN + i_r0))*DM + h*DH;
        const float* qp1 = q + ((size_t)(b*QN + i_r1))*DM + h*DH;
        const float* up  = vvec + h*DH;
        #pragma unroll
        for (int ks = 0; ks < 8; ks++) {
            int k0 = ks*8 + t4;
            float u0 = up[k0], u1 = up[k0+4];
            qf[ks][0] = f2tf(qp0[k0]   + u0);
            qf[ks][1] = f2tf(qp1[k0]   + u0);
            qf[ks][2] = f2tf(qp0[k0+4] + u1);
            qf[ks][3] = f2tf(qp1[k0+4] + u1);
        }
    }
    // load R chunk
    #pragma unroll
    for (int t = 0; t < 4; t++) {
        int idx = tid + 256*t;
        int row = idx >> 4, c4 = (idx & 15) * 4;
        float4 rr = *(const float4*)&r[((size_t)(t0 + row))*DM + h*DH + c4];
        float* rd = Rs + row*RS_STRIDE + c4;
        rd[0]=tfv(rr.x); rd[1]=tfv(rr.y); rd[2]=tfv(rr.z); rd[3]=tfv(rr.w);
    }
    __syncthreads();

    float s[8][4];
    #pragma unroll
    for (int nt = 0; nt < 8; nt++)
        #pragma unroll
        for (int e = 0; e < 4; e++) s[nt][e] = 0.0f;

    #pragma unroll
    for (int ks = 0; ks < 8; ks++)
        #pragma unroll
        for (int nt = 0; nt < 8; nt++) {
            unsigned b0 = __float_as_uint(Rs[(nt*8+grp)*RS_STRIDE + ks*8 + t4]);
            unsigned b1 = __float_as_uint(Rs[(nt*8+grp)*RS_STRIDE + ks*8 + t4 + 4]);
            MMA_TF32(s[nt], qf[ks], b0, b1);
        }

    float* o0 = bdout + (((size_t)(b*HN + h))*QN + i_r0)*KLEN + t0;
    float* o1 = bdout + (((size_t)(b*HN + h))*QN + i_r1)*KLEN + t0;
    #pragma unroll
    for (int nt = 0; nt < 8; nt++) {
        int cc = nt*8 + 2*t4;
        *(float2*)&o0[cc] = make_float2(s[nt][0], s[nt][1]);
        *(float2*)&o1[cc] = make_float2(s[nt][2], s[nt][3]);
    }
}

// ---------------- MMA flash attention ----------------
// block: 128 q-rows, 8 warps (m16 x n64 each), j-chunks of 64.
// smem strides chosen for conflict-free fragment loads:
//   Ks stride 68 -> banks 4*grp + t4 (distinct);  Vs stride 72 -> 8*t4 + grp;
//   Ps stride 68 -> 4*grp + t4.
#define KS_STRIDE 68
#define VS_STRIDE 72
#define PS_STRIDE 68
#define FLASH_SMEM ((64*KS_STRIDE + 64*VS_STRIDE + 128*PS_STRIDE) * 4)

__global__ __launch_bounds__(256)
void flashmma(const float* __restrict__ q, const float* __restrict__ k,
              const float* __restrict__ v, const float* __restrict__ bd,
              const float* __restrict__ uvec, float* __restrict__ out,
              int klen, int useMask) {
    extern __shared__ float sm[];
    float* Ks = sm;
    float* Vs = Ks + 64*KS_STRIDE;
    float* Ps = Vs + 64*VS_STRIDE;

    const int i0 = blockIdx.x * 128;
    const int h = blockIdx.y, b = blockIdx.z;
    const int tid = threadIdx.x;
    const int lane = tid & 31, wid = tid >> 5;
    const int grp = lane >> 2, t4 = lane & 3;
    const int r0 = wid*16 + grp, r1 = r0 + 8;     // local P rows
    const int i_r0 = i0 + r0, i_r1 = i0 + r1;     // global query rows

    // Q fragments (+u) in registers
    unsigned qf[8][4];
    {
        const float* qp0 = q + ((size_t)(b*QN + i_r0))*DM + h*DH;
        const float* qp1 = q + ((size_t)(b*QN + i_r1))*DM + h*DH;
        #pragma unroll
        for (int ks = 0; ks < 8; ks++) {
            int k0 = ks*8 + t4;
            float u0 = uvec ? uvec[h*DH + k0]     : 0.0f;
            float u1 = uvec ? uvec[h*DH + k0 + 4] : 0.0f;
            qf[ks][0] = f2tf(qp0[k0]   + u0);
            qf[ks][1] = f2tf(qp1[k0]   + u0);
            qf[ks][2] = f2tf(qp0[k0+4] + u1);
            qf[ks][3] = f2tf(qp1[k0+4] + u1);
        }
    }

    float m0 = -INFINITY, m1 = -INFINITY, l0 = 0.0f, l1 = 0.0f;
    float o[8][4];
    #pragma unroll
    for (int nt = 0; nt < 8; nt++)
        #pragma unroll
        for (int e = 0; e < 4; e++) o[nt][e] = 0.0f;

    const float* bdr0 = bd ? bd + (((size_t)(b*HN + h))*QN + i_r0)*KLEN : (const float*)0;
    const float* bdr1 = bd ? bd + (((size_t)(b*HN + h))*QN + i_r1)*KLEN : (const float*)0;

    int lastj = klen - 1;
    if (useMask) { int lm = i0 + 127 + MN; if (lm < lastj) lastj = lm; }

    for (int j0 = 0; j0 <= lastj; j0 += 64) {
        __syncthreads();
        #pragma unroll
        for (int t = 0; t < 4; t++) {
            int idx = tid + 256*t;
            int row = idx >> 4, c4 = (idx & 15) * 4;
            size_t gb = ((size_t)(b*klen + j0 + row))*DM + h*DH + c4;
            float4 kk4 = *(const float4*)&k[gb];
            float4 vv4 = *(const float4*)&v[gb];
            float* kd = Ks + row*KS_STRIDE + c4;
            kd[0]=tfv(kk4.x); kd[1]=tfv(kk4.y); kd[2]=tfv(kk4.z); kd[3]=tfv(kk4.w);
            float* vd = Vs + row*VS_STRIDE + c4;
            vd[0]=tfv(vv4.x); vd[1]=tfv(vv4.y); vd[2]=tfv(vv4.z); vd[3]=tfv(vv4.w);
        }
        __syncthreads();

        // prefetch BD gathers (overlap with MMAs)
        float bdv[8][4];
        if (bd) {
            #pragma unroll
            for (int nt = 0; nt < 8; nt++) {
                int jA = j0 + nt*8 + 2*t4;
                int jr0 = jA - i_r0 + (QN-1);
                int jr1 = jA - i_r1 + (QN-1);
                jr0 = max(0, min(KLEN-2, jr0));
                jr1 = max(0, min(KLEN-2, jr1));
                bdv[nt][0] = bdr0[jr0];   bdv[nt][1] = bdr0[jr0+1];
                bdv[nt][2] = bdr1[jr1];   bdv[nt][3] = bdr1[jr1+1];
            }
        }

        // S = Q @ K^T
        float s[8][4];
        #pragma unroll
        for (int nt = 0; nt < 8; nt++)
            #pragma unroll
            for (int e = 0; e < 4; e++) s[nt][e] = 0.0f;
        #pragma unroll
        for (int ks = 0; ks < 8; ks++)
            #pragma unroll
            for (int nt = 0; nt < 8; nt++) {
                unsigned b0 = __float_as_uint(Ks[(nt*8+grp)*KS_STRIDE + ks*8 + t4]);
                unsigned b1 = __float_as_uint(Ks[(nt*8+grp)*KS_STRIDE + ks*8 + t4 + 4]);
                MMA_TF32(s[nt], qf[ks], b0, b1);
            }

        // BD add, mask, scale; rowwise max
        float mc0 = -INFINITY, mc1 = -INFINITY;
        #pragma unroll
        for (int nt = 0; nt < 8; nt++) {
            int jA = j0 + nt*8 + 2*t4;
            int jB = jA + 1;
            float v0 = s[nt][0], v1 = s[nt][1], v2 = s[nt][2], v3 = s[nt][3];
            if (bd) { v0 += bdv[nt][0]; v1 += bdv[nt][1]; v2 += bdv[nt][2]; v3 += bdv[nt][3]; }
            v0 *= 0.125f; v1 *= 0.125f; v2 *= 0.125f; v3 *= 0.125f;
            if (useMask) {
                if (jA > i_r0 + MN) v0 = -INFINITY;
                if (jB > i_r0 + MN) v1 = -INFINITY;
                if (jA > i_r1 + MN) v2 = -INFINITY;
                if (jB > i_r1 + MN) v3 = -INFINITY;
            }
            s[nt][0]=v0; s[nt][1]=v1; s[nt][2]=v2; s[nt][3]=v3;
            mc0 = fmaxf(mc0, fmaxf(v0, v1));
            mc1 = fmaxf(mc1, fmaxf(v2, v3));
        }
        mc0 = fmaxf(mc0, __shfl_xor_sync(0xffffffffu, mc0, 1));
        mc0 = fmaxf(mc0, __shfl_xor_sync(0xffffffffu, mc0, 2));
        mc1 = fmaxf(mc1, __shfl_xor_sync(0xffffffffu, mc1, 1));
        mc1 = fmaxf(mc1, __shfl_xor_sync(0xffffffffu, mc1, 2));

        float nm0 = fmaxf(m0, mc0), nm1 = fmaxf(m1, mc1);
        float corr0 = __expf(m0 - nm0), corr1 = __expf(m1 - nm1);
        float ps0 = 0.0f, ps1 = 0.0f;
        #pragma unroll
        for (int nt = 0; nt < 8; nt++) {
            float p0 = __expf(s[nt][0] - nm0);
            float p1 = __expf(s[nt][1] - nm0);
            float p2 = __expf(s[nt][2] - nm1);
            float p3 = __expf(s[nt][3] - nm1);
            ps0 += p0 + p1; ps1 += p2 + p3;
            int cc = nt*8 + 2*t4;
            Ps[r0*PS_STRIDE + cc]     = __uint_as_float(f2tf(p0));
            Ps[r0*PS_STRIDE + cc + 1] = __uint_as_float(f2tf(p1));
            Ps[r1*PS_STRIDE + cc]     = __uint_as_float(f2tf(p2));
            Ps[r1*PS_STRIDE + cc + 1] = __uint_as_float(f2tf(p3));
        }
        ps0 += __shfl_xor_sync(0xffffffffu, ps0, 1);
        ps0 += __shfl_xor_sync(0xffffffffu, ps0, 2);
        ps1 += __shfl_xor_sync(0xffffffffu, ps1, 1);
        ps1 += __shfl_xor_sync(0xffffffffu, ps1, 2);
        l0 = l0 * corr0 + ps0;  m0 = nm0;
        l1 = l1 * corr1 + ps1;  m1 = nm1;
        #pragma unroll
        for (int nt = 0; nt < 8; nt++) {
            o[nt][0] *= corr0; o[nt][1] *= corr0;
            o[nt][2] *= corr1; o[nt][3] *= corr1;
        }
        __syncwarp();

        // O += P @ V
        #pragma unroll
        for (int ks = 0; ks < 8; ks++) {
            unsigned a[4];
            a[0] = __float_as_uint(Ps[r0*PS_STRIDE + ks*8 + t4]);
            a[1] = __float_as_uint(Ps[r1*PS_STRIDE + ks*8 + t4]);
            a[2] = __float_as_uint(Ps[r0*PS_STRIDE + ks*8 + t4 + 4]);
            a[3] = __float_as_uint(Ps[r1*PS_STRIDE + ks*8 + t4 + 4]);
            #pragma unroll
            for (int nt = 0; nt < 8; nt++) {
                unsigned b0 = __float_as_uint(Vs[(ks*8+t4)*VS_STRIDE + nt*8 + grp]);
                unsigned b1 = __float_as_uint(Vs[(ks*8+t4+4)*VS_STRIDE + nt*8 + grp]);
                MMA_TF32(o[nt], a, b0, b1);
            }
        }
    }

    const float inv0 = 1.0f / l0, inv1 = 1.0f / l1;
    float* op0 = out + ((size_t)(b*QN + i_r0))*DM + h*DH;
    float* op1 = out + ((size_t)(b*QN + i_r1))*DM + h*DH;
    #pragma unroll
    for (int nt = 0; nt < 8; nt++) {
        int cc = nt*8 + 2*t4;
        *(float2*)&op0[cc] = make_float2(o[nt][0]*inv0, o[nt][1]*inv0);
        *(float2*)&op1[cc] = make_float2(o[nt][2]*inv1, o[nt][3]*inv1);
    }
}

// ---------------- residual add + LayerNorm ----------------
__global__ __launch_bounds__(256)
void ln_kernel(float* __restrict__ x, const float* __restrict__ y,
               const float* __restrict__ gamma, const float* __restrict__ beta) {
    const int row = blockIdx.x;
    const int tid = threadIdx.x;
    __shared__ float red[256];

    float s[4];
    float local = 0.0f;
    #pragma unroll
    for (int kk = 0; kk < 4; kk++) {
        int c = tid + kk*256;
        float val = x[(size_t)row*DM + c] + y[(size_t)row*DM + c];
        s[kk] = val;
        local += val;
    }
    red[tid] = local;
    __syncthreads();
    for (int t = 128; t > 0; t >>= 1) {
        if (tid < t) red[tid] += red[tid+t];
        __syncthreads();
    }
    const float mu = red[0] * (1.0f / DM);
    __syncthreads();

    local = 0.0f;
    #pragma unroll
    for (int kk = 0; kk < 4; kk++) {
        float dlt = s[kk] - mu;
        local += dlt * dlt;
    }
    red[tid] = local;
    __syncthreads();
    for (int t = 128; t > 0; t >>= 1) {
        if (tid < t) red[tid] += red[tid+t];
        __syncthreads();
    }
    const float rstd = rsqrtf(red[0] * (1.0f / DM) + 1e-5f);
    __syncthreads();

    #pragma unroll
    for (int kk = 0; kk < 4; kk++) {
        int c = tid + kk*256;
        x[(size_t)row*DM + c] = (s[kk] - mu) * rstd * gamma[c] + beta[c];
    }
}

// ---------------- host orchestration ----------------
static inline void run_gemm(const float* A, const float* B, const float* bias,
                            float* C, int N, int D, int K, bool gelu) {
    dim3 grid(K/128, N/128);
    if (gelu) mm_tf32<true ><<<grid, 256>>>(A, B, bias, C, N, D, K);
    else      mm_tf32<false><<<grid, 256>>>(A, B, bias, C, N, D, K);
}

extern "C" void kernel_launch(void* const* d_in, const int* in_sizes, int n_in,
                              void* d_out, int out_size) {
    const float* enc    = (const float*)d_in[0];
    const float* mems   = (const float*)d_in[1];
    const float* emb    = (const float*)d_in[2];
    const float* u      = (const float*)d_in[3];
    const float* vpar   = (const float*)d_in[4];
    const float* saWq   = (const float*)d_in[5];
    const float* saWk   = (const float*)d_in[6];
    const float* saWv   = (const float*)d_in[7];
    const float* saWr   = (const float*)d_in[8];
    const float* safcW  = (const float*)d_in[9];
    const float* safcB  = (const float*)d_in[10];
    const float* ln1g   = (const float*)d_in[11];
    const float* ln1b   = (const float*)d_in[12];
    const float* caWq   = (const float*)d_in[13];
    const float* caWk   = (const float*)d_in[14];
    const float* caWv   = (const float*)d_in[15];
    const float* cafcW  = (const float*)d_in[16];
    const float* cafcB  = (const float*)d_in[17];
    const float* ln2g   = (const float*)d_in[18];
    const float* ln2b   = (const float*)d_in[19];
    const float* ffW1   = (const float*)d_in[20];
    const float* ffb1   = (const float*)d_in[21];
    const float* ffW2   = (const float*)d_in[22];
    const float* ffb2   = (const float*)d_in[23];
    const float* ln3g   = (const float*)d_in[24];
    const float* ln3b   = (const float*)d_in[25];
    const float* outW   = (const float*)d_in[26];
    const int*   ids    = (const int*)  d_in[27];
    float* out = (float*)d_out;

    float *x, *memb, *qb, *kb, *vb, *rb, *remb, *att, *tmp, *ff, *bdb;
    cudaGetSymbolAddress((void**)&x,    g_x);
    cudaGetSymbolAddress((void**)&memb, g_mem);
    cudaGetSymbolAddress((void**)&qb,   g_q);
    cudaGetSymbolAddress((void**)&kb,   g_k);
    cudaGetSymbolAddress((void**)&vb,   g_v);
    cudaGetSymbolAddress((void**)&rb,   g_r);
    cudaGetSymbolAddress((void**)&remb, g_remb);
    cudaGetSymbolAddress((void**)&att,  g_att);
    cudaGetSymbolAddress((void**)&tmp,  g_tmp);
    cudaGetSymbolAddress((void**)&ff,   g_ff);
    cudaGetSymbolAddress((void**)&bdb,  g_bd);

    static int smem_set = 0;
    if (!smem_set) {
        cudaFuncSetAttribute(flashmma, cudaFuncAttributeMaxDynamicSharedMemorySize,
                             FLASH_SMEM);
        smem_set = 1;
    }

    embed_kernel<<<(BN*QN*DM + 255)/256, 256>>>(ids, emb, x);
    remb_kernel <<<(KLEN*DM + 255)/256, 256>>>(remb);

    dim3 flash_grid(QN/128, HN, BN);
    dim3 bd_grid(KLEN/64, QN/128, BN*HN);

    for (int l = 0; l < LNUM; l++) {
        // ---- self-attention (TransformerXL relative) ----
        concat_kernel<<<(BN*KLEN*DM + 255)/256, 256>>>(
            mems + (size_t)l*BN*MN*DM, x, memb);

        run_gemm(x,    saWq + (size_t)l*DM*DM, nullptr, qb, BN*QN,  DM, DM, false);
        run_gemm(memb, saWk + (size_t)l*DM*DM, nullptr, kb, BN*KLEN,DM, DM, false);
        run_gemm(memb, saWv + (size_t)l*DM*DM, nullptr, vb, BN*KLEN,DM, DM, false);
        run_gemm(remb, saWr + (size_t)l*DM*DM, nullptr, rb, KLEN,   DM, DM, false);

        bd_mma<<<bd_grid, 256>>>(qb, rb, vpar, bdb);
        flashmma<<<flash_grid, 256, FLASH_SMEM>>>(qb, kb, vb, bdb, u, att, KLEN, 1);

        run_gemm(att, safcW + (size_t)l*DM*DM, safcB + (size_t)l*DM,
                 tmp, BN*QN, DM, DM, false);
        ln_kernel<<<BN*QN, 256>>>(x, tmp, ln1g + (size_t)l*DM, ln1b + (size_t)l*DM);

        // ---- cross-attention ----
        run_gemm(x,   caWq + (size_t)l*DM*DM, nullptr, qb, BN*QN, DM, DM, false);
        run_gemm(enc, caWk + (size_t)l*DM*DM, nullptr, kb, BN*EN, DM, DM, false);
        run_gemm(enc, caWv + (size_t)l*DM*DM, nullptr, vb, BN*EN, DM, DM, false);

        flashmma<<<flash_grid, 256, FLASH_SMEM>>>(qb, kb, vb, nullptr, nullptr,
                                                  att, EN, 0);

        run_gemm(att, cafcW + (size_t)l*DM*DM, cafcB + (size_t)l*DM,
                 tmp, BN*QN, DM, DM, false);
        ln_kernel<<<BN*QN, 256>>>(x, tmp, ln2g + (size_t)l*DM, ln2b + (size_t)l*DM);

        // ---- feed-forward ----
        run_gemm(x,  ffW1 + (size_t)l*DM*FFN, ffb1 + (size_t)l*FFN,
                 ff, BN*QN, DM, FFN, true);
        run_gemm(ff, ffW2 + (size_t)l*FFN*DM, ffb2 + (size_t)l*DM,
                 tmp, BN*QN, FFN, DM, false);
        ln_kernel<<<BN*QN, 256>>>(x, tmp, ln3g + (size_t)l*DM, ln3b + (size_t)l*DM);
    }

    // ---- output projection ----
    run_gemm(x, outW, nullptr, out, BN*QN, DM, VN, false);
}

// round 6
// speedup vs baseline: 13.8841x; 1.2466x over previous
#include <cuda_runtime.h>
#include <math.h>

// Problem constants
#define LNUM 4
#define DM   1024
#define HN   16
#define DH   64
#define FFN  4096
#define VN   8192
#define BN   4
#define QN   512
#define MN   512
#define EN   512
#define KLEN 1024   // M + Q

// ---------------- scratch (device globals; no allocation) ----------------
__device__ float g_x   [BN*QN*DM];
__device__ float g_mem [BN*KLEN*DM];
__device__ float g_q   [BN*QN*DM];
__device__ float g_k   [BN*KLEN*DM];
__device__ float g_v   [BN*KLEN*DM];
__device__ float g_remb[KLEN*DM];
__device__ float g_r   [KLEN*DM];
__device__ float g_att [BN*QN*DM];
__device__ float g_tmp [BN*QN*DM];
__device__ float g_ff  [BN*QN*FFN];
__device__ float g_bd  [BN*HN*QN*KLEN];   // relative-position BD_raw

// ---------------- tf32 helpers ----------------
__device__ __forceinline__ unsigned f2tf(float x) {
    unsigned u; asm("cvt.rna.tf32.f32 %0, %1;" : "=r"(u) : "f"(x)); return u;
}
__device__ __forceinline__ float tfv(float x) { return __uint_as_float(f2tf(x)); }

#define MMA_TF32(C, A, B0, B1)                                                \
    asm volatile(                                                             \
        "mma.sync.aligned.m16n8k8.row.col.f32.tf32.tf32.f32 "                 \
        "{%0,%1,%2,%3}, {%4,%5,%6,%7}, {%8,%9}, {%0,%1,%2,%3};"               \
        : "+f"((C)[0]), "+f"((C)[1]), "+f"((C)[2]), "+f"((C)[3])              \
        : "r"((A)[0]), "r"((A)[1]), "r"((A)[2]), "r"((A)[3]),                 \
          "r"(B0), "r"(B1))

__device__ __forceinline__ void cp16(float* dst, const float* src) {
    unsigned d = (unsigned)__cvta_generic_to_shared(dst);
    asm volatile("cp.async.cg.shared.global [%0], [%1], 16;\n" :: "r"(d), "l"(src));
}
#define CP_COMMIT()  asm volatile("cp.async.commit_group;\n" ::)
#define CP_WAIT2()   asm volatile("cp.async.wait_group 2;\n" ::)

// ---------------- elementwise kernels ----------------
__global__ void embed_kernel(const int* __restrict__ ids,
                             const float* __restrict__ emb,
                             float* __restrict__ x) {
    int idx = blockIdx.x * blockDim.x + threadIdx.x;
    if (idx >= BN*QN*DM) return;
    int row = idx / DM;
    int d   = idx - row * DM;
    int tok = ids[row];
    x[idx] = emb[tok * DM + d] * 32.0f;
}

__global__ void remb_kernel(float* __restrict__ remb) {
    int idx = blockIdx.x * blockDim.x + threadIdx.x;
    if (idx >= KLEN*DM) return;
    int p = idx / DM;
    int d = idx - p * DM;
    float pos = (float)(KLEN - 1 - p);
    int k = (d < DM/2) ? d : d - DM/2;
    float invf = powf(10000.0f, -(float)k / (float)(DM/2));
    float a = pos * invf;
    remb[idx] = (d < DM/2) ? sinf(a) : cosf(a);
}

__global__ void concat_kernel(const float* __restrict__ mems_l,
                              const float* __restrict__ x,
                              float* __restrict__ mem) {
    int idx = blockIdx.x * blockDim.x + threadIdx.x;
    if (idx >= BN*KLEN*DM) return;
    int d   = idx % DM;
    int rem = idx / DM;
    int j   = rem % KLEN;
    int b   = rem / KLEN;
    float val;
    if (j < MN) val = mems_l[(b*MN + j)*DM + d];
    else        val = x[(b*QN + (j - MN))*DM + d];
    mem[idx] = val;
}

// ---------------- tf32 tensor-core GEMM, 4-stage cp.async pipeline ----------
// C[N,K] = A[N,D] @ B[D,K] (+bias, optional GELU). N,K mult of 128, D mult 16.
#define STAGES    4
#define AS_STRIDE 20
#define BS_STRIDE 136
#define AS_SZ     (128*AS_STRIDE)    // floats per stage
#define BS_SZ     (16*BS_STRIDE)
#define MM_SMEM   (STAGES*(AS_SZ+BS_SZ)*4)

template<bool GELU>
__global__ __launch_bounds__(256, 2)
void mm_tf32(const float* __restrict__ A, const float* __restrict__ B,
             const float* __restrict__ bias, float* __restrict__ C,
             int N, int D, int K) {
    extern __shared__ float sm[];
    float* As = sm;                   // [STAGES][128][AS_STRIDE]
    float* Bs = sm + STAGES*AS_SZ;    // [STAGES][16][BS_STRIDE]

    const int tid  = threadIdx.x;
    const int row0 = blockIdx.y * 128, col0 = blockIdx.x * 128;
    const int lane = tid & 31, wid = tid >> 5;
    const int grp  = lane >> 2, t4 = lane & 3;
    const int wm   = (wid & 3) * 32, wn = (wid >> 2) * 64;

    const int ar = tid >> 2, ak = (tid & 3) * 4;   // A loader: rows ar, ar+64
    const int bk = tid >> 5, bc = (tid & 31) * 4;  // B loader: k rows bk, bk+8

    const float* Ag0 = A + (size_t)(row0 + ar)      * D + ak;
    const float* Ag1 = A + (size_t)(row0 + ar + 64) * D + ak;
    const float* Bg0 = B + (size_t)bk       * K + col0 + bc;
    const float* Bg1 = B + (size_t)(bk + 8) * K + col0 + bc;

    float* sA0 = As + ar*AS_STRIDE + ak;
    float* sA1 = As + (ar+64)*AS_STRIDE + ak;
    float* sB0 = Bs + bk*BS_STRIDE + bc;
    float* sB1 = Bs + (bk+8)*BS_STRIDE + bc;

    const int KT = D >> 4;

    float c[2][8][4];
    #pragma unroll
    for (int i = 0; i < 2; i++)
        #pragma unroll
        for (int j = 0; j < 8; j++)
            #pragma unroll
            for (int t = 0; t < 4; t++) c[i][j][t] = 0.0f;

    // prologue: stages 0..2 in flight
    #pragma unroll
    for (int s = 0; s < 3; s++) {
        const int kb = s * 16;
        cp16(sA0 + s*AS_SZ, Ag0 + kb);
        cp16(sA1 + s*AS_SZ, Ag1 + kb);
        cp16(sB0 + s*BS_SZ, Bg0 + (size_t)kb*K);
        cp16(sB1 + s*BS_SZ, Bg1 + (size_t)kb*K);
        CP_COMMIT();
    }

    for (int kt = 0; kt < KT; kt++) {
        CP_WAIT2();
        __syncthreads();
        const int st = kt & (STAGES-1);
        const float* Ast = As + st*AS_SZ;
        const float* Bst = Bs + st*BS_SZ;

        #pragma unroll
        for (int half = 0; half < 2; half++) {
            const int kk = half * 8;
            unsigned af[2][4], bfr[8][2];
            #pragma unroll
            for (int mt = 0; mt < 2; mt++) {
                const int m = wm + mt*16 + grp;
                af[mt][0] = f2tf(Ast[(m  )*AS_STRIDE + kk + t4    ]);
                af[mt][1] = f2tf(Ast[(m+8)*AS_STRIDE + kk + t4    ]);
                af[mt][2] = f2tf(Ast[(m  )*AS_STRIDE + kk + t4 + 4]);
                af[mt][3] = f2tf(Ast[(m+8)*AS_STRIDE + kk + t4 + 4]);
            }
            #pragma unroll
            for (int nt = 0; nt < 8; nt++) {
                const int n = wn + nt*8 + grp;
                bfr[nt][0] = f2tf(Bst[(kk + t4    )*BS_STRIDE + n]);
                bfr[nt][1] = f2tf(Bst[(kk + t4 + 4)*BS_STRIDE + n]);
            }
            #pragma unroll
            for (int mt = 0; mt < 2; mt++)
                #pragma unroll
                for (int nt = 0; nt < 8; nt++)
                    MMA_TF32(c[mt][nt], af[mt], bfr[nt][0], bfr[nt][1]);

            if (half == 0) {
                // refill stage (kt+3): buffer (kt-1)&3, safe after this iter's sync
                const int kn = kt + 3;
                if (kn < KT) {
                    const int sn = kn & (STAGES-1);
                    const int kb = kn * 16;
                    cp16(sA0 + sn*AS_SZ, Ag0 + kb);
                    cp16(sA1 + sn*AS_SZ, Ag1 + kb);
                    cp16(sB0 + sn*BS_SZ, Bg0 + (size_t)kb*K);
                    cp16(sB1 + sn*BS_SZ, Bg1 + (size_t)kb*K);
                }
                CP_COMMIT();
            }
        }
    }

    #pragma unroll
    for (int mt = 0; mt < 2; mt++)
        #pragma unroll
        for (int nt = 0; nt < 8; nt++) {
            int r  = row0 + wm + mt*16 + grp;
            int cc = col0 + wn + nt*8 + t4*2;
            #pragma unroll
            for (int half = 0; half < 2; half++) {
                int rr = r + half*8;
                #pragma unroll
                for (int e = 0; e < 2; e++) {
                    float val = c[mt][nt][half*2 + e];
                    int col = cc + e;
                    if (bias) val += bias[col];
                    if (GELU) val = 0.5f*val*(1.0f + erff(val*0.70710678118654752f));
                    C[(size_t)rr*K + col] = val;
                }
            }
        }
}

// ---------------- BD_raw via tensor cores ----------------
// bdout[b,h,i,t] = sum_d (q[b,i,h,d] + vvec[h,d]) * r[t,h,d]
#define RS_STRIDE 68
__global__ __launch_bounds__(256)
void bd_mma(const float* __restrict__ q, const float* __restrict__ r,
            const float* __restrict__ vvec, float* __restrict__ bdout) {
    __shared__ float Rs[64*RS_STRIDE];
    const int t0 = blockIdx.x * 64;
    const int i0 = blockIdx.y * 128;
    const int h = blockIdx.z & (HN-1), b = blockIdx.z >> 4;
    const int tid = threadIdx.x;
    const int lane = tid & 31, wid = tid >> 5;
    const int grp = lane >> 2, t4 = lane & 3;
    const int i_r0 = i0 + wid*16 + grp, i_r1 = i_r0 + 8;

    unsigned qf[8][4];
    {
        const float* qp0 = q + ((size_t)(b*QN + i_r0))*DM + h*DH;
        const float* qp1 = q + ((size_t)(b*QN + i_r1))*DM + h*DH;
        const float* up  = vvec + h*DH;
        #pragma unroll
        for (int ks = 0; ks < 8; ks++) {
            int k0 = ks*8 + t4;
            float u0 = up[k0], u1 = up[k0+4];
            qf[ks][0] = f2tf(qp0[k0]   + u0);
            qf[ks][1] = f2tf(qp1[k0]   + u0);
            qf[ks][2] = f2tf(qp0[k0+4] + u1);
            qf[ks][3] = f2tf(qp1[k0+4] + u1);
        }
    }
    #pragma unroll
    for (int t = 0; t < 4; t++) {
        int idx = tid + 256*t;
        int row = idx >> 4, c4 = (idx & 15) * 4;
        float4 rr = *(const float4*)&r[((size_t)(t0 + row))*DM + h*DH + c4];
        float* rd = Rs + row*RS_STRIDE + c4;
        rd[0]=tfv(rr.x); rd[1]=tfv(rr.y); rd[2]=tfv(rr.z); rd[3]=tfv(rr.w);
    }
    __syncthreads();

    float s[8][4];
    #pragma unroll
    for (int nt = 0; nt < 8; nt++)
        #pragma unroll
        for (int e = 0; e < 4; e++) s[nt][e] = 0.0f;

    #pragma unroll
    for (int ks = 0; ks < 8; ks++)
        #pragma unroll
        for (int nt = 0; nt < 8; nt++) {
            unsigned b0 = __float_as_uint(Rs[(nt*8+grp)*RS_STRIDE + ks*8 + t4]);
            unsigned b1 = __float_as_uint(Rs[(nt*8+grp)*RS_STRIDE + ks*8 + t4 + 4]);
            MMA_TF32(s[nt], qf[ks], b0, b1);
        }

    float* o0 = bdout + (((size_t)(b*HN + h))*QN + i_r0)*KLEN + t0;
    float* o1 = bdout + (((size_t)(b*HN + h))*QN + i_r1)*KLEN + t0;
    #pragma unroll
    for (int nt = 0; nt < 8; nt++) {
        int cc = nt*8 + 2*t4;
        *(float2*)&o0[cc] = make_float2(s[nt][0], s[nt][1]);
        *(float2*)&o1[cc] = make_float2(s[nt][2], s[nt][3]);
    }
}

// ---------------- MMA flash attention ----------------
#define KS_STRIDE 68
#define VS_STRIDE 72
#define PS_STRIDE 68
#define FLASH_SMEM ((64*KS_STRIDE + 64*VS_STRIDE + 128*PS_STRIDE) * 4)

__global__ __launch_bounds__(256)
void flashmma(const float* __restrict__ q, const float* __restrict__ k,
              const float* __restrict__ v, const float* __restrict__ bd,
              const float* __restrict__ uvec, float* __restrict__ out,
              int klen, int useMask) {
    extern __shared__ float sm[];
    float* Ks = sm;
    float* Vs = Ks + 64*KS_STRIDE;
    float* Ps = Vs + 64*VS_STRIDE;

    const int i0 = blockIdx.x * 128;
    const int h = blockIdx.y, b = blockIdx.z;
    const int tid = threadIdx.x;
    const int lane = tid & 31, wid = tid >> 5;
    const int grp = lane >> 2, t4 = lane & 3;
    const int r0 = wid*16 + grp, r1 = r0 + 8;
    const int i_r0 = i0 + r0, i_r1 = i0 + r1;

    unsigned qf[8][4];
    {
        const float* qp0 = q + ((size_t)(b*QN + i_r0))*DM + h*DH;
        const float* qp1 = q + ((size_t)(b*QN + i_r1))*DM + h*DH;
        #pragma unroll
        for (int ks = 0; ks < 8; ks++) {
            int k0 = ks*8 + t4;
            float u0 = uvec ? uvec[h*DH + k0]     : 0.0f;
            float u1 = uvec ? uvec[h*DH + k0 + 4] : 0.0f;
            qf[ks][0] = f2tf(qp0[k0]   + u0);
            qf[ks][1] = f2tf(qp1[k0]   + u0);
            qf[ks][2] = f2tf(qp0[k0+4] + u1);
            qf[ks][3] = f2tf(qp1[k0+4] + u1);
        }
    }

    float m0 = -INFINITY, m1 = -INFINITY, l0 = 0.0f, l1 = 0.0f;
    float o[8][4];
    #pragma unroll
    for (int nt = 0; nt < 8; nt++)
        #pragma unroll
        for (int e = 0; e < 4; e++) o[nt][e] = 0.0f;

    const float* bdr0 = bd ? bd + (((size_t)(b*HN + h))*QN + i_r0)*KLEN : (const float*)0;
    const float* bdr1 = bd ? bd + (((size_t)(b*HN + h))*QN + i_r1)*KLEN : (const float*)0;

    int lastj = klen - 1;
    if (useMask) { int lm = i0 + 127 + MN; if (lm < lastj) lastj = lm; }

    for (int j0 = 0; j0 <= lastj; j0 += 64) {
        __syncthreads();
        #pragma unroll
        for (int t = 0; t < 4; t++) {
            int idx = tid + 256*t;
            int row = idx >> 4, c4 = (idx & 15) * 4;
            size_t gb = ((size_t)(b*klen + j0 + row))*DM + h*DH + c4;
            float4 kk4 = *(const float4*)&k[gb];
            float4 vv4 = *(const float4*)&v[gb];
            float* kd = Ks + row*KS_STRIDE + c4;
            kd[0]=tfv(kk4.x); kd[1]=tfv(kk4.y); kd[2]=tfv(kk4.z); kd[3]=tfv(kk4.w);
            float* vd = Vs + row*VS_STRIDE + c4;
            vd[0]=tfv(vv4.x); vd[1]=tfv(vv4.y); vd[2]=tfv(vv4.z); vd[3]=tfv(vv4.w);
        }
        __syncthreads();

        float bdv[8][4];
        if (bd) {
            #pragma unroll
            for (int nt = 0; nt < 8; nt++) {
                int jA = j0 + nt*8 + 2*t4;
                int jr0 = jA - i_r0 + (QN-1);
                int jr1 = jA - i_r1 + (QN-1);
                jr0 = max(0, min(KLEN-2, jr0));
                jr1 = max(0, min(KLEN-2, jr1));
                bdv[nt][0] = bdr0[jr0];   bdv[nt][1] = bdr0[jr0+1];
                bdv[nt][2] = bdr1[jr1];   bdv[nt][3] = bdr1[jr1+1];
            }
        }

        float s[8][4];
        #pragma unroll
        for (int nt = 0; nt < 8; nt++)
            #pragma unroll
            for (int e = 0; e < 4; e++) s[nt][e] = 0.0f;
        #pragma unroll
        for (int ks = 0; ks < 8; ks++)
            #pragma unroll
            for (int nt = 0; nt < 8; nt++) {
                unsigned b0 = __float_as_uint(Ks[(nt*8+grp)*KS_STRIDE + ks*8 + t4]);
                unsigned b1 = __float_as_uint(Ks[(nt*8+grp)*KS_STRIDE + ks*8 + t4 + 4]);
                MMA_TF32(s[nt], qf[ks], b0, b1);
            }

        float mc0 = -INFINITY, mc1 = -INFINITY;
        #pragma unroll
        for (int nt = 0; nt < 8; nt++) {
            int jA = j0 + nt*8 + 2*t4;
            int jB = jA + 1;
            float v0 = s[nt][0], v1 = s[nt][1], v2 = s[nt][2], v3 = s[nt][3];
            if (bd) { v0 += bdv[nt][0]; v1 += bdv[nt][1]; v2 += bdv[nt][2]; v3 += bdv[nt][3]; }
            v0 *= 0.125f; v1 *= 0.125f; v2 *= 0.125f; v3 *= 0.125f;
            if (useMask) {
                if (jA > i_r0 + MN) v0 = -INFINITY;
                if (jB > i_r0 + MN) v1 = -INFINITY;
                if (jA > i_r1 + MN) v2 = -INFINITY;
                if (jB > i_r1 + MN) v3 = -INFINITY;
            }
            s[nt][0]=v0; s[nt][1]=v1; s[nt][2]=v2; s[nt][3]=v3;
            mc0 = fmaxf(mc0, fmaxf(v0, v1));
            mc1 = fmaxf(mc1, fmaxf(v2, v3));
        }
        mc0 = fmaxf(mc0, __shfl_xor_sync(0xffffffffu, mc0, 1));
        mc0 = fmaxf(mc0, __shfl_xor_sync(0xffffffffu, mc0, 2));
        mc1 = fmaxf(mc1, __shfl_xor_sync(0xffffffffu, mc1, 1));
        mc1 = fmaxf(mc1, __shfl_xor_sync(0xffffffffu, mc1, 2));

        float nm0 = fmaxf(m0, mc0), nm1 = fmaxf(m1, mc1);
        float corr0 = __expf(m0 - nm0), corr1 = __expf(m1 - nm1);
        float ps0 = 0.0f, ps1 = 0.0f;
        #pragma unroll
        for (int nt = 0; nt < 8; nt++) {
            float p0 = __expf(s[nt][0] - nm0);
            float p1 = __expf(s[nt][1] - nm0);
            float p2 = __expf(s[nt][2] - nm1);
            float p3 = __expf(s[nt][3] - nm1);
            ps0 += p0 + p1; ps1 += p2 + p3;
            int cc = nt*8 + 2*t4;
            Ps[r0*PS_STRIDE + cc]     = __uint_as_float(f2tf(p0));
            Ps[r0*PS_STRIDE + cc + 1] = __uint_as_float(f2tf(p1));
            Ps[r1*PS_STRIDE + cc]     = __uint_as_float(f2tf(p2));
            Ps[r1*PS_STRIDE + cc + 1] = __uint_as_float(f2tf(p3));
        }
        ps0 += __shfl_xor_sync(0xffffffffu, ps0, 1);
        ps0 += __shfl_xor_sync(0xffffffffu, ps0, 2);
        ps1 += __shfl_xor_sync(0xffffffffu, ps1, 1);
        ps1 += __shfl_xor_sync(0xffffffffu, ps1, 2);
        l0 = l0 * corr0 + ps0;  m0 = nm0;
        l1 = l1 * corr1 + ps1;  m1 = nm1;
        #pragma unroll
        for (int nt = 0; nt < 8; nt++) {
            o[nt][0] *= corr0; o[nt][1] *= corr0;
            o[nt][2] *= corr1; o[nt][3] *= corr1;
        }
        __syncwarp();

        #pragma unroll
        for (int ks = 0; ks < 8; ks++) {
            unsigned a[4];
            a[0] = __float_as_uint(Ps[r0*PS_STRIDE + ks*8 + t4]);
            a[1] = __float_as_uint(Ps[r1*PS_STRIDE + ks*8 + t4]);
            a[2] = __float_as_uint(Ps[r0*PS_STRIDE + ks*8 + t4 + 4]);
            a[3] = __float_as_uint(Ps[r1*PS_STRIDE + ks*8 + t4 + 4]);
            #pragma unroll
            for (int nt = 0; nt < 8; nt++) {
                unsigned b0 = __float_as_uint(Vs[(ks*8+t4)*VS_STRIDE + nt*8 + grp]);
                unsigned b1 = __float_as_uint(Vs[(ks*8+t4+4)*VS_STRIDE + nt*8 + grp]);
                MMA_TF32(o[nt], a, b0, b1);
            }
        }
    }

    const float inv0 = 1.0f / l0, inv1 = 1.0f / l1;
    float* op0 = out + ((size_t)(b*QN + i_r0))*DM + h*DH;
    float* op1 = out + ((size_t)(b*QN + i_r1))*DM + h*DH;
    #pragma unroll
    for (int nt = 0; nt < 8; nt++) {
        int cc = nt*8 + 2*t4;
        *(float2*)&op0[cc] = make_float2(o[nt][0]*inv0, o[nt][1]*inv0);
        *(float2*)&op1[cc] = make_float2(o[nt][2]*inv1, o[nt][3]*inv1);
    }
}

// ---------------- residual add + LayerNorm ----------------
__global__ __launch_bounds__(256)
void ln_kernel(float* __restrict__ x, const float* __restrict__ y,
               const float* __restrict__ gamma, const float* __restrict__ beta) {
    const int row = blockIdx.x;
    const int tid = threadIdx.x;
    __shared__ float red[256];

    float s[4];
    float local = 0.0f;
    #pragma unroll
    for (int kk = 0; kk < 4; kk++) {
        int c = tid + kk*256;
        float val = x[(size_t)row*DM + c] + y[(size_t)row*DM + c];
        s[kk] = val;
        local += val;
    }
    red[tid] = local;
    __syncthreads();
    for (int t = 128; t > 0; t >>= 1) {
        if (tid < t) red[tid] += red[tid+t];
        __syncthreads();
    }
    const float mu = red[0] * (1.0f / DM);
    __syncthreads();

    local = 0.0f;
    #pragma unroll
    for (int kk = 0; kk < 4; kk++) {
        float dlt = s[kk] - mu;
        local += dlt * dlt;
    }
    red[tid] = local;
    __syncthreads();
    for (int t = 128; t > 0; t >>= 1) {
        if (tid < t) red[tid] += red[tid+t];
        __syncthreads();
    }
    const float rstd = rsqrtf(red[0] * (1.0f / DM) + 1e-5f);
    __syncthreads();

    #pragma unroll
    for (int kk = 0; kk < 4; kk++) {
        int c = tid + kk*256;
        x[(size_t)row*DM + c] = (s[kk] - mu) * rstd * gamma[c] + beta[c];
    }
}

// ---------------- host orchestration ----------------
static inline void run_gemm(const float* A, const float* B, const float* bias,
                            float* C, int N, int D, int K, bool gelu) {
    dim3 grid(K/128, N/128);
    if (gelu) mm_tf32<true ><<<grid, 256, MM_SMEM>>>(A, B, bias, C, N, D, K);
    else      mm_tf32<false><<<grid, 256, MM_SMEM>>>(A, B, bias, C, N, D, K);
}

extern "C" void kernel_launch(void* const* d_in, const int* in_sizes, int n_in,
                              void* d_out, int out_size) {
    const float* enc    = (const float*)d_in[0];
    const float* mems   = (const float*)d_in[1];
    const float* emb    = (const float*)d_in[2];
    const float* u      = (const float*)d_in[3];
    const float* vpar   = (const float*)d_in[4];
    const float* saWq   = (const float*)d_in[5];
    const float* saWk   = (const float*)d_in[6];
    const float* saWv   = (const float*)d_in[7];
    const float* saWr   = (const float*)d_in[8];
    const float* safcW  = (const float*)d_in[9];
    const float* safcB  = (const float*)d_in[10];
    const float* ln1g   = (const float*)d_in[11];
    const float* ln1b   = (const float*)d_in[12];
    const float* caWq   = (const float*)d_in[13];
    const float* caWk   = (const float*)d_in[14];
    const float* caWv   = (const float*)d_in[15];
    const float* cafcW  = (const float*)d_in[16];
    const float* cafcB  = (const float*)d_in[17];
    const float* ln2g   = (const float*)d_in[18];
    const float* ln2b   = (const float*)d_in[19];
    const float* ffW1   = (const float*)d_in[20];
    const float* ffb1   = (const float*)d_in[21];
    const float* ffW2   = (const float*)d_in[22];
    const float* ffb2   = (const float*)d_in[23];
    const float* ln3g   = (const float*)d_in[24];
    const float* ln3b   = (const float*)d_in[25];
    const float* outW   = (const float*)d_in[26];
    const int*   ids    = (const int*)  d_in[27];
    float* out = (float*)d_out;

    float *x, *memb, *qb, *kb, *vb, *rb, *remb, *att, *tmp, *ff, *bdb;
    cudaGetSymbolAddress((void**)&x,    g_x);
    cudaGetSymbolAddress((void**)&memb, g_mem);
    cudaGetSymbolAddress((void**)&qb,   g_q);
    cudaGetSymbolAddress((void**)&kb,   g_k);
    cudaGetSymbolAddress((void**)&vb,   g_v);
    cudaGetSymbolAddress((void**)&rb,   g_r);
    cudaGetSymbolAddress((void**)&remb, g_remb);
    cudaGetSymbolAddress((void**)&att,  g_att);
    cudaGetSymbolAddress((void**)&tmp,  g_tmp);
    cudaGetSymbolAddress((void**)&ff,   g_ff);
    cudaGetSymbolAddress((void**)&bdb,  g_bd);

    static int smem_set = 0;
    if (!smem_set) {
        cudaFuncSetAttribute(flashmma, cudaFuncAttributeMaxDynamicSharedMemorySize,
                             FLASH_SMEM);
        cudaFuncSetAttribute(mm_tf32<true >, cudaFuncAttributeMaxDynamicSharedMemorySize,
                             MM_SMEM);
        cudaFuncSetAttribute(mm_tf32<false>, cudaFuncAttributeMaxDynamicSharedMemorySize,
                             MM_SMEM);
        smem_set = 1;
    }

    embed_kernel<<<(BN*QN*DM + 255)/256, 256>>>(ids, emb, x);
    remb_kernel <<<(KLEN*DM + 255)/256, 256>>>(remb);

    dim3 flash_grid(QN/128, HN, BN);
    dim3 bd_grid(KLEN/64, QN/128, BN*HN);

    for (int l = 0; l < LNUM; l++) {
        // ---- self-attention (TransformerXL relative) ----
        concat_kernel<<<(BN*KLEN*DM + 255)/256, 256>>>(
            mems + (size_t)l*BN*MN*DM, x, memb);

        run_gemm(x,    saWq + (size_t)l*DM*DM, nullptr, qb, BN*QN,  DM, DM, false);
        run_gemm(memb, saWk + (size_t)l*DM*DM, nullptr, kb, BN*KLEN,DM, DM, false);
        run_gemm(memb, saWv + (size_t)l*DM*DM, nullptr, vb, BN*KLEN,DM, DM, false);
        run_gemm(remb, saWr + (size_t)l*DM*DM, nullptr, rb, KLEN,   DM, DM, false);

        bd_mma<<<bd_grid, 256>>>(qb, rb, vpar, bdb);
        flashmma<<<flash_grid, 256, FLASH_SMEM>>>(qb, kb, vb, bdb, u, att, KLEN, 1);

        run_gemm(att, safcW + (size_t)l*DM*DM, safcB + (size_t)l*DM,
                 tmp, BN*QN, DM, DM, false);
        ln_kernel<<<BN*QN, 256>>>(x, tmp, ln1g + (size_t)l*DM, ln1b + (size_t)l*DM);

        // ---- cross-attention ----
        run_gemm(x,   caWq + (size_t)l*DM*DM, nullptr, qb, BN*QN, DM, DM, false);
        run_gemm(enc, caWk + (size_t)l*DM*DM, nullptr, kb, BN*EN, DM, DM, false);
        run_gemm(enc, caWv + (size_t)l*DM*DM, nullptr, vb, BN*EN, DM, DM, false);

        flashmma<<<flash_grid, 256, FLASH_SMEM>>>(qb, kb, vb, nullptr, nullptr,
                                                  att, EN, 0);

        run_gemm(att, cafcW + (size_t)l*DM*DM, cafcB + (size_t)l*DM,
                 tmp, BN*QN, DM, DM, false);
        ln_kernel<<<BN*QN, 256>>>(x, tmp, ln2g + (size_t)l*DM, ln2b + (size_t)l*DM);

        // ---- feed-forward ----
        run_gemm(x,  ffW1 + (size_t)l*DM*FFN, ffb1 + (size_t)l*FFN,
                 ff, BN*QN, DM, FFN, true);
        run_gemm(ff, ffW2 + (size_t)l*FFN*DM, ffb2 + (size_t)l*DM,
                 tmp, BN*QN, FFN, DM, false);
        ln_kernel<<<BN*QN, 256>>>(x, tmp, ln3g + (size_t)l*DM, ln3b + (size_t)l*DM);
    }

    // ---- output projection ----
    run_gemm(x, outW, nullptr, out, BN*QN, DM, VN, false);
}

// round 7
// speedup vs baseline: 14.0680x; 1.0132x over previous
#include <cuda_runtime.h>
#include <math.h>

// Problem constants
#define LNUM 4
#define DM   1024
#define HN   16
#define DH   64
#define FFN  4096
#define VN   8192
#define BN   4
#define QN   512
#define MN   512
#define EN   512
#define KLEN 1024   // M + Q

// ---------------- scratch (device globals; no allocation) ----------------
__device__ float g_x    [BN*QN*DM];
__device__ float g_mem  [BN*KLEN*DM];
__device__ float g_q    [BN*QN*DM];
__device__ float g_remb [KLEN*DM];
__device__ float g_att  [BN*QN*DM];
__device__ float g_tmp  [BN*QN*DM];
__device__ float g_ff   [BN*QN*FFN];
__device__ float g_bd   [BN*HN*QN*KLEN];      // relative-position BD_raw
// fused projections
__device__ float g_qkv  [BN*KLEN*3072];       // memb @ [Wq|Wk|Wv]
__device__ float g_cakv [BN*EN*8192];         // enc @ [Wk|Wv] x 4 layers
__device__ float g_r4   [KLEN*4096];          // remb @ Wr x 4 layers
// fused weights (built per call)
__device__ float g_wqkv [LNUM*DM*3072];
__device__ float g_wcakv[DM*8192];
__device__ float g_wr4  [DM*4096];

// ---------------- tf32 helpers ----------------
__device__ __forceinline__ unsigned f2tf(float x) {
    unsigned u; asm("cvt.rna.tf32.f32 %0, %1;" : "=r"(u) : "f"(x)); return u;
}
__device__ __forceinline__ float tfv(float x) { return __uint_as_float(f2tf(x)); }

#define MMA_TF32(C, A, B0, B1)                                                \
    asm volatile(                                                             \
        "mma.sync.aligned.m16n8k8.row.col.f32.tf32.tf32.f32 "                 \
        "{%0,%1,%2,%3}, {%4,%5,%6,%7}, {%8,%9}, {%0,%1,%2,%3};"               \
        : "+f"((C)[0]), "+f"((C)[1]), "+f"((C)[2]), "+f"((C)[3])              \
        : "r"((A)[0]), "r"((A)[1]), "r"((A)[2]), "r"((A)[3]),                 \
          "r"(B0), "r"(B1))

__device__ __forceinline__ void cp16(float* dst, const float* src) {
    unsigned d = (unsigned)__cvta_generic_to_shared(dst);
    asm volatile("cp.async.cg.shared.global [%0], [%1], 16;\n" :: "r"(d), "l"(src));
}
#define CP_COMMIT()  asm volatile("cp.async.commit_group;\n" ::)

// ---------------- elementwise kernels ----------------
__global__ void embed_kernel(const int* __restrict__ ids,
                             const float* __restrict__ emb,
                             float* __restrict__ x) {
    int idx = blockIdx.x * blockDim.x + threadIdx.x;
    if (idx >= BN*QN*DM) return;
    int row = idx / DM;
    int d   = idx - row * DM;
    int tok = ids[row];
    x[idx] = emb[tok * DM + d] * 32.0f;
}

__global__ void remb_kernel(float* __restrict__ remb) {
    int idx = blockIdx.x * blockDim.x + threadIdx.x;
    if (idx >= KLEN*DM) return;
    int p = idx / DM;
    int d = idx - p * DM;
    float pos = (float)(KLEN - 1 - p);
    int k = (d < DM/2) ? d : d - DM/2;
    float invf = powf(10000.0f, -(float)k / (float)(DM/2));
    float a = pos * invf;
    remb[idx] = (d < DM/2) ? sinf(a) : cosf(a);
}

__global__ void concat_kernel(const float* __restrict__ mems_l,
                              const float* __restrict__ x,
                              float* __restrict__ mem) {
    int idx = blockIdx.x * blockDim.x + threadIdx.x;
    if (idx >= BN*KLEN*DM) return;
    int d   = idx % DM;
    int rem = idx / DM;
    int j   = rem % KLEN;
    int b   = rem / KLEN;
    float val;
    if (j < MN) val = mems_l[(b*MN + j)*DM + d];
    else        val = x[(b*QN + (j - MN))*DM + d];
    mem[idx] = val;
}

// ---------------- weight fusion kernels ----------------
__global__ void wqkv_concat(const float* __restrict__ wq,
                            const float* __restrict__ wk,
                            const float* __restrict__ wv,
                            float* __restrict__ dst) {
    int idx = blockIdx.x * blockDim.x + threadIdx.x;     // L*D*3072
    if (idx >= LNUM*DM*3072) return;
    int c  = idx % 3072;
    int ld = idx / 3072;          // l*DM + d
    int sel = c >> 10, cc = c & 1023;
    const float* w = (sel == 0) ? wq : (sel == 1) ? wk : wv;
    dst[idx] = w[(size_t)ld*DM + cc];
}

__global__ void wcakv_concat(const float* __restrict__ wk,
                             const float* __restrict__ wv,
                             float* __restrict__ dst) {
    int idx = blockIdx.x * blockDim.x + threadIdx.x;     // D*8192
    if (idx >= DM*8192) return;
    int c = idx % 8192;
    int d = idx / 8192;
    int l = c >> 11, cc = c & 2047;
    float val;
    if (cc < 1024) val = wk[((size_t)l*DM + d)*DM + cc];
    else           val = wv[((size_t)l*DM + d)*DM + (cc - 1024)];
    dst[idx] = val;
}

__global__ void wr4_concat(const float* __restrict__ wr,
                           float* __restrict__ dst) {
    int idx = blockIdx.x * blockDim.x + threadIdx.x;     // D*4096
    if (idx >= DM*4096) return;
    int c = idx % 4096;
    int d = idx / 4096;
    int l = c >> 10;
    dst[idx] = wr[((size_t)l*DM + d)*DM + (c & 1023)];
}

// ---------------- tf32 tensor-core GEMM, STG-stage cp.async pipeline -------
// C[N,K] = A[N,D] @ B[D,K] (+bias, optional GELU). N,K mult of 128, D mult 16.
#define AS_STRIDE 20
#define BS_STRIDE 136
#define AS_SZ     (128*AS_STRIDE)    // floats per stage
#define BS_SZ     (16*BS_STRIDE)
#define MM_SMEM(STG)   ((STG)*(AS_SZ+BS_SZ)*4)

template<bool GELU, int STG>
__global__ __launch_bounds__(256, (STG==3) ? 2 : 1)
void mm_tf32(const float* __restrict__ A, const float* __restrict__ B,
             const float* __restrict__ bias, float* __restrict__ C,
             int N, int D, int K) {
    extern __shared__ float sm[];
    float* As = sm;                   // [STG][128][AS_STRIDE]
    float* Bs = sm + STG*AS_SZ;      // [STG][16][BS_STRIDE]

    const int tid  = threadIdx.x;
    const int row0 = blockIdx.y * 128, col0 = blockIdx.x * 128;
    const int lane = tid & 31, wid = tid >> 5;
    const int grp  = lane >> 2, t4 = lane & 3;
    const int wm   = (wid & 3) * 32, wn = (wid >> 2) * 64;

    const int ar = tid >> 2, ak = (tid & 3) * 4;   // A loader: rows ar, ar+64
    const int bk = tid >> 5, bc = (tid & 31) * 4;  // B loader: k rows bk, bk+8

    const float* Ag0 = A + (size_t)(row0 + ar)      * D + ak;
    const float* Ag1 = A + (size_t)(row0 + ar + 64) * D + ak;
    const float* Bg0 = B + (size_t)bk       * K + col0 + bc;
    const float* Bg1 = B + (size_t)(bk + 8) * K + col0 + bc;

    float* sA0 = As + ar*AS_STRIDE + ak;
    float* sA1 = As + (ar+64)*AS_STRIDE + ak;
    float* sB0 = Bs + bk*BS_STRIDE + bc;
    float* sB1 = Bs + (bk+8)*BS_STRIDE + bc;

    const int KT = D >> 4;

    float c[2][8][4];
    #pragma unroll
    for (int i = 0; i < 2; i++)
        #pragma unroll
        for (int j = 0; j < 8; j++)
            #pragma unroll
            for (int t = 0; t < 4; t++) c[i][j][t] = 0.0f;

    // prologue: stages 0..STG-2 in flight
    #pragma unroll
    for (int s = 0; s < STG-1; s++) {
        const int kb = s * 16;
        cp16(sA0 + s*AS_SZ, Ag0 + kb);
        cp16(sA1 + s*AS_SZ, Ag1 + kb);
        cp16(sB0 + s*BS_SZ, Bg0 + (size_t)kb*K);
        cp16(sB1 + s*BS_SZ, Bg1 + (size_t)kb*K);
        CP_COMMIT();
    }

    for (int kt = 0; kt < KT; kt++) {
        if (STG == 3) asm volatile("cp.async.wait_group 1;\n" ::);
        else          asm volatile("cp.async.wait_group 2;\n" ::);
        __syncthreads();
        const int st = kt % STG;
        const float* Ast = As + st*AS_SZ;
        const float* Bst = Bs + st*BS_SZ;

        #pragma unroll
        for (int half = 0; half < 2; half++) {
            const int kk = half * 8;
            unsigned af[2][4], bfr[8][2];
            #pragma unroll
            for (int mt = 0; mt < 2; mt++) {
                const int m = wm + mt*16 + grp;
                af[mt][0] = f2tf(Ast[(m  )*AS_STRIDE + kk + t4    ]);
                af[mt][1] = f2tf(Ast[(m+8)*AS_STRIDE + kk + t4    ]);
                af[mt][2] = f2tf(Ast[(m  )*AS_STRIDE + kk + t4 + 4]);
                af[mt][3] = f2tf(Ast[(m+8)*AS_STRIDE + kk + t4 + 4]);
            }
            #pragma unroll
            for (int nt = 0; nt < 8; nt++) {
                const int n = wn + nt*8 + grp;
                bfr[nt][0] = f2tf(Bst[(kk + t4    )*BS_STRIDE + n]);
                bfr[nt][1] = f2tf(Bst[(kk + t4 + 4)*BS_STRIDE + n]);
            }
            #pragma unroll
            for (int mt = 0; mt < 2; mt++)
                #pragma unroll
                for (int nt = 0; nt < 8; nt++)
                    MMA_TF32(c[mt][nt], af[mt], bfr[nt][0], bfr[nt][1]);

            if (half == 0) {
                // refill stage kt+STG-1 into the slot consumed at iter kt-1
                const int kn = kt + STG - 1;
                if (kn < KT) {
                    const int sn = kn % STG;
                    const int kb = kn * 16;
                    cp16(sA0 + sn*AS_SZ, Ag0 + kb);
                    cp16(sA1 + sn*AS_SZ, Ag1 + kb);
                    cp16(sB0 + sn*BS_SZ, Bg0 + (size_t)kb*K);
                    cp16(sB1 + sn*BS_SZ, Bg1 + (size_t)kb*K);
                }
                CP_COMMIT();
            }
        }
    }

    #pragma unroll
    for (int mt = 0; mt < 2; mt++)
        #pragma unroll
        for (int nt = 0; nt < 8; nt++) {
            int r  = row0 + wm + mt*16 + grp;
            int cc = col0 + wn + nt*8 + t4*2;
            #pragma unroll
            for (int half = 0; half < 2; half++) {
                int rr = r + half*8;
                #pragma unroll
                for (int e = 0; e < 2; e++) {
                    float val = c[mt][nt][half*2 + e];
                    int col = cc + e;
                    if (bias) val += bias[col];
                    if (GELU) val = 0.5f*val*(1.0f + erff(val*0.70710678118654752f));
                    C[(size_t)rr*K + col] = val;
                }
            }
        }
}

// ---------------- BD_raw via tensor cores ----------------
// bdout[b,h,i,t] = sum_d (q[i,h,d] + vvec[h,d]) * r[t,h,d]
#define RS_STRIDE 68
__global__ __launch_bounds__(256)
void bd_mma(const float* __restrict__ q, int qrs, size_t qbs,
            const float* __restrict__ r, int rrs,
            const float* __restrict__ vvec, float* __restrict__ bdout) {
    __shared__ float Rs[64*RS_STRIDE];
    const int t0 = blockIdx.x * 64;
    const int i0 = blockIdx.y * 128;
    const int h = blockIdx.z & (HN-1), b = blockIdx.z >> 4;
    const int tid = threadIdx.x;
    const int lane = tid & 31, wid = tid >> 5;
    const int grp = lane >> 2, t4 = lane & 3;
    const int i_r0 = i0 + wid*16 + grp, i_r1 = i_r0 + 8;

    unsigned qf[8][4];
    {
        const float* qp0 = q + (size_t)b*qbs + (size_t)i_r0*qrs + h*DH;
        const float* qp1 = q + (size_t)b*qbs + (size_t)i_r1*qrs + h*DH;
        const float* up  = vvec + h*DH;
        #pragma unroll
        for (int ks = 0; ks < 8; ks++) {
            int k0 = ks*8 + t4;
            float u0 = up[k0], u1 = up[k0+4];
            qf[ks][0] = f2tf(qp0[k0]   + u0);
            qf[ks][1] = f2tf(qp1[k0]   + u0);
            qf[ks][2] = f2tf(qp0[k0+4] + u1);
            qf[ks][3] = f2tf(qp1[k0+4] + u1);
        }
    }
    #pragma unroll
    for (int t = 0; t < 4; t++) {
        int idx = tid + 256*t;
        int row = idx >> 4, c4 = (idx & 15) * 4;
        float4 rr = *(const float4*)&r[(size_t)(t0 + row)*rrs + h*DH + c4];
        float* rd = Rs + row*RS_STRIDE + c4;
        rd[0]=tfv(rr.x); rd[1]=tfv(rr.y); rd[2]=tfv(rr.z); rd[3]=tfv(rr.w);
    }
    __syncthreads();

    float s[8][4];
    #pragma unroll
    for (int nt = 0; nt < 8; nt++)
        #pragma unroll
        for (int e = 0; e < 4; e++) s[nt][e] = 0.0f;

    #pragma unroll
    for (int ks = 0; ks < 8; ks++)
        #pragma unroll
        for (int nt = 0; nt < 8; nt++) {
            unsigned b0 = __float_as_uint(Rs[(nt*8+grp)*RS_STRIDE + ks*8 + t4]);
            unsigned b1 = __float_as_uint(Rs[(nt*8+grp)*RS_STRIDE + ks*8 + t4 + 4]);
            MMA_TF32(s[nt], qf[ks], b0, b1);
        }

    float* o0 = bdout + (((size_t)(b*HN + h))*QN + i_r0)*KLEN + t0;
    float* o1 = bdout + (((size_t)(b*HN + h))*QN + i_r1)*KLEN + t0;
    #pragma unroll
    for (int nt = 0; nt < 8; nt++) {
        int cc = nt*8 + 2*t4;
        *(float2*)&o0[cc] = make_float2(s[nt][0], s[nt][1]);
        *(float2*)&o1[cc] = make_float2(s[nt][2], s[nt][3]);
    }
}

// ---------------- MMA flash attention (strided q/k/v) ----------------
#define KS_STRIDE 68
#define VS_STRIDE 72
#define PS_STRIDE 68
#define FLASH_SMEM ((64*KS_STRIDE + 64*VS_STRIDE + 128*PS_STRIDE) * 4)

__global__ __launch_bounds__(256)
void flashmma(const float* __restrict__ q, int qrs, size_t qbs,
              const float* __restrict__ k, const float* __restrict__ v,
              int kvrs, size_t kvbs,
              const float* __restrict__ bd, const float* __restrict__ uvec,
              float* __restrict__ out, int klen, int useMask) {
    extern __shared__ float sm[];
    float* Ks = sm;
    float* Vs = Ks + 64*KS_STRIDE;
    float* Ps = Vs + 64*VS_STRIDE;

    const int i0 = blockIdx.x * 128;
    const int h = blockIdx.y, b = blockIdx.z;
    const int tid = threadIdx.x;
    const int lane = tid & 31, wid = tid >> 5;
    const int grp = lane >> 2, t4 = lane & 3;
    const int r0 = wid*16 + grp, r1 = r0 + 8;
    const int i_r0 = i0 + r0, i_r1 = i0 + r1;

    unsigned qf[8][4];
    {
        const float* qp0 = q + (size_t)b*qbs + (size_t)i_r0*qrs + h*DH;
        const float* qp1 = q + (size_t)b*qbs + (size_t)i_r1*qrs + h*DH;
        #pragma unroll
        for (int ks = 0; ks < 8; ks++) {
            int k0 = ks*8 + t4;
            float u0 = uvec ? uvec[h*DH + k0]     : 0.0f;
            float u1 = uvec ? uvec[h*DH + k0 + 4] : 0.0f;
            qf[ks][0] = f2tf(qp0[k0]   + u0);
            qf[ks][1] = f2tf(qp1[k0]   + u0);
            qf[ks][2] = f2tf(qp0[k0+4] + u1);
            qf[ks][3] = f2tf(qp1[k0+4] + u1);
        }
    }

    float m0 = -INFINITY, m1 = -INFINITY, l0 = 0.0f, l1 = 0.0f;
    float o[8][4];
    #pragma unroll
    for (int nt = 0; nt < 8; nt++)
        #pragma unroll
        for (int e = 0; e < 4; e++) o[nt][e] = 0.0f;

    const float* bdr0 = bd ? bd + (((size_t)(b*HN + h))*QN + i_r0)*KLEN : (const float*)0;
    const float* bdr1 = bd ? bd + (((size_t)(b*HN + h))*QN + i_r1)*KLEN : (const float*)0;

    int lastj = klen - 1;
    if (useMask) { int lm = i0 + 127 + MN; if (lm < lastj) lastj = lm; }

    for (int j0 = 0; j0 <= lastj; j0 += 64) {
        __syncthreads();
        #pragma unroll
        for (int t = 0; t < 4; t++) {
            int idx = tid + 256*t;
            int row = idx >> 4, c4 = (idx & 15) * 4;
            size_t gb = (size_t)b*kvbs + (size_t)(j0 + row)*kvrs + h*DH + c4;
            float4 kk4 = *(const float4*)&k[gb];
            float4 vv4 = *(const float4*)&v[gb];
            float* kd = Ks + row*KS_STRIDE + c4;
            kd[0]=tfv(kk4.x); kd[1]=tfv(kk4.y); kd[2]=tfv(kk4.z); kd[3]=tfv(kk4.w);
            float* vd = Vs + row*VS_STRIDE + c4;
            vd[0]=tfv(vv4.x); vd[1]=tfv(vv4.y); vd[2]=tfv(vv4.z); vd[3]=tfv(vv4.w);
        }
        __syncthreads();

        float bdv[8][4];
        if (bd) {
            #pragma unroll
            for (int nt = 0; nt < 8; nt++) {
                int jA = j0 + nt*8 + 2*t4;
                int jr0 = jA - i_r0 + (QN-1);
                int jr1 = jA - i_r1 + (QN-1);
                jr0 = max(0, min(KLEN-2, jr0));
                jr1 = max(0, min(KLEN-2, jr1));
                bdv[nt][0] = bdr0[jr0];   bdv[nt][1] = bdr0[jr0+1];
                bdv[nt][2] = bdr1[jr1];   bdv[nt][3] = bdr1[jr1+1];
            }
        }

        float s[8][4];
        #pragma unroll
        for (int nt = 0; nt < 8; nt++)
            #pragma unroll
            for (int e = 0; e < 4; e++) s[nt][e] = 0.0f;
        #pragma unroll
        for (int ks = 0; ks < 8; ks++)
            #pragma unroll
            for (int nt = 0; nt < 8; nt++) {
                unsigned b0 = __float_as_uint(Ks[(nt*8+grp)*KS_STRIDE + ks*8 + t4]);
                unsigned b1 = __float_as_uint(Ks[(nt*8+grp)*KS_STRIDE + ks*8 + t4 + 4]);
                MMA_TF32(s[nt], qf[ks], b0, b1);
            }

        float mc0 = -INFINITY, mc1 = -INFINITY;
        #pragma unroll
        for (int nt = 0; nt < 8; nt++) {
            int jA = j0 + nt*8 + 2*t4;
            int jB = jA + 1;
            float v0 = s[nt][0], v1 = s[nt][1], v2 = s[nt][2], v3 = s[nt][3];
            if (bd) { v0 += bdv[nt][0]; v1 += bdv[nt][1]; v2 += bdv[nt][2]; v3 += bdv[nt][3]; }
            v0 *= 0.125f; v1 *= 0.125f; v2 *= 0.125f; v3 *= 0.125f;
            if (useMask) {
                if (jA > i_r0 + MN) v0 = -INFINITY;
                if (jB > i_r0 + MN) v1 = -INFINITY;
                if (jA > i_r1 + MN) v2 = -INFINITY;
                if (jB > i_r1 + MN) v3 = -INFINITY;
            }
            s[nt][0]=v0; s[nt][1]=v1; s[nt][2]=v2; s[nt][3]=v3;
            mc0 = fmaxf(mc0, fmaxf(v0, v1));
            mc1 = fmaxf(mc1, fmaxf(v2, v3));
        }
        mc0 = fmaxf(mc0, __shfl_xor_sync(0xffffffffu, mc0, 1));
        mc0 = fmaxf(mc0, __shfl_xor_sync(0xffffffffu, mc0, 2));
        mc1 = fmaxf(mc1, __shfl_xor_sync(0xffffffffu, mc1, 1));
        mc1 = fmaxf(mc1, __shfl_xor_sync(0xffffffffu, mc1, 2));

        float nm0 = fmaxf(m0, mc0), nm1 = fmaxf(m1, mc1);
        float corr0 = __expf(m0 - nm0), corr1 = __expf(m1 - nm1);
        float ps0 = 0.0f, ps1 = 0.0f;
        #pragma unroll
        for (int nt = 0; nt < 8; nt++) {
            float p0 = __expf(s[nt][0] - nm0);
            float p1 = __expf(s[nt][1] - nm0);
            float p2 = __expf(s[nt][2] - nm1);
            float p3 = __expf(s[nt][3] - nm1);
            ps0 += p0 + p1; ps1 += p2 + p3;
            int cc = nt*8 + 2*t4;
            Ps[r0*PS_STRIDE + cc]     = __uint_as_float(f2tf(p0));
            Ps[r0*PS_STRIDE + cc + 1] = __uint_as_float(f2tf(p1));
            Ps[r1*PS_STRIDE + cc]     = __uint_as_float(f2tf(p2));
            Ps[r1*PS_STRIDE + cc + 1] = __uint_as_float(f2tf(p3));
        }
        ps0 += __shfl_xor_sync(0xffffffffu, ps0, 1);
        ps0 += __shfl_xor_sync(0xffffffffu, ps0, 2);
        ps1 += __shfl_xor_sync(0xffffffffu, ps1, 1);
        ps1 += __shfl_xor_sync(0xffffffffu, ps1, 2);
        l0 = l0 * corr0 + ps0;  m0 = nm0;
        l1 = l1 * corr1 + ps1;  m1 = nm1;
        #pragma unroll
        for (int nt = 0; nt < 8; nt++) {
            o[nt][0] *= corr0; o[nt][1] *= corr0;
            o[nt][2] *= corr1; o[nt][3] *= corr1;
        }
        __syncwarp();

        #pragma unroll
        for (int ks = 0; ks < 8; ks++) {
            unsigned a[4];
            a[0] = __float_as_uint(Ps[r0*PS_STRIDE + ks*8 + t4]);
            a[1] = __float_as_uint(Ps[r1*PS_STRIDE + ks*8 + t4]);
            a[2] = __float_as_uint(Ps[r0*PS_STRIDE + ks*8 + t4 + 4]);
            a[3] = __float_as_uint(Ps[r1*PS_STRIDE + ks*8 + t4 + 4]);
            #pragma unroll
            for (int nt = 0; nt < 8; nt++) {
                unsigned b0 = __float_as_uint(Vs[(ks*8+t4)*VS_STRIDE + nt*8 + grp]);
                unsigned b1 = __float_as_uint(Vs[(ks*8+t4+4)*VS_STRIDE + nt*8 + grp]);
                MMA_TF32(o[nt], a, b0, b1);
            }
        }
    }

    const float inv0 = 1.0f / l0, inv1 = 1.0f / l1;
    float* op0 = out + ((size_t)(b*QN + i_r0))*DM + h*DH;
    float* op1 = out + ((size_t)(b*QN + i_r1))*DM + h*DH;
    #pragma unroll
    for (int nt = 0; nt < 8; nt++) {
        int cc = nt*8 + 2*t4;
        *(float2*)&op0[cc] = make_float2(o[nt][0]*inv0, o[nt][1]*inv0);
        *(float2*)&op1[cc] = make_float2(o[nt][2]*inv1, o[nt][3]*inv1);
    }
}

// ---------------- residual add + LayerNorm ----------------
__global__ __launch_bounds__(256)
void ln_kernel(float* __restrict__ x, const float* __restrict__ y,
               const float* __restrict__ gamma, const float* __restrict__ beta) {
    const int row = blockIdx.x;
    const int tid = threadIdx.x;
    __shared__ float red[256];

    float s[4];
    float local = 0.0f;
    #pragma unroll
    for (int kk = 0; kk < 4; kk++) {
        int c = tid + kk*256;
        float val = x[(size_t)row*DM + c] + y[(size_t)row*DM + c];
        s[kk] = val;
        local += val;
    }
    red[tid] = local;
    __syncthreads();
    for (int t = 128; t > 0; t >>= 1) {
        if (tid < t) red[tid] += red[tid+t];
        __syncthreads();
    }
    const float mu = red[0] * (1.0f / DM);
    __syncthreads();

    local = 0.0f;
    #pragma unroll
    for (int kk = 0; kk < 4; kk++) {
        float dlt = s[kk] - mu;
        local += dlt * dlt;
    }
    red[tid] = local;
    __syncthreads();
    for (int t = 128; t > 0; t >>= 1) {
        if (tid < t) red[tid] += red[tid+t];
        __syncthreads();
    }
    const float rstd = rsqrtf(red[0] * (1.0f / DM) + 1e-5f);
    __syncthreads();

    #pragma unroll
    for (int kk = 0; kk < 4; kk++) {
        int c = tid + kk*256;
        x[(size_t)row*DM + c] = (s[kk] - mu) * rstd * gamma[c] + beta[c];
    }
}

// ---------------- host orchestration ----------------
static inline void run_gemm(const float* A, const float* B, const float* bias,
                            float* C, int N, int D, int K, bool gelu) {
    dim3 grid(K/128, N/128);
    int ctas = (K/128) * (N/128);
    if (ctas >= 296) {
        if (gelu) mm_tf32<true ,3><<<grid, 256, MM_SMEM(3)>>>(A, B, bias, C, N, D, K);
        else      mm_tf32<false,3><<<grid, 256, MM_SMEM(3)>>>(A, B, bias, C, N, D, K);
    } else {
        if (gelu) mm_tf32<true ,4><<<grid, 256, MM_SMEM(4)>>>(A, B, bias, C, N, D, K);
        else      mm_tf32<false,4><<<grid, 256, MM_SMEM(4)>>>(A, B, bias, C, N, D, K);
    }
}

extern "C" void kernel_launch(void* const* d_in, const int* in_sizes, int n_in,
                              void* d_out, int out_size) {
    const float* enc    = (const float*)d_in[0];
    const float* mems   = (const float*)d_in[1];
    const float* emb    = (const float*)d_in[2];
    const float* u      = (const float*)d_in[3];
    const float* vpar   = (const float*)d_in[4];
    const float* saWq   = (const float*)d_in[5];
    const float* saWk   = (const float*)d_in[6];
    const float* saWv   = (const float*)d_in[7];
    const float* saWr   = (const float*)d_in[8];
    const float* safcW  = (const float*)d_in[9];
    const float* safcB  = (const float*)d_in[10];
    const float* ln1g   = (const float*)d_in[11];
    const float* ln1b   = (const float*)d_in[12];
    const float* caWq   = (const float*)d_in[13];
    const float* caWk   = (const float*)d_in[14];
    const float* caWv   = (const float*)d_in[15];
    const float* cafcW  = (const float*)d_in[16];
    const float* cafcB  = (const float*)d_in[17];
    const float* ln2g   = (const float*)d_in[18];
    const float* ln2b   = (const float*)d_in[19];
    const float* ffW1   = (const float*)d_in[20];
    const float* ffb1   = (const float*)d_in[21];
    const float* ffW2   = (const float*)d_in[22];
    const float* ffb2   = (const float*)d_in[23];
    const float* ln3g   = (const float*)d_in[24];
    const float* ln3b   = (const float*)d_in[25];
    const float* outW   = (const float*)d_in[26];
    const int*   ids    = (const int*)  d_in[27];
    float* out = (float*)d_out;

    float *x, *memb, *qb, *remb, *att, *tmp, *ff, *bdb;
    float *qkvb, *cakvb, *r4b, *wqkvb, *wcakvb, *wr4b;
    cudaGetSymbolAddress((void**)&x,      g_x);
    cudaGetSymbolAddress((void**)&memb,   g_mem);
    cudaGetSymbolAddress((void**)&qb,     g_q);
    cudaGetSymbolAddress((void**)&remb,   g_remb);
    cudaGetSymbolAddress((void**)&att,    g_att);
    cudaGetSymbolAddress((void**)&tmp,    g_tmp);
    cudaGetSymbolAddress((void**)&ff,     g_ff);
    cudaGetSymbolAddress((void**)&bdb,    g_bd);
    cudaGetSymbolAddress((void**)&qkvb,   g_qkv);
    cudaGetSymbolAddress((void**)&cakvb,  g_cakv);
    cudaGetSymbolAddress((void**)&r4b,    g_r4);
    cudaGetSymbolAddress((void**)&wqkvb,  g_wqkv);
    cudaGetSymbolAddress((void**)&wcakvb, g_wcakv);
    cudaGetSymbolAddress((void**)&wr4b,   g_wr4);

    static int smem_set = 0;
    if (!smem_set) {
        cudaFuncSetAttribute(flashmma, cudaFuncAttributeMaxDynamicSharedMemorySize,
                             FLASH_SMEM);
        cudaFuncSetAttribute((mm_tf32<true ,3>), cudaFuncAttributeMaxDynamicSharedMemorySize, MM_SMEM(3));
        cudaFuncSetAttribute((mm_tf32<false,3>), cudaFuncAttributeMaxDynamicSharedMemorySize, MM_SMEM(3));
        cudaFuncSetAttribute((mm_tf32<true ,4>), cudaFuncAttributeMaxDynamicSharedMemorySize, MM_SMEM(4));
        cudaFuncSetAttribute((mm_tf32<false,4>), cudaFuncAttributeMaxDynamicSharedMemorySize, MM_SMEM(4));
        smem_set = 1;
    }

    // weight fusion + embedding + positional encodings
    wqkv_concat <<<(LNUM*DM*3072 + 255)/256, 256>>>(saWq, saWk, saWv, wqkvb);
    wcakv_concat<<<(DM*8192 + 255)/256, 256>>>(caWk, caWv, wcakvb);
    wr4_concat  <<<(DM*4096 + 255)/256, 256>>>(saWr, wr4b);
    embed_kernel<<<(BN*QN*DM + 255)/256, 256>>>(ids, emb, x);
    remb_kernel <<<(KLEN*DM + 255)/256, 256>>>(remb);

    // layer-independent projections (fused across layers)
    run_gemm(remb, wr4b,   nullptr, r4b,   KLEN,  DM, 4096, false);  // grid 256
    run_gemm(enc,  wcakvb, nullptr, cakvb, BN*EN, DM, 8192, false);  // grid 1024

    dim3 flash_grid(QN/128, HN, BN);
    dim3 bd_grid(KLEN/64, QN/128, BN*HN);

    for (int l = 0; l < LNUM; l++) {
        // ---- self-attention (TransformerXL relative) ----
        concat_kernel<<<(BN*KLEN*DM + 255)/256, 256>>>(
            mems + (size_t)l*BN*MN*DM, x, memb);

        // fused QKV: memb[4096,1024] @ Wqkv[1024,3072]  (grid 768)
        run_gemm(memb, wqkvb + (size_t)l*DM*3072, nullptr, qkvb,
                 BN*KLEN, DM, 3072, false);

        const float* qself = qkvb + (size_t)MN*3072;          // q rows at j>=MN
        bd_mma<<<bd_grid, 256>>>(qself, 3072, (size_t)KLEN*3072,
                                 r4b + (size_t)l*1024, 4096, vpar, bdb);
        flashmma<<<flash_grid, 256, FLASH_SMEM>>>(
            qself, 3072, (size_t)KLEN*3072,
            qkvb + 1024, qkvb + 2048, 3072, (size_t)KLEN*3072,
            bdb, u, att, KLEN, 1);

        run_gemm(att, safcW + (size_t)l*DM*DM, safcB + (size_t)l*DM,
                 tmp, BN*QN, DM, DM, false);
        ln_kernel<<<BN*QN, 256>>>(x, tmp, ln1g + (size_t)l*DM, ln1b + (size_t)l*DM);

        // ---- cross-attention ----
        run_gemm(x, caWq + (size_t)l*DM*DM, nullptr, qb, BN*QN, DM, DM, false);

        flashmma<<<flash_grid, 256, FLASH_SMEM>>>(
            qb, DM, (size_t)QN*DM,
            cakvb + (size_t)l*2048, cakvb + (size_t)l*2048 + 1024,
            8192, (size_t)EN*8192,
            nullptr, nullptr, att, EN, 0);

        run_gemm(att, cafcW + (size_t)l*DM*DM, cafcB + (size_t)l*DM,
                 tmp, BN*QN, DM, DM, false);
        ln_kernel<<<BN*QN, 256>>>(x, tmp, ln2g + (size_t)l*DM, ln2b + (size_t)l*DM);

        // ---- feed-forward ----
        run_gemm(x,  ffW1 + (size_t)l*DM*FFN, ffb1 + (size_t)l*FFN,
                 ff, BN*QN, DM, FFN, true);
        run_gemm(ff, ffW2 + (size_t)l*FFN*DM, ffb2 + (size_t)l*DM,
                 tmp, BN*QN, FFN, DM, false);
        ln_kernel<<<BN*QN, 256>>>(x, tmp, ln3g + (size_t)l*DM, ln3b + (size_t)l*DM);
    }

    // ---- output projection ----
    run_gemm(x, outW, nullptr, out, BN*QN, DM, VN, false);
}

// round 8
// speedup vs baseline: 14.8140x; 1.0530x over previous
#include <cuda_runtime.h>
#include <math.h>

// Problem constants
#define LNUM 4
#define DM   1024
#define HN   16
#define DH   64
#define FFN  4096
#define VN   8192
#define BN   4
#define QN   512
#define MN   512
#define EN   512
#define KLEN 1024   // M + Q

// ---------------- scratch (device globals; no allocation) ----------------
__device__ float g_x    [BN*QN*DM];
__device__ float g_mem  [BN*KLEN*DM];
__device__ float g_q    [BN*QN*DM];
__device__ float g_remb [KLEN*DM];
__device__ float g_att  [BN*QN*DM];
__device__ float g_tmp  [BN*QN*DM];
__device__ float g_ff   [BN*QN*FFN];
__device__ float g_bd   [BN*HN*QN*KLEN];      // relative-position BD_raw
// fused projections
__device__ float g_qkv  [BN*KLEN*3072];       // memb @ [Wq|Wk|Wv]
__device__ float g_cakv [BN*EN*8192];         // enc @ [Wk|Wv] x 4 layers
__device__ float g_r4   [KLEN*4096];          // remb @ Wr x 4 layers
// fused / tf32-rounded weights (built per call)
__device__ float g_wqkv [LNUM*DM*3072];
__device__ float g_wcakv[DM*8192];
__device__ float g_wr4  [DM*4096];
__device__ float g_wsafc[LNUM*DM*DM];
__device__ float g_wcafc[LNUM*DM*DM];
__device__ float g_wcaq [LNUM*DM*DM];
__device__ float g_wff1 [LNUM*DM*FFN];
__device__ float g_wff2 [LNUM*FFN*DM];
__device__ float g_wout [DM*VN];
__device__ float g_enc  [BN*EN*DM];

// ---------------- tf32 helpers ----------------
__device__ __forceinline__ unsigned f2tf(float x) {
    unsigned u; asm("cvt.rna.tf32.f32 %0, %1;" : "=r"(u) : "f"(x)); return u;
}
__device__ __forceinline__ float tfv(float x) { return __uint_as_float(f2tf(x)); }

#define MMA_TF32(C, A, B0, B1)                                                \
    asm volatile(                                                             \
        "mma.sync.aligned.m16n8k8.row.col.f32.tf32.tf32.f32 "                 \
        "{%0,%1,%2,%3}, {%4,%5,%6,%7}, {%8,%9}, {%0,%1,%2,%3};"               \
        : "+f"((C)[0]), "+f"((C)[1]), "+f"((C)[2]), "+f"((C)[3])              \
        : "r"((A)[0]), "r"((A)[1]), "r"((A)[2]), "r"((A)[3]),                 \
          "r"(B0), "r"(B1))

__device__ __forceinline__ void cp16(float* dst, const float* src) {
    unsigned d = (unsigned)__cvta_generic_to_shared(dst);
    asm volatile("cp.async.cg.shared.global [%0], [%1], 16;\n" :: "r"(d), "l"(src));
}
#define CP_COMMIT()  asm volatile("cp.async.commit_group;\n" ::)

// ---------------- elementwise kernels ----------------
__global__ void round_copy4(const float* __restrict__ src,
                            float* __restrict__ dst, int n4) {
    int i = blockIdx.x * blockDim.x + threadIdx.x;
    if (i >= n4) return;
    float4 v = ((const float4*)src)[i];
    ((float4*)dst)[i] = make_float4(tfv(v.x), tfv(v.y), tfv(v.z), tfv(v.w));
}

__global__ void embed_kernel(const int* __restrict__ ids,
                             const float* __restrict__ emb,
                             float* __restrict__ x) {
    int idx = blockIdx.x * blockDim.x + threadIdx.x;
    if (idx >= BN*QN*DM) return;
    int row = idx / DM;
    int d   = idx - row * DM;
    int tok = ids[row];
    x[idx] = tfv(emb[tok * DM + d] * 32.0f);
}

__global__ void remb_kernel(float* __restrict__ remb) {
    int idx = blockIdx.x * blockDim.x + threadIdx.x;
    if (idx >= KLEN*DM) return;
    int p = idx / DM;
    int d = idx - p * DM;
    float pos = (float)(KLEN - 1 - p);
    int k = (d < DM/2) ? d : d - DM/2;
    float invf = powf(10000.0f, -(float)k / (float)(DM/2));
    float a = pos * invf;
    remb[idx] = tfv((d < DM/2) ? sinf(a) : cosf(a));
}

__global__ void concat_kernel(const float* __restrict__ mems_l,
                              const float* __restrict__ x,
                              float* __restrict__ mem) {
    int idx = blockIdx.x * blockDim.x + threadIdx.x;
    if (idx >= BN*KLEN*DM) return;
    int d   = idx % DM;
    int rem = idx / DM;
    int j   = rem % KLEN;
    int b   = rem / KLEN;
    float val;
    if (j < MN) val = tfv(mems_l[(b*MN + j)*DM + d]);
    else        val = x[(b*QN + (j - MN))*DM + d];   // x already rounded
    mem[idx] = val;
}

// ---------------- weight fusion kernels (tf32-rounded) ----------------
__global__ void wqkv_concat(const float* __restrict__ wq,
                            const float* __restrict__ wk,
                            const float* __restrict__ wv,
                            float* __restrict__ dst) {
    int idx = blockIdx.x * blockDim.x + threadIdx.x;     // L*D*3072
    if (idx >= LNUM*DM*3072) return;
    int c  = idx % 3072;
    int ld = idx / 3072;          // l*DM + d
    int sel = c >> 10, cc = c & 1023;
    const float* w = (sel == 0) ? wq : (sel == 1) ? wk : wv;
    dst[idx] = tfv(w[(size_t)ld*DM + cc]);
}

__global__ void wcakv_concat(const float* __restrict__ wk,
                             const float* __restrict__ wv,
                             float* __restrict__ dst) {
    int idx = blockIdx.x * blockDim.x + threadIdx.x;     // D*8192
    if (idx >= DM*8192) return;
    int c = idx % 8192;
    int d = idx / 8192;
    int l = c >> 11, cc = c & 2047;
    float val;
    if (cc < 1024) val = wk[((size_t)l*DM + d)*DM + cc];
    else           val = wv[((size_t)l*DM + d)*DM + (cc - 1024)];
    dst[idx] = tfv(val);
}

__global__ void wr4_concat(const float* __restrict__ wr,
                           float* __restrict__ dst) {
    int idx = blockIdx.x * blockDim.x + threadIdx.x;     // D*4096
    if (idx >= DM*4096) return;
    int c = idx % 4096;
    int d = idx / 4096;
    int l = c >> 10;
    dst[idx] = tfv(wr[((size_t)l*DM + d)*DM + (c & 1023)]);
}

// ---------------- tf32 tensor-core GEMM, 4-stage cp.async, 2 CTAs/SM -------
// C[N,K] = A[N,D] @ B[D,K] (+bias, optional GELU). N,K mult of 128, D mult 16.
// ALL inputs must be pre-rounded to tf32 (RNA) — no cvt in the mainloop.
#define STG       4
#define AS_STRIDE 20
#define BS_STRIDE 136
#define AS_SZ     (128*AS_STRIDE)    // floats per stage
#define BS_SZ     (16*BS_STRIDE)
#define MM_SMEM   (STG*(AS_SZ+BS_SZ)*4)

template<bool GELU>
__global__ __launch_bounds__(256, 2)
void mm_tf32(const float* __restrict__ A, const float* __restrict__ B,
             const float* __restrict__ bias, float* __restrict__ C,
             int N, int D, int K) {
    extern __shared__ float sm[];
    float* As = sm;                   // [STG][128][AS_STRIDE]
    float* Bs = sm + STG*AS_SZ;       // [STG][16][BS_STRIDE]

    const int tid  = threadIdx.x;
    const int row0 = blockIdx.y * 128, col0 = blockIdx.x * 128;
    const int lane = tid & 31, wid = tid >> 5;
    const int grp  = lane >> 2, t4 = lane & 3;
    const int wm   = (wid & 3) * 32, wn = (wid >> 2) * 64;

    const int ar = tid >> 2, ak = (tid & 3) * 4;   // A loader: rows ar, ar+64
    const int bk = tid >> 5, bc = (tid & 31) * 4;  // B loader: k rows bk, bk+8

    const float* Ag0 = A + (size_t)(row0 + ar)      * D + ak;
    const float* Ag1 = A + (size_t)(row0 + ar + 64) * D + ak;
    const float* Bg0 = B + (size_t)bk       * K + col0 + bc;
    const float* Bg1 = B + (size_t)(bk + 8) * K + col0 + bc;

    float* sA0 = As + ar*AS_STRIDE + ak;
    float* sA1 = As + (ar+64)*AS_STRIDE + ak;
    float* sB0 = Bs + bk*BS_STRIDE + bc;
    float* sB1 = Bs + (bk+8)*BS_STRIDE + bc;

    const int KT = D >> 4;

    float c[2][8][4];
    #pragma unroll
    for (int i = 0; i < 2; i++)
        #pragma unroll
        for (int j = 0; j < 8; j++)
            #pragma unroll
            for (int t = 0; t < 4; t++) c[i][j][t] = 0.0f;

    // prologue: stages 0..2 in flight
    #pragma unroll
    for (int s = 0; s < STG-1; s++) {
        const int kb = s * 16;
        cp16(sA0 + s*AS_SZ, Ag0 + kb);
        cp16(sA1 + s*AS_SZ, Ag1 + kb);
        cp16(sB0 + s*BS_SZ, Bg0 + (size_t)kb*K);
        cp16(sB1 + s*BS_SZ, Bg1 + (size_t)kb*K);
        CP_COMMIT();
    }

    for (int kt = 0; kt < KT; kt++) {
        asm volatile("cp.async.wait_group 2;\n" ::);
        __syncthreads();
        const int st = kt & (STG-1);
        const float* Ast = As + st*AS_SZ;
        const float* Bst = Bs + st*BS_SZ;

        #pragma unroll
        for (int half = 0; half < 2; half++) {
            const int kk = half * 8;
            unsigned af[2][4], bfr[8][2];
            #pragma unroll
            for (int mt = 0; mt < 2; mt++) {
                const int m = wm + mt*16 + grp;
                af[mt][0] = __float_as_uint(Ast[(m  )*AS_STRIDE + kk + t4    ]);
                af[mt][1] = __float_as_uint(Ast[(m+8)*AS_STRIDE + kk + t4    ]);
                af[mt][2] = __float_as_uint(Ast[(m  )*AS_STRIDE + kk + t4 + 4]);
                af[mt][3] = __float_as_uint(Ast[(m+8)*AS_STRIDE + kk + t4 + 4]);
            }
            #pragma unroll
            for (int nt = 0; nt < 8; nt++) {
                const int n = wn + nt*8 + grp;
                bfr[nt][0] = __float_as_uint(Bst[(kk + t4    )*BS_STRIDE + n]);
                bfr[nt][1] = __float_as_uint(Bst[(kk + t4 + 4)*BS_STRIDE + n]);
            }
            #pragma unroll
            for (int mt = 0; mt < 2; mt++)
                #pragma unroll
                for (int nt = 0; nt < 8; nt++)
                    MMA_TF32(c[mt][nt], af[mt], bfr[nt][0], bfr[nt][1]);

            if (half == 0) {
                const int kn = kt + STG - 1;
                if (kn < KT) {
                    const int sn = kn & (STG-1);
                    const int kb = kn * 16;
                    cp16(sA0 + sn*AS_SZ, Ag0 + kb);
                    cp16(sA1 + sn*AS_SZ, Ag1 + kb);
                    cp16(sB0 + sn*BS_SZ, Bg0 + (size_t)kb*K);
                    cp16(sB1 + sn*BS_SZ, Bg1 + (size_t)kb*K);
                }
                CP_COMMIT();
            }
        }
    }

    #pragma unroll
    for (int mt = 0; mt < 2; mt++)
        #pragma unroll
        for (int nt = 0; nt < 8; nt++) {
            int r  = row0 + wm + mt*16 + grp;
            int cc = col0 + wn + nt*8 + t4*2;
            #pragma unroll
            for (int half = 0; half < 2; half++) {
                int rr = r + half*8;
                #pragma unroll
                for (int e = 0; e < 2; e++) {
                    float val = c[mt][nt][half*2 + e];
                    int col = cc + e;
                    if (bias) val += bias[col];
                    if (GELU) {
                        val = 0.5f*val*(1.0f + erff(val*0.70710678118654752f));
                        val = tfv(val);   // output feeds another GEMM
                    }
                    C[(size_t)rr*K + col] = val;
                }
            }
        }
}

// ---------------- BD_raw via tensor cores ----------------
// bdout[b,h,i,t] = sum_d (q[i,h,d] + vvec[h,d]) * r[t,h,d]
#define RS_STRIDE 68
__global__ __launch_bounds__(256)
void bd_mma(const float* __restrict__ q, int qrs, size_t qbs,
            const float* __restrict__ r, int rrs,
            const float* __restrict__ vvec, float* __restrict__ bdout) {
    __shared__ float Rs[64*RS_STRIDE];
    const int t0 = blockIdx.x * 64;
    const int i0 = blockIdx.y * 128;
    const int h = blockIdx.z & (HN-1), b = blockIdx.z >> 4;
    const int tid = threadIdx.x;
    const int lane = tid & 31, wid = tid >> 5;
    const int grp = lane >> 2, t4 = lane & 3;
    const int i_r0 = i0 + wid*16 + grp, i_r1 = i_r0 + 8;

    unsigned qf[8][4];
    {
        const float* qp0 = q + (size_t)b*qbs + (size_t)i_r0*qrs + h*DH;
        const float* qp1 = q + (size_t)b*qbs + (size_t)i_r1*qrs + h*DH;
        const float* up  = vvec + h*DH;
        #pragma unroll
        for (int ks = 0; ks < 8; ks++) {
            int k0 = ks*8 + t4;
            float u0 = up[k0], u1 = up[k0+4];
            qf[ks][0] = f2tf(qp0[k0]   + u0);
            qf[ks][1] = f2tf(qp1[k0]   + u0);
            qf[ks][2] = f2tf(qp0[k0+4] + u1);
            qf[ks][3] = f2tf(qp1[k0+4] + u1);
        }
    }
    #pragma unroll
    for (int t = 0; t < 4; t++) {
        int idx = tid + 256*t;
        int row = idx >> 4, c4 = (idx & 15) * 4;
        float4 rr = *(const float4*)&r[(size_t)(t0 + row)*rrs + h*DH + c4];
        float* rd = Rs + row*RS_STRIDE + c4;
        rd[0]=tfv(rr.x); rd[1]=tfv(rr.y); rd[2]=tfv(rr.z); rd[3]=tfv(rr.w);
    }
    __syncthreads();

    float s[8][4];
    #pragma unroll
    for (int nt = 0; nt < 8; nt++)
        #pragma unroll
        for (int e = 0; e < 4; e++) s[nt][e] = 0.0f;

    #pragma unroll
    for (int ks = 0; ks < 8; ks++)
        #pragma unroll
        for (int nt = 0; nt < 8; nt++) {
            unsigned b0 = __float_as_uint(Rs[(nt*8+grp)*RS_STRIDE + ks*8 + t4]);
            unsigned b1 = __float_as_uint(Rs[(nt*8+grp)*RS_STRIDE + ks*8 + t4 + 4]);
            MMA_TF32(s[nt], qf[ks], b0, b1);
        }

    float* o0 = bdout + (((size_t)(b*HN + h))*QN + i_r0)*KLEN + t0;
    float* o1 = bdout + (((size_t)(b*HN + h))*QN + i_r1)*KLEN + t0;
    #pragma unroll
    for (int nt = 0; nt < 8; nt++) {
        int cc = nt*8 + 2*t4;
        *(float2*)&o0[cc] = make_float2(s[nt][0], s[nt][1]);
        *(float2*)&o1[cc] = make_float2(s[nt][2], s[nt][3]);
    }
}

// ---------------- MMA flash attention (strided q/k/v) ----------------
#define KS_STRIDE 68
#define VS_STRIDE 72
#define PS_STRIDE 68
#define FLASH_SMEM ((64*KS_STRIDE + 64*VS_STRIDE + 128*PS_STRIDE) * 4)

__global__ __launch_bounds__(256)
void flashmma(const float* __restrict__ q, int qrs, size_t qbs,
              const float* __restrict__ k, const float* __restrict__ v,
              int kvrs, size_t kvbs,
              const float* __restrict__ bd, const float* __restrict__ uvec,
              float* __restrict__ out, int klen, int useMask) {
    extern __shared__ float sm[];
    float* Ks = sm;
    float* Vs = Ks + 64*KS_STRIDE;
    float* Ps = Vs + 64*VS_STRIDE;

    const int i0 = blockIdx.x * 128;
    const int h = blockIdx.y, b = blockIdx.z;
    const int tid = threadIdx.x;
    const int lane = tid & 31, wid = tid >> 5;
    const int grp = lane >> 2, t4 = lane & 3;
    const int r0 = wid*16 + grp, r1 = r0 + 8;
    const int i_r0 = i0 + r0, i_r1 = i0 + r1;

    unsigned qf[8][4];
    {
        const float* qp0 = q + (size_t)b*qbs + (size_t)i_r0*qrs + h*DH;
        const float* qp1 = q + (size_t)b*qbs + (size_t)i_r1*qrs + h*DH;
        #pragma unroll
        for (int ks = 0; ks < 8; ks++) {
            int k0 = ks*8 + t4;
            float u0 = uvec ? uvec[h*DH + k0]     : 0.0f;
            float u1 = uvec ? uvec[h*DH + k0 + 4] : 0.0f;
            qf[ks][0] = f2tf(qp0[k0]   + u0);
            qf[ks][1] = f2tf(qp1[k0]   + u0);
            qf[ks][2] = f2tf(qp0[k0+4] + u1);
            qf[ks][3] = f2tf(qp1[k0+4] + u1);
        }
    }

    float m0 = -INFINITY, m1 = -INFINITY, l0 = 0.0f, l1 = 0.0f;
    float o[8][4];
    #pragma unroll
    for (int nt = 0; nt < 8; nt++)
        #pragma unroll
        for (int e = 0; e < 4; e++) o[nt][e] = 0.0f;

    const float* bdr0 = bd ? bd + (((size_t)(b*HN + h))*QN + i_r0)*KLEN : (const float*)0;
    const float* bdr1 = bd ? bd + (((size_t)(b*HN + h))*QN + i_r1)*KLEN : (const float*)0;

    int lastj = klen - 1;
    if (useMask) { int lm = i0 + 127 + MN; if (lm < lastj) lastj = lm; }

    for (int j0 = 0; j0 <= lastj; j0 += 64) {
        __syncthreads();
        #pragma unroll
        for (int t = 0; t < 4; t++) {
            int idx = tid + 256*t;
            int row = idx >> 4, c4 = (idx & 15) * 4;
            size_t gb = (size_t)b*kvbs + (size_t)(j0 + row)*kvrs + h*DH + c4;
            float4 kk4 = *(const float4*)&k[gb];
            float4 vv4 = *(const float4*)&v[gb];
            float* kd = Ks + row*KS_STRIDE + c4;
            kd[0]=tfv(kk4.x); kd[1]=tfv(kk4.y); kd[2]=tfv(kk4.z); kd[3]=tfv(kk4.w);
            float* vd = Vs + row*VS_STRIDE + c4;
            vd[0]=tfv(vv4.x); vd[1]=tfv(vv4.y); vd[2]=tfv(vv4.z); vd[3]=tfv(vv4.w);
        }
        __syncthreads();

        float bdv[8][4];
        if (bd) {
            #pragma unroll
            for (int nt = 0; nt < 8; nt++) {
                int jA = j0 + nt*8 + 2*t4;
                int jr0 = jA - i_r0 + (QN-1);
                int jr1 = jA - i_r1 + (QN-1);
                jr0 = max(0, min(KLEN-2, jr0));
                jr1 = max(0, min(KLEN-2, jr1));
                bdv[nt][0] = bdr0[jr0];   bdv[nt][1] = bdr0[jr0+1];
                bdv[nt][2] = bdr1[jr1];   bdv[nt][3] = bdr1[jr1+1];
            }
        }

        float s[8][4];
        #pragma unroll
        for (int nt = 0; nt < 8; nt++)
            #pragma unroll
            for (int e = 0; e < 4; e++) s[nt][e] = 0.0f;
        #pragma unroll
        for (int ks = 0; ks < 8; ks++)
            #pragma unroll
            for (int nt = 0; nt < 8; nt++) {
                unsigned b0 = __float_as_uint(Ks[(nt*8+grp)*KS_STRIDE + ks*8 + t4]);
                unsigned b1 = __float_as_uint(Ks[(nt*8+grp)*KS_STRIDE + ks*8 + t4 + 4]);
                MMA_TF32(s[nt], qf[ks], b0, b1);
            }

        float mc0 = -INFINITY, mc1 = -INFINITY;
        #pragma unroll
        for (int nt = 0; nt < 8; nt++) {
            int jA = j0 + nt*8 + 2*t4;
            int jB = jA + 1;
            float v0 = s[nt][0], v1 = s[nt][1], v2 = s[nt][2], v3 = s[nt][3];
            if (bd) { v0 += bdv[nt][0]; v1 += bdv[nt][1]; v2 += bdv[nt][2]; v3 += bdv[nt][3]; }
            v0 *= 0.125f; v1 *= 0.125f; v2 *= 0.125f; v3 *= 0.125f;
            if (useMask) {
                if (jA > i_r0 + MN) v0 = -INFINITY;
                if (jB > i_r0 + MN) v1 = -INFINITY;
                if (jA > i_r1 + MN) v2 = -INFINITY;
                if (jB > i_r1 + MN) v3 = -INFINITY;
            }
            s[nt][0]=v0; s[nt][1]=v1; s[nt][2]=v2; s[nt][3]=v3;
            mc0 = fmaxf(mc0, fmaxf(v0, v1));
            mc1 = fmaxf(mc1, fmaxf(v2, v3));
        }
        mc0 = fmaxf(mc0, __shfl_xor_sync(0xffffffffu, mc0, 1));
        mc0 = fmaxf(mc0, __shfl_xor_sync(0xffffffffu, mc0, 2));
        mc1 = fmaxf(mc1, __shfl_xor_sync(0xffffffffu, mc1, 1));
        mc1 = fmaxf(mc1, __shfl_xor_sync(0xffffffffu, mc1, 2));

        float nm0 = fmaxf(m0, mc0), nm1 = fmaxf(m1, mc1);
        float corr0 = __expf(m0 - nm0), corr1 = __expf(m1 - nm1);
        float ps0 = 0.0f, ps1 = 0.0f;
        #pragma unroll
        for (int nt = 0; nt < 8; nt++) {
            float p0 = __expf(s[nt][0] - nm0);
            float p1 = __expf(s[nt][1] - nm0);
            float p2 = __expf(s[nt][2] - nm1);
            float p3 = __expf(s[nt][3] - nm1);
            ps0 += p0 + p1; ps1 += p2 + p3;
            int cc = nt*8 + 2*t4;
            Ps[r0*PS_STRIDE + cc]     = __uint_as_float(f2tf(p0));
            Ps[r0*PS_STRIDE + cc + 1] = __uint_as_float(f2tf(p1));
            Ps[r1*PS_STRIDE + cc]     = __uint_as_float(f2tf(p2));
            Ps[r1*PS_STRIDE + cc + 1] = __uint_as_float(f2tf(p3));
        }
        ps0 += __shfl_xor_sync(0xffffffffu, ps0, 1);
        ps0 += __shfl_xor_sync(0xffffffffu, ps0, 2);
        ps1 += __shfl_xor_sync(0xffffffffu, ps1, 1);
        ps1 += __shfl_xor_sync(0xffffffffu, ps1, 2);
        l0 = l0 * corr0 + ps0;  m0 = nm0;
        l1 = l1 * corr1 + ps1;  m1 = nm1;
        #pragma unroll
        for (int nt = 0; nt < 8; nt++) {
            o[nt][0] *= corr0; o[nt][1] *= corr0;
            o[nt][2] *= corr1; o[nt][3] *= corr1;
        }
        __syncwarp();

        #pragma unroll
        for (int ks = 0; ks < 8; ks++) {
            unsigned a[4];
            a[0] = __float_as_uint(Ps[r0*PS_STRIDE + ks*8 + t4]);
            a[1] = __float_as_uint(Ps[r1*PS_STRIDE + ks*8 + t4]);
            a[2] = __float_as_uint(Ps[r0*PS_STRIDE + ks*8 + t4 + 4]);
            a[3] = __float_as_uint(Ps[r1*PS_STRIDE + ks*8 + t4 + 4]);
            #pragma unroll
            for (int nt = 0; nt < 8; nt++) {
                unsigned b0 = __float_as_uint(Vs[(ks*8+t4)*VS_STRIDE + nt*8 + grp]);
                unsigned b1 = __float_as_uint(Vs[(ks*8+t4+4)*VS_STRIDE + nt*8 + grp]);
                MMA_TF32(o[nt], a, b0, b1);
            }
        }
    }

    const float inv0 = 1.0f / l0, inv1 = 1.0f / l1;
    float* op0 = out + ((size_t)(b*QN + i_r0))*DM + h*DH;
    float* op1 = out + ((size_t)(b*QN + i_r1))*DM + h*DH;
    #pragma unroll
    for (int nt = 0; nt < 8; nt++) {
        int cc = nt*8 + 2*t4;
        // rounded: attention output feeds the projection GEMM
        *(float2*)&op0[cc] = make_float2(tfv(o[nt][0]*inv0), tfv(o[nt][1]*inv0));
        *(float2*)&op1[cc] = make_float2(tfv(o[nt][2]*inv1), tfv(o[nt][3]*inv1));
    }
}

// ---------------- residual add + LayerNorm (tf32-rounded output) ----------
__global__ __launch_bounds__(256)
void ln_kernel(float* __restrict__ x, const float* __restrict__ y,
               const float* __restrict__ gamma, const float* __restrict__ beta) {
    const int row = blockIdx.x;
    const int tid = threadIdx.x;
    __shared__ float red[256];

    float s[4];
    float local = 0.0f;
    #pragma unroll
    for (int kk = 0; kk < 4; kk++) {
        int c = tid + kk*256;
        float val = x[(size_t)row*DM + c] + y[(size_t)row*DM + c];
        s[kk] = val;
        local += val;
    }
    red[tid] = local;
    __syncthreads();
    for (int t = 128; t > 0; t >>= 1) {
        if (tid < t) red[tid] += red[tid+t];
        __syncthreads();
    }
    const float mu = red[0] * (1.0f / DM);
    __syncthreads();

    local = 0.0f;
    #pragma unroll
    for (int kk = 0; kk < 4; kk++) {
        float dlt = s[kk] - mu;
        local += dlt * dlt;
    }
    red[tid] = local;
    __syncthreads();
    for (int t = 128; t > 0; t >>= 1) {
        if (tid < t) red[tid] += red[tid+t];
        __syncthreads();
    }
    const float rstd = rsqrtf(red[0] * (1.0f / DM) + 1e-5f);
    __syncthreads();

    #pragma unroll
    for (int kk = 0; kk < 4; kk++) {
        int c = tid + kk*256;
        x[(size_t)row*DM + c] = tfv((s[kk] - mu) * rstd * gamma[c] + beta[c]);
    }
}

// ---------------- host orchestration ----------------
static inline void run_gemm(const float* A, const float* B, const float* bias,
                            float* C, int N, int D, int K, bool gelu) {
    dim3 grid(K/128, N/128);
    if (gelu) mm_tf32<true ><<<grid, 256, MM_SMEM>>>(A, B, bias, C, N, D, K);
    else      mm_tf32<false><<<grid, 256, MM_SMEM>>>(A, B, bias, C, N, D, K);
}

static inline void round_weights(const float* src, float* dst, size_t n) {
    round_copy4<<<(unsigned)((n/4 + 255)/256), 256>>>(src, dst, (int)(n/4));
}

extern "C" void kernel_launch(void* const* d_in, const int* in_sizes, int n_in,
                              void* d_out, int out_size) {
    const float* enc    = (const float*)d_in[0];
    const float* mems   = (const float*)d_in[1];
    const float* emb    = (const float*)d_in[2];
    const float* u      = (const float*)d_in[3];
    const float* vpar   = (const float*)d_in[4];
    const float* saWq   = (const float*)d_in[5];
    const float* saWk   = (const float*)d_in[6];
    const float* saWv   = (const float*)d_in[7];
    const float* saWr   = (const float*)d_in[8];
    const float* safcW  = (const float*)d_in[9];
    const float* safcB  = (const float*)d_in[10];
    const float* ln1g   = (const float*)d_in[11];
    const float* ln1b   = (const float*)d_in[12];
    const float* caWq   = (const float*)d_in[13];
    const float* caWk   = (const float*)d_in[14];
    const float* caWv   = (const float*)d_in[15];
    const float* cafcW  = (const float*)d_in[16];
    const float* cafcB  = (const float*)d_in[17];
    const float* ln2g   = (const float*)d_in[18];
    const float* ln2b   = (const float*)d_in[19];
    const float* ffW1   = (const float*)d_in[20];
    const float* ffb1   = (const float*)d_in[21];
    const float* ffW2   = (const float*)d_in[22];
    const float* ffb2   = (const float*)d_in[23];
    const float* ln3g   = (const float*)d_in[24];
    const float* ln3b   = (const float*)d_in[25];
    const float* outW   = (const float*)d_in[26];
    const int*   ids    = (const int*)  d_in[27];
    float* out = (float*)d_out;

    float *x, *memb, *qb, *remb, *att, *tmp, *ff, *bdb;
    float *qkvb, *cakvb, *r4b, *wqkvb, *wcakvb, *wr4b;
    float *wsafc, *wcafc, *wcaq, *wff1, *wff2, *wout, *encr;
    cudaGetSymbolAddress((void**)&x,      g_x);
    cudaGetSymbolAddress((void**)&memb,   g_mem);
    cudaGetSymbolAddress((void**)&qb,     g_q);
    cudaGetSymbolAddress((void**)&remb,   g_remb);
    cudaGetSymbolAddress((void**)&att,    g_att);
    cudaGetSymbolAddress((void**)&tmp,    g_tmp);
    cudaGetSymbolAddress((void**)&ff,     g_ff);
    cudaGetSymbolAddress((void**)&bdb,    g_bd);
    cudaGetSymbolAddress((void**)&qkvb,   g_qkv);
    cudaGetSymbolAddress((void**)&cakvb,  g_cakv);
    cudaGetSymbolAddress((void**)&r4b,    g_r4);
    cudaGetSymbolAddress((void**)&wqkvb,  g_wqkv);
    cudaGetSymbolAddress((void**)&wcakvb, g_wcakv);
    cudaGetSymbolAddress((void**)&wr4b,   g_wr4);
    cudaGetSymbolAddress((void**)&wsafc,  g_wsafc);
    cudaGetSymbolAddress((void**)&wcafc,  g_wcafc);
    cudaGetSymbolAddress((void**)&wcaq,   g_wcaq);
    cudaGetSymbolAddress((void**)&wff1,   g_wff1);
    cudaGetSymbolAddress((void**)&wff2,   g_wff2);
    cudaGetSymbolAddress((void**)&wout,   g_wout);
    cudaGetSymbolAddress((void**)&encr,   g_enc);

    static int smem_set = 0;
    if (!smem_set) {
        cudaFuncSetAttribute(flashmma, cudaFuncAttributeMaxDynamicSharedMemorySize,
                             FLASH_SMEM);
        cudaFuncSetAttribute((mm_tf32<true >), cudaFuncAttributeMaxDynamicSharedMemorySize, MM_SMEM);
        cudaFuncSetAttribute((mm_tf32<false>), cudaFuncAttributeMaxDynamicSharedMemorySize, MM_SMEM);
        smem_set = 1;
    }

    // tf32-rounded weight/input copies + fusions
    wqkv_concat <<<(LNUM*DM*3072 + 255)/256, 256>>>(saWq, saWk, saWv, wqkvb);
    wcakv_concat<<<(DM*8192 + 255)/256, 256>>>(caWk, caWv, wcakvb);
    wr4_concat  <<<(DM*4096 + 255)/256, 256>>>(saWr, wr4b);
    round_weights(safcW, wsafc, (size_t)LNUM*DM*DM);
    round_weights(cafcW, wcafc, (size_t)LNUM*DM*DM);
    round_weights(caWq,  wcaq,  (size_t)LNUM*DM*DM);
    round_weights(ffW1,  wff1,  (size_t)LNUM*DM*FFN);
    round_weights(ffW2,  wff2,  (size_t)LNUM*FFN*DM);
    round_weights(outW,  wout,  (size_t)DM*VN);
    round_weights(enc,   encr,  (size_t)BN*EN*DM);
    embed_kernel<<<(BN*QN*DM + 255)/256, 256>>>(ids, emb, x);
    remb_kernel <<<(KLEN*DM + 255)/256, 256>>>(remb);

    // layer-independent projections (fused across layers)
    run_gemm(remb, wr4b,   nullptr, r4b,   KLEN,  DM, 4096, false);
    run_gemm(encr, wcakvb, nullptr, cakvb, BN*EN, DM, 8192, false);

    dim3 flash_grid(QN/128, HN, BN);
    dim3 bd_grid(KLEN/64, QN/128, BN*HN);

    for (int l = 0; l < LNUM; l++) {
        // ---- self-attention (TransformerXL relative) ----
        concat_kernel<<<(BN*KLEN*DM + 255)/256, 256>>>(
            mems + (size_t)l*BN*MN*DM, x, memb);

        run_gemm(memb, wqkvb + (size_t)l*DM*3072, nullptr, qkvb,
                 BN*KLEN, DM, 3072, false);

        const float* qself = qkvb + (size_t)MN*3072;
        bd_mma<<<bd_grid, 256>>>(qself, 3072, (size_t)KLEN*3072,
                                 r4b + (size_t)l*1024, 4096, vpar, bdb);
        flashmma<<<flash_grid, 256, FLASH_SMEM>>>(
            qself, 3072, (size_t)KLEN*3072,
            qkvb + 1024, qkvb + 2048, 3072, (size_t)KLEN*3072,
            bdb, u, att, KLEN, 1);

        run_gemm(att, wsafc + (size_t)l*DM*DM, safcB + (size_t)l*DM,
                 tmp, BN*QN, DM, DM, false);
        ln_kernel<<<BN*QN, 256>>>(x, tmp, ln1g + (size_t)l*DM, ln1b + (size_t)l*DM);

        // ---- cross-attention ----
        run_gemm(x, wcaq + (size_t)l*DM*DM, nullptr, qb, BN*QN, DM, DM, false);

        flashmma<<<flash_grid, 256, FLASH_SMEM>>>(
            qb, DM, (size_t)QN*DM,
            cakvb + (size_t)l*2048, cakvb + (size_t)l*2048 + 1024,
            8192, (size_t)EN*8192,
            nullptr, nullptr, att, EN, 0);

        run_gemm(att, wcafc + (size_t)l*DM*DM, cafcB + (size_t)l*DM,
                 tmp, BN*QN, DM, DM, false);
        ln_kernel<<<BN*QN, 256>>>(x, tmp, ln2g + (size_t)l*DM, ln2b + (size_t)l*DM);

        // ---- feed-forward ----
        run_gemm(x,  wff1 + (size_t)l*DM*FFN, ffb1 + (size_t)l*FFN,
                 ff, BN*QN, DM, FFN, true);
        run_gemm(ff, wff2 + (size_t)l*FFN*DM, ffb2 + (size_t)l*DM,
                 tmp, BN*QN, FFN, DM, false);
        ln_kernel<<<BN*QN, 256>>>(x, tmp, ln3g + (size_t)l*DM, ln3b + (size_t)l*DM);
    }

    // ---- output projection ----
    run_gemm(x, wout, nullptr, out, BN*QN, DM, VN, false);
}

// round 10
// speedup vs baseline: 20.5566x; 1.3877x over previous
#include <cuda_runtime.h>
#include <cuda_fp16.h>
#include <math.h>
#include <stdint.h>

// Problem constants
#define LNUM 4
#define DM   1024
#define HN   16
#define DH   64
#define FFN  4096
#define VN   8192
#define BN   4
#define QN   512
#define MN   512
#define EN   512
#define KLEN 1024   // M + Q

// ---------------- scratch (device globals; no allocation) ----------------
__device__ float  g_x   [BN*QN*DM];         // residual stream (full fp32)
__device__ float  g_tmp [BN*QN*DM];
__device__ float  g_bd  [BN*HN*QN*KLEN];
// half activation buffers (GEMM/flash operands)
__device__ __half g_hxh  [BN*QN*DM];
__device__ __half g_hmem [BN*KLEN*DM];
__device__ __half g_hqkv [BN*KLEN*3072];
__device__ __half g_hcakv[BN*EN*8192];
__device__ __half g_hr4  [KLEN*4096];
__device__ __half g_hatt [BN*QN*DM];
__device__ __half g_hq   [BN*QN*DM];
__device__ __half g_hff  [BN*QN*FFN];
__device__ __half g_hremb[KLEN*DM];
__device__ __half g_henc [BN*EN*DM];
// transposed half weights (B^T, [n][k] row-major), built per call
__device__ __half g_wqkv [LNUM*3072*DM];
__device__ __half g_wcakv[8192*DM];
__device__ __half g_wr4  [4096*DM];
__device__ __half g_wsafc[LNUM*DM*DM];
__device__ __half g_wcafc[LNUM*DM*DM];
__device__ __half g_wcaq [LNUM*DM*DM];
__device__ __half g_wff1 [LNUM*FFN*DM];
__device__ __half g_wff2 [LNUM*DM*FFN];
__device__ __half g_wout [VN*DM];

// ---------------- helpers ----------------
__device__ __forceinline__ unsigned f2tf(float x) {
    unsigned u; asm("cvt.rna.tf32.f32 %0, %1;" : "=r"(u) : "f"(x)); return u;
}
__device__ __forceinline__ float tfv(float x) { return __uint_as_float(f2tf(x)); }

#define MMA_TF32(C, A, B0, B1)                                                \
    asm volatile(                                                             \
        "mma.sync.aligned.m16n8k8.row.col.f32.tf32.tf32.f32 "                 \
        "{%0,%1,%2,%3}, {%4,%5,%6,%7}, {%8,%9}, {%0,%1,%2,%3};"               \
        : "+f"((C)[0]), "+f"((C)[1]), "+f"((C)[2]), "+f"((C)[3])              \
        : "r"((A)[0]), "r"((A)[1]), "r"((A)[2]), "r"((A)[3]),                 \
          "r"(B0), "r"(B1))

#define MMA_F16(C, A0, A1, A2, A3, B0, B1)                                    \
    asm volatile(                                                             \
        "mma.sync.aligned.m16n8k16.row.col.f32.f16.f16.f32 "                  \
        "{%0,%1,%2,%3}, {%4,%5,%6,%7}, {%8,%9}, {%0,%1,%2,%3};"               \
        : "+f"((C)[0]), "+f"((C)[1]), "+f"((C)[2]), "+f"((C)[3])              \
        : "r"(A0), "r"(A1), "r"(A2), "r"(A3), "r"(B0), "r"(B1))

__device__ __forceinline__ void cp16(uint32_t dst, const void* src) {
    asm volatile("cp.async.cg.shared.global [%0], [%1], 16;\n" :: "r"(dst), "l"(src));
}
#define CP_COMMIT()  asm volatile("cp.async.commit_group;\n" ::)

__device__ __forceinline__ uint32_t smem_u32(const void* p) {
    uint32_t a;
    asm("{ .reg .u64 t; cvta.to.shared.u64 t, %1; cvt.u32.u64 %0, t; }"
        : "=r"(a) : "l"(p));
    return a;
}

// ---------------- elementwise kernels ----------------
__global__ void half_copy(const float* __restrict__ src,
                          __half* __restrict__ dst, int n4) {
    int i = blockIdx.x * blockDim.x + threadIdx.x;
    if (i >= n4) return;
    float4 v = ((const float4*)src)[i];
    ((__half2*)dst)[2*i]   = __floats2half2_rn(v.x, v.y);
    ((__half2*)dst)[2*i+1] = __floats2half2_rn(v.z, v.w);
}

// transpose + half: src [R, C] fp32 row-major -> dst [C, R] half row-major
__global__ void trans_half(const float* __restrict__ src, __half* __restrict__ dst,
                           int R, int C, size_t sbs, size_t dbs) {
    __shared__ float t[32][33];
    const float* s = src + (size_t)blockIdx.z * sbs;
    __half*      d = dst + (size_t)blockIdx.z * dbs;
    int c0 = blockIdx.x * 32, r0 = blockIdx.y * 32;
    int tx = threadIdx.x, ty = threadIdx.y;
    #pragma unroll
    for (int i = 0; i < 4; i++)
        t[ty + 8*i][tx] = s[(size_t)(r0 + ty + 8*i) * C + c0 + tx];
    __syncthreads();
    #pragma unroll
    for (int i = 0; i < 4; i++)
        d[(size_t)(c0 + ty + 8*i) * R + r0 + tx] = __float2half_rn(t[tx][ty + 8*i]);
}

__global__ void embed_kernel(const int* __restrict__ ids,
                             const float* __restrict__ emb,
                             float* __restrict__ x) {
    int idx = blockIdx.x * blockDim.x + threadIdx.x;
    if (idx >= BN*QN*DM) return;
    int row = idx / DM;
    int d   = idx - row * DM;
    int tok = ids[row];
    x[idx] = emb[tok * DM + d] * 32.0f;
}

__global__ void remb_kernel(__half* __restrict__ remb) {
    int idx = blockIdx.x * blockDim.x + threadIdx.x;
    if (idx >= KLEN*DM) return;
    int p = idx / DM;
    int d = idx - p * DM;
    float pos = (float)(KLEN - 1 - p);
    int k = (d < DM/2) ? d : d - DM/2;
    float invf = powf(10000.0f, -(float)k / (float)(DM/2));
    float a = pos * invf;
    remb[idx] = __float2half_rn((d < DM/2) ? sinf(a) : cosf(a));
}

__global__ void concat_kernel(const float* __restrict__ mems_l,
                              const float* __restrict__ x,
                              __half* __restrict__ mem) {
    int idx = blockIdx.x * blockDim.x + threadIdx.x;
    if (idx >= BN*KLEN*DM) return;
    int d   = idx % DM;
    int rem = idx / DM;
    int j   = rem % KLEN;
    int b   = rem / KLEN;
    float val;
    if (j < MN) val = mems_l[(b*MN + j)*DM + d];
    else        val = x[(b*QN + (j - MN))*DM + d];
    mem[idx] = __float2half_rn(val);
}

// ---------------- fp16 tensor-core GEMM, 4-stage cp.async, 2 CTAs/SM -------
// C[N,K] = A[N,D] @ W[D,K]; Bt = W^T as half [K, D] row-major.
// A is half [N, D]. N,K mult of 128, D mult of 16.
#define STG    4
#define ROWU   12                      // uints per smem row (8 pairs + 4 pad)
#define TILE_U (128*ROWU)              // uints per tile
#define STAGE_U (2*TILE_U)
#define MM_SMEM (STG*STAGE_U*4)

template<bool GELU, bool HOUT>
__global__ __launch_bounds__(256, 2)
void mm_h(const __half* __restrict__ A, const __half* __restrict__ Bt,
          const float* __restrict__ bias, void* __restrict__ Cout,
          int N, int D, int K) {
    extern __shared__ uint32_t smu[];
    const uint32_t sb = smem_u32(smu);

    const int tid  = threadIdx.x;
    const int row0 = blockIdx.y * 128, col0 = blockIdx.x * 128;
    const int lane = tid & 31, wid = tid >> 5;
    const int grp  = lane >> 2, t4 = lane & 3;
    const int wm   = (wid & 3) * 32, wn = (wid >> 2) * 64;

    // loader: thread handles one 16B chunk of A and one of B per stage
    const int lrow = tid >> 1;          // 0..127
    const int lseg = tid & 1;           // 0..1 (8-half segment)
    const __half* Ag = A  + (size_t)(row0 + lrow) * D + lseg * 8;
    const __half* Bg = Bt + (size_t)(col0 + lrow) * D + lseg * 8;
    const uint32_t dstA = sb + (lrow*ROWU + lseg*4) * 4;
    const uint32_t dstB = dstA + TILE_U*4;

    const int KT = D >> 4;

    float c[2][8][4];
    #pragma unroll
    for (int i = 0; i < 2; i++)
        #pragma unroll
        for (int j = 0; j < 8; j++)
            #pragma unroll
            for (int t = 0; t < 4; t++) c[i][j][t] = 0.0f;

    #pragma unroll
    for (int s = 0; s < STG-1; s++) {
        cp16(dstA + s*STAGE_U*4, Ag + (size_t)s*16);
        cp16(dstB + s*STAGE_U*4, Bg + (size_t)s*16);
        CP_COMMIT();
    }

    for (int kt = 0; kt < KT; kt++) {
        asm volatile("cp.async.wait_group 2;\n" ::);
        __syncthreads();
        const int st = kt & (STG-1);
        const uint32_t* AsU = smu + st*STAGE_U;
        const uint32_t* BsU = AsU + TILE_U;

        uint32_t af[2][4], bf[8][2];
        #pragma unroll
        for (int mt = 0; mt < 2; mt++) {
            const int m = wm + mt*16 + grp;
            af[mt][0] = AsU[(m  )*ROWU + t4    ];
            af[mt][1] = AsU[(m+8)*ROWU + t4    ];
            af[mt][2] = AsU[(m  )*ROWU + t4 + 4];
            af[mt][3] = AsU[(m+8)*ROWU + t4 + 4];
        }
        #pragma unroll
        for (int nt = 0; nt < 8; nt++) {
            const int n = wn + nt*8 + grp;
            bf[nt][0] = BsU[n*ROWU + t4    ];
            bf[nt][1] = BsU[n*ROWU + t4 + 4];
        }

        // refill stage kt+3 (slot consumed at iter kt-1; all threads past sync)
        const int kn = kt + STG - 1;
        if (kn < KT) {
            const int sn = kn & (STG-1);
            cp16(dstA + sn*STAGE_U*4, Ag + (size_t)kn*16);
            cp16(dstB + sn*STAGE_U*4, Bg + (size_t)kn*16);
        }
        CP_COMMIT();

        #pragma unroll
        for (int mt = 0; mt < 2; mt++)
            #pragma unroll
            for (int nt = 0; nt < 8; nt++)
                MMA_F16(c[mt][nt], af[mt][0], af[mt][1], af[mt][2], af[mt][3],
                        bf[nt][0], bf[nt][1]);
    }

    #pragma unroll
    for (int mt = 0; mt < 2; mt++)
        #pragma unroll
        for (int nt = 0; nt < 8; nt++) {
            int r  = row0 + wm + mt*16 + grp;
            int cc = col0 + wn + nt*8 + t4*2;
            #pragma unroll
            for (int half = 0; half < 2; half++) {
                int rr = r + half*8;
                float v0 = c[mt][nt][half*2 + 0];
                float v1 = c[mt][nt][half*2 + 1];
                if (bias) { v0 += bias[cc]; v1 += bias[cc+1]; }
                if (GELU) {
                    v0 = 0.5f*v0*(1.0f + erff(v0*0.70710678118654752f));
                    v1 = 0.5f*v1*(1.0f + erff(v1*0.70710678118654752f));
                }
                if (HOUT) {
                    __half* Ch = (__half*)Cout;
                    *(__half2*)&Ch[(size_t)rr*K + cc] = __floats2half2_rn(v0, v1);
                } else {
                    float* Cf = (float*)Cout;
                    *(float2*)&Cf[(size_t)rr*K + cc] = make_float2(v0, v1);
                }
            }
        }
}

// ---------------- BD_raw via tensor cores (tf32; half inputs) --------------
#define RS_STRIDE 68
__global__ __launch_bounds__(256)
void bd_mma(const __half* __restrict__ q, int qrs, size_t qbs,
            const __half* __restrict__ r, int rrs,
            const float* __restrict__ vvec, float* __restrict__ bdout) {
    __shared__ float Rs[64*RS_STRIDE];
    const int t0 = blockIdx.x * 64;
    const int i0 = blockIdx.y * 128;
    const int h = blockIdx.z & (HN-1), b = blockIdx.z >> 4;
    const int tid = threadIdx.x;
    const int lane = tid & 31, wid = tid >> 5;
    const int grp = lane >> 2, t4 = lane & 3;
    const int i_r0 = i0 + wid*16 + grp, i_r1 = i_r0 + 8;

    unsigned qf[8][4];
    {
        const __half* qp0 = q + (size_t)b*qbs + (size_t)i_r0*qrs + h*DH;
        const __half* qp1 = q + (size_t)b*qbs + (size_t)i_r1*qrs + h*DH;
        const float* up  = vvec + h*DH;
        #pragma unroll
        for (int ks = 0; ks < 8; ks++) {
            int k0 = ks*8 + t4;
            float u0 = up[k0], u1 = up[k0+4];
            qf[ks][0] = f2tf(__half2float(qp0[k0])   + u0);
            qf[ks][1] = f2tf(__half2float(qp1[k0])   + u0);
            qf[ks][2] = f2tf(__half2float(qp0[k0+4]) + u1);
            qf[ks][3] = f2tf(__half2float(qp1[k0+4]) + u1);
        }
    }
    #pragma unroll
    for (int t = 0; t < 2; t++) {
        int idx = tid + 256*t;
        int row = idx >> 3, c8 = (idx & 7) * 8;
        uint4 rv = *(const uint4*)&r[(size_t)(t0 + row)*rrs + h*DH + c8];
        float* rd = Rs + row*RS_STRIDE + c8;
        float2 f0 = __half22float2(*(__half2*)&rv.x);
        float2 f1 = __half22float2(*((__half2*)&rv.x + 1));
        float2 f2 = __half22float2(*(__half2*)&rv.z);
        float2 f3 = __half22float2(*((__half2*)&rv.z + 1));
        rd[0]=f0.x; rd[1]=f0.y; rd[2]=f1.x; rd[3]=f1.y;
        rd[4]=f2.x; rd[5]=f2.y; rd[6]=f3.x; rd[7]=f3.y;
    }
    __syncthreads();

    float s[8][4];
    #pragma unroll
    for (int nt = 0; nt < 8; nt++)
        #pragma unroll
        for (int e = 0; e < 4; e++) s[nt][e] = 0.0f;

    #pragma unroll
    for (int ks = 0; ks < 8; ks++)
        #pragma unroll
        for (int nt = 0; nt < 8; nt++) {
            unsigned b0 = __float_as_uint(Rs[(nt*8+grp)*RS_STRIDE + ks*8 + t4]);
            unsigned b1 = __float_as_uint(Rs[(nt*8+grp)*RS_STRIDE + ks*8 + t4 + 4]);
            MMA_TF32(s[nt], qf[ks], b0, b1);
        }

    float* o0 = bdout + (((size_t)(b*HN + h))*QN + i_r0)*KLEN + t0;
    float* o1 = bdout + (((size_t)(b*HN + h))*QN + i_r1)*KLEN + t0;
    #pragma unroll
    for (int nt = 0; nt < 8; nt++) {
        int cc = nt*8 + 2*t4;
        *(float2*)&o0[cc] = make_float2(s[nt][0], s[nt][1]);
        *(float2*)&o1[cc] = make_float2(s[nt][2], s[nt][3]);
    }
}

// ---------------- MMA flash attention (tf32 core; half in/out) -------------
#define KS_STRIDE 68
#define VS_STRIDE 72
#define PS_STRIDE 68
#define FLASH_SMEM ((64*KS_STRIDE + 64*VS_STRIDE + 128*PS_STRIDE) * 4)

__global__ __launch_bounds__(256)
void flashmma(const __half* __restrict__ q, int qrs, size_t qbs,
              const __half* __restrict__ k, const __half* __restrict__ v,
              int kvrs, size_t kvbs,
              const float* __restrict__ bd, const float* __restrict__ uvec,
              __half* __restrict__ out, int klen, int useMask) {
    extern __shared__ float sm[];
    float* Ks = sm;
    float* Vs = Ks + 64*KS_STRIDE;
    float* Ps = Vs + 64*VS_STRIDE;

    const int i0 = blockIdx.x * 128;
    const int h = blockIdx.y, b = blockIdx.z;
    const int tid = threadIdx.x;
    const int lane = tid & 31, wid = tid >> 5;
    const int grp = lane >> 2, t4 = lane & 3;
    const int r0 = wid*16 + grp, r1 = r0 + 8;
    const int i_r0 = i0 + r0, i_r1 = i0 + r1;

    unsigned qf[8][4];
    {
        const __half* qp0 = q + (size_t)b*qbs + (size_t)i_r0*qrs + h*DH;
        const __half* qp1 = q + (size_t)b*qbs + (size_t)i_r1*qrs + h*DH;
        #pragma unroll
        for (int ks = 0; ks < 8; ks++) {
            int k0 = ks*8 + t4;
            float u0 = uvec ? uvec[h*DH + k0]     : 0.0f;
            float u1 = uvec ? uvec[h*DH + k0 + 4] : 0.0f;
            qf[ks][0] = f2tf(__half2float(qp0[k0])   + u0);
            qf[ks][1] = f2tf(__half2float(qp1[k0])   + u0);
            qf[ks][2] = f2tf(__half2float(qp0[k0+4]) + u1);
            qf[ks][3] = f2tf(__half2float(qp1[k0+4]) + u1);
        }
    }

    float m0 = -INFINITY, m1 = -INFINITY, l0 = 0.0f, l1 = 0.0f;
    float o[8][4];
    #pragma unroll
    for (int nt = 0; nt < 8; nt++)
        #pragma unroll
        for (int e = 0; e < 4; e++) o[nt][e] = 0.0f;

    const float* bdr0 = bd ? bd + (((size_t)(b*HN + h))*QN + i_r0)*KLEN : (const float*)0;
    const float* bdr1 = bd ? bd + (((size_t)(b*HN + h))*QN + i_r1)*KLEN : (const float*)0;

    int lastj = klen - 1;
    if (useMask) { int lm = i0 + 127 + MN; if (lm < lastj) lastj = lm; }

    for (int j0 = 0; j0 <= lastj; j0 += 64) {
        __syncthreads();
        #pragma unroll
        for (int t = 0; t < 2; t++) {
            int idx = tid + 256*t;
            int row = idx >> 3, c8 = (idx & 7) * 8;
            size_t gb = (size_t)b*kvbs + (size_t)(j0 + row)*kvrs + h*DH + c8;
            uint4 kv = *(const uint4*)&k[gb];
            uint4 vv = *(const uint4*)&v[gb];
            float* kd = Ks + row*KS_STRIDE + c8;
            float* vd = Vs + row*VS_STRIDE + c8;
            {
                float2 f0 = __half22float2(*(__half2*)&kv.x);
                float2 f1 = __half22float2(*((__half2*)&kv.x + 1));
                float2 f2 = __half22float2(*(__half2*)&kv.z);
                float2 f3 = __half22float2(*((__half2*)&kv.z + 1));
                kd[0]=f0.x; kd[1]=f0.y; kd[2]=f1.x; kd[3]=f1.y;
                kd[4]=f2.x; kd[5]=f2.y; kd[6]=f3.x; kd[7]=f3.y;
            }
            {
                float2 f0 = __half22float2(*(__half2*)&vv.x);
                float2 f1 = __half22float2(*((__half2*)&vv.x + 1));
                float2 f2 = __half22float2(*(__half2*)&vv.z);
                float2 f3 = __half22float2(*((__half2*)&vv.z + 1));
                vd[0]=f0.x; vd[1]=f0.y; vd[2]=f1.x; vd[3]=f1.y;
                vd[4]=f2.x; vd[5]=f2.y; vd[6]=f3.x; vd[7]=f3.y;
            }
        }
        __syncthreads();

        float bdv[8][4];
        if (bd) {
            #pragma unroll
            for (int nt = 0; nt < 8; nt++) {
                int jA = j0 + nt*8 + 2*t4;
                int jr0 = jA - i_r0 + (QN-1);
                int jr1 = jA - i_r1 + (QN-1);
                jr0 = max(0, min(KLEN-2, jr0));
                jr1 = max(0, min(KLEN-2, jr1));
                bdv[nt][0] = bdr0[jr0];   bdv[nt][1] = bdr0[jr0+1];
                bdv[nt][2] = bdr1[jr1];   bdv[nt][3] = bdr1[jr1+1];
            }
        }

        float s[8][4];
        #pragma unroll
        for (int nt = 0; nt < 8; nt++)
            #pragma unroll
            for (int e = 0; e < 4; e++) s[nt][e] = 0.0f;
        #pragma unroll
        for (int ks = 0; ks < 8; ks++)
            #pragma unroll
            for (int nt = 0; nt < 8; nt++) {
                unsigned b0 = __float_as_uint(Ks[(nt*8+grp)*KS_STRIDE + ks*8 + t4]);
                unsigned b1 = __float_as_uint(Ks[(nt*8+grp)*KS_STRIDE + ks*8 + t4 + 4]);
                MMA_TF32(s[nt], qf[ks], b0, b1);
            }

        float mc0 = -INFINITY, mc1 = -INFINITY;
        #pragma unroll
        for (int nt = 0; nt < 8; nt++) {
            int jA = j0 + nt*8 + 2*t4;
            int jB = jA + 1;
            float v0 = s[nt][0], v1 = s[nt][1], v2 = s[nt][2], v3 = s[nt][3];
            if (bd) { v0 += bdv[nt][0]; v1 += bdv[nt][1]; v2 += bdv[nt][2]; v3 += bdv[nt][3]; }
            v0 *= 0.125f; v1 *= 0.125f; v2 *= 0.125f; v3 *= 0.125f;
            if (useMask) {
                if (jA > i_r0 + MN) v0 = -INFINITY;
                if (jB > i_r0 + MN) v1 = -INFINITY;
                if (jA > i_r1 + MN) v2 = -INFINITY;
                if (jB > i_r1 + MN) v3 = -INFINITY;
            }
            s[nt][0]=v0; s[nt][1]=v1; s[nt][2]=v2; s[nt][3]=v3;
            mc0 = fmaxf(mc0, fmaxf(v0, v1));
            mc1 = fmaxf(mc1, fmaxf(v2, v3));
        }
        mc0 = fmaxf(mc0, __shfl_xor_sync(0xffffffffu, mc0, 1));
        mc0 = fmaxf(mc0, __shfl_xor_sync(0xffffffffu, mc0, 2));
        mc1 = fmaxf(mc1, __shfl_xor_sync(0xffffffffu, mc1, 1));
        mc1 = fmaxf(mc1, __shfl_xor_sync(0xffffffffu, mc1, 2));

        float nm0 = fmaxf(m0, mc0), nm1 = fmaxf(m1, mc1);
        float corr0 = __expf(m0 - nm0), corr1 = __expf(m1 - nm1);
        float ps0 = 0.0f, ps1 = 0.0f;
        #pragma unroll
        for (int nt = 0; nt < 8; nt++) {
            float p0 = __expf(s[nt][0] - nm0);
            float p1 = __expf(s[nt][1] - nm0);
            float p2 = __expf(s[nt][2] - nm1);
            float p3 = __expf(s[nt][3] - nm1);
            ps0 += p0 + p1; ps1 += p2 + p3;
            int cc = nt*8 + 2*t4;
            Ps[r0*PS_STRIDE + cc]     = __uint_as_float(f2tf(p0));
            Ps[r0*PS_STRIDE + cc + 1] = __uint_as_float(f2tf(p1));
            Ps[r1*PS_STRIDE + cc]     = __uint_as_float(f2tf(p2));
            Ps[r1*PS_STRIDE + cc + 1] = __uint_as_float(f2tf(p3));
        }
        ps0 += __shfl_xor_sync(0xffffffffu, ps0, 1);
        ps0 += __shfl_xor_sync(0xffffffffu, ps0, 2);
        ps1 += __shfl_xor_sync(0xffffffffu, ps1, 1);
        ps1 += __shfl_xor_sync(0xffffffffu, ps1, 2);
        l0 = l0 * corr0 + ps0;  m0 = nm0;
        l1 = l1 * corr1 + ps1;  m1 = nm1;
        #pragma unroll
        for (int nt = 0; nt < 8; nt++) {
            o[nt][0] *= corr0; o[nt][1] *= corr0;
            o[nt][2] *= corr1; o[nt][3] *= corr1;
        }
        __syncwarp();

        #pragma unroll
        for (int ks = 0; ks < 8; ks++) {
            unsigned a[4];
            a[0] = __float_as_uint(Ps[r0*PS_STRIDE + ks*8 + t4]);
            a[1] = __float_as_uint(Ps[r1*PS_STRIDE + ks*8 + t4]);
            a[2] = __float_as_uint(Ps[r0*PS_STRIDE + ks*8 + t4 + 4]);
            a[3] = __float_as_uint(Ps[r1*PS_STRIDE + ks*8 + t4 + 4]);
            #pragma unroll
            for (int nt = 0; nt < 8; nt++) {
                unsigned b0 = __float_as_uint(Vs[(ks*8+t4)*VS_STRIDE + nt*8 + grp]);
                unsigned b1 = __float_as_uint(Vs[(ks*8+t4+4)*VS_STRIDE + nt*8 + grp]);
                MMA_TF32(o[nt], a, b0, b1);
            }
        }
    }

    const float inv0 = 1.0f / l0, inv1 = 1.0f / l1;
    __half* op0 = out + ((size_t)(b*QN + i_r0))*DM + h*DH;
    __half* op1 = out + ((size_t)(b*QN + i_r1))*DM + h*DH;
    #pragma unroll
    for (int nt = 0; nt < 8; nt++) {
        int cc = nt*8 + 2*t4;
        *(__half2*)&op0[cc] = __floats2half2_rn(o[nt][0]*inv0, o[nt][1]*inv0);
        *(__half2*)&op1[cc] = __floats2half2_rn(o[nt][2]*inv1, o[nt][3]*inv1);
    }
}

// ------- residual add + LayerNorm: x=full fp32, xh=half copy ---------------
__global__ __launch_bounds__(256)
void ln_kernel(float* __restrict__ x, __half* __restrict__ xh,
               const float* __restrict__ y,
               const float* __restrict__ gamma, const float* __restrict__ beta) {
    const int row = blockIdx.x;
    const int tid = threadIdx.x;
    __shared__ float red[256];

    float s[4];
    float local = 0.0f;
    #pragma unroll
    for (int kk = 0; kk < 4; kk++) {
        int c = tid + kk*256;
        float val = x[(size_t)row*DM + c] + y[(size_t)row*DM + c];
        s[kk] = val;
        local += val;
    }
    red[tid] = local;
    __syncthreads();
    for (int t = 128; t > 0; t >>= 1) {
        if (tid < t) red[tid] += red[tid+t];
        __syncthreads();
    }
    const float mu = red[0] * (1.0f / DM);
    __syncthreads();

    local = 0.0f;
    #pragma unroll
    for (int kk = 0; kk < 4; kk++) {
        float dlt = s[kk] - mu;
        local += dlt * dlt;
    }
    red[tid] = local;
    __syncthreads();
    for (int t = 128; t > 0; t >>= 1) {
        if (tid < t) red[tid] += red[tid+t];
        __syncthreads();
    }
    const float rstd = rsqrtf(red[0] * (1.0f / DM) + 1e-5f);
    __syncthreads();

    #pragma unroll
    for (int kk = 0; kk < 4; kk++) {
        int c = tid + kk*256;
        float val = (s[kk] - mu) * rstd * gamma[c] + beta[c];
        x [(size_t)row*DM + c] = val;
        xh[(size_t)row*DM + c] = __float2half_rn(val);
    }
}

// ---------------- host orchestration ----------------
static inline void run_gemm(const __half* A, const __half* Bt, const float* bias,
                            void* C, int N, int D, int K, bool gelu, bool hout) {
    dim3 grid(K/128, N/128);
    if (gelu)      mm_h<true , true ><<<grid, 256, MM_SMEM>>>(A, Bt, bias, C, N, D, K);
    else if (hout) mm_h<false, true ><<<grid, 256, MM_SMEM>>>(A, Bt, bias, C, N, D, K);
    else           mm_h<false, false><<<grid, 256, MM_SMEM>>>(A, Bt, bias, C, N, D, K);
}

extern "C" void kernel_launch(void* const* d_in, const int* in_sizes, int n_in,
                              void* d_out, int out_size) {
    const float* enc    = (const float*)d_in[0];
    const float* mems   = (const float*)d_in[1];
    const float* emb    = (const float*)d_in[2];
    const float* u      = (const float*)d_in[3];
    const float* vpar   = (const float*)d_in[4];
    const float* saWq   = (const float*)d_in[5];
    const float* saWk   = (const float*)d_in[6];
    const float* saWv   = (const float*)d_in[7];
    const float* saWr   = (const float*)d_in[8];
    const float* safcW  = (const float*)d_in[9];
    const float* safcB  = (const float*)d_in[10];
    const float* ln1g   = (const float*)d_in[11];
    const float* ln1b   = (const float*)d_in[12];
    const float* caWq   = (const float*)d_in[13];
    const float* caWk   = (const float*)d_in[14];
    const float* caWv   = (const float*)d_in[15];
    const float* cafcW  = (const float*)d_in[16];
    const float* cafcB  = (const float*)d_in[17];
    const float* ln2g   = (const float*)d_in[18];
    const float* ln2b   = (const float*)d_in[19];
    const float* ffW1   = (const float*)d_in[20];
    const float* ffb1   = (const float*)d_in[21];
    const float* ffW2   = (const float*)d_in[22];
    const float* ffb2   = (const float*)d_in[23];
    const float* ln3g   = (const float*)d_in[24];
    const float* ln3b   = (const float*)d_in[25];
    const float* outW   = (const float*)d_in[26];
    const int*   ids    = (const int*)  d_in[27];
    float* out = (float*)d_out;

    float *x, *tmp, *bdb;
    __half *hxh, *hmem, *hqkv, *hcakv, *hr4, *hatt, *hq, *hff, *hremb, *henc;
    __half *wqkvh, *wcakvh, *wr4h, *wsafch, *wcafch, *wcaqh, *wff1h, *wff2h, *wouth;
    cudaGetSymbolAddress((void**)&x,      g_x);
    cudaGetSymbolAddress((void**)&tmp,    g_tmp);
    cudaGetSymbolAddress((void**)&bdb,    g_bd);
    cudaGetSymbolAddress((void**)&hxh,    g_hxh);
    cudaGetSymbolAddress((void**)&hmem,   g_hmem);
    cudaGetSymbolAddress((void**)&hqkv,   g_hqkv);
    cudaGetSymbolAddress((void**)&hcakv,  g_hcakv);
    cudaGetSymbolAddress((void**)&hr4,    g_hr4);
    cudaGetSymbolAddress((void**)&hatt,   g_hatt);
    cudaGetSymbolAddress((void**)&hq,     g_hq);
    cudaGetSymbolAddress((void**)&hff,    g_hff);
    cudaGetSymbolAddress((void**)&hremb,  g_hremb);
    cudaGetSymbolAddress((void**)&henc,   g_henc);
    cudaGetSymbolAddress((void**)&wqkvh,  g_wqkv);
    cudaGetSymbolAddress((void**)&wcakvh, g_wcakv);
    cudaGetSymbolAddress((void**)&wr4h,   g_wr4);
    cudaGetSymbolAddress((void**)&wsafch, g_wsafc);
    cudaGetSymbolAddress((void**)&wcafch, g_wcafc);
    cudaGetSymbolAddress((void**)&wcaqh,  g_wcaq);
    cudaGetSymbolAddress((void**)&wff1h,  g_wff1);
    cudaGetSymbolAddress((void**)&wff2h,  g_wff2);
    cudaGetSymbolAddress((void**)&wouth,  g_wout);

    static int smem_set = 0;
    if (!smem_set) {
        cudaFuncSetAttribute(flashmma, cudaFuncAttributeMaxDynamicSharedMemorySize,
                             FLASH_SMEM);
        cudaFuncSetAttribute((mm_h<true , true >), cudaFuncAttributeMaxDynamicSharedMemorySize, MM_SMEM);
        cudaFuncSetAttribute((mm_h<false, true >), cudaFuncAttributeMaxDynamicSharedMemorySize, MM_SMEM);
        cudaFuncSetAttribute((mm_h<false, false>), cudaFuncAttributeMaxDynamicSharedMemorySize, MM_SMEM);
        smem_set = 1;
    }

    // transposed half weights (Bt = W^T, [n][k] row-major)
    dim3 tb(32, 8);
    trans_half<<<dim3(DM/32, DM/32, LNUM), tb>>>(saWq, wqkvh,                   DM, DM, (size_t)DM*DM, (size_t)3072*DM);
    trans_half<<<dim3(DM/32, DM/32, LNUM), tb>>>(saWk, wqkvh + (size_t)1024*DM, DM, DM, (size_t)DM*DM, (size_t)3072*DM);
    trans_half<<<dim3(DM/32, DM/32, LNUM), tb>>>(saWv, wqkvh + (size_t)2048*DM, DM, DM, (size_t)DM*DM, (size_t)3072*DM);
    trans_half<<<dim3(DM/32, DM/32, LNUM), tb>>>(caWk, wcakvh,                  DM, DM, (size_t)DM*DM, (size_t)2048*DM);
    trans_half<<<dim3(DM/32, DM/32, LNUM), tb>>>(caWv, wcakvh + (size_t)1024*DM,DM, DM, (size_t)DM*DM, (size_t)2048*DM);
    trans_half<<<dim3(DM/32, DM/32, LNUM), tb>>>(saWr,  wr4h + 0,  DM, DM, (size_t)DM*DM, (size_t)DM*DM);
    trans_half<<<dim3(DM/32, DM/32, LNUM), tb>>>(safcW, wsafch, DM, DM, (size_t)DM*DM, (size_t)DM*DM);
    trans_half<<<dim3(DM/32, DM/32, LNUM), tb>>>(cafcW, wcafch, DM, DM, (size_t)DM*DM, (size_t)DM*DM);
    trans_half<<<dim3(DM/32, DM/32, LNUM), tb>>>(caWq,  wcaqh,  DM, DM, (size_t)DM*DM, (size_t)DM*DM);
    trans_half<<<dim3(FFN/32, DM/32, LNUM), tb>>>(ffW1, wff1h,  DM, FFN, (size_t)DM*FFN, (size_t)DM*FFN);
    trans_half<<<dim3(DM/32, FFN/32, LNUM), tb>>>(ffW2, wff2h,  FFN, DM, (size_t)DM*FFN, (size_t)DM*FFN);
    trans_half<<<dim3(VN/32, DM/32, 1),     tb>>>(outW, wouth,  DM, VN, 0, 0);
    half_copy<<<((BN*EN*DM/4) + 255)/256, 256>>>(enc, henc, BN*EN*DM/4);

    embed_kernel<<<(BN*QN*DM + 255)/256, 256>>>(ids, emb, x);
    remb_kernel <<<(KLEN*DM + 255)/256, 256>>>(hremb);

    // layer-independent projections (fused across layers)
    run_gemm(hremb, wr4h,   nullptr, hr4,   KLEN,  DM, 4096, false, true);
    run_gemm(henc,  wcakvh, nullptr, hcakv, BN*EN, DM, 8192, false, true);

    dim3 flash_grid(QN/128, HN, BN);
    dim3 bd_grid(KLEN/64, QN/128, BN*HN);

    for (int l = 0; l < LNUM; l++) {
        // ---- self-attention (TransformerXL relative) ----
        concat_kernel<<<(BN*KLEN*DM + 255)/256, 256>>>(
            mems + (size_t)l*BN*MN*DM, x, hmem);

        run_gemm(hmem, wqkvh + (size_t)l*3072*DM, nullptr, hqkv,
                 BN*KLEN, DM, 3072, false, true);

        const __half* qself = hqkv + (size_t)MN*3072;
        bd_mma<<<bd_grid, 256>>>(qself, 3072, (size_t)KLEN*3072,
                                 hr4 + (size_t)l*1024, 4096, vpar, bdb);
        flashmma<<<flash_grid, 256, FLASH_SMEM>>>(
            qself, 3072, (size_t)KLEN*3072,
            hqkv + 1024, hqkv + 2048, 3072, (size_t)KLEN*3072,
            bdb, u, hatt, KLEN, 1);

        run_gemm(hatt, wsafch + (size_t)l*DM*DM, safcB + (size_t)l*DM,
                 tmp, BN*QN, DM, DM, false, false);
        ln_kernel<<<BN*QN, 256>>>(x, hxh, tmp, ln1g + (size_t)l*DM, ln1b + (size_t)l*DM);

        // ---- cross-attention ----
        run_gemm(hxh, wcaqh + (size_t)l*DM*DM, nullptr, hq, BN*QN, DM, DM, false, true);

        flashmma<<<flash_grid, 256, FLASH_SMEM>>>(
            hq, DM, (size_t)QN*DM,
            hcakv + (size_t)l*2048, hcakv + (size_t)l*2048 + 1024,
            8192, (size_t)EN*8192,
            nullptr, nullptr, hatt, EN, 0);

        run_gemm(hatt, wcafch + (size_t)l*DM*DM, cafcB + (size_t)l*DM,
                 tmp, BN*QN, DM, DM, false, false);
        ln_kernel<<<BN*QN, 256>>>(x, hxh, tmp, ln2g + (size_t)l*DM, ln2b + (size_t)l*DM);

        // ---- feed-forward ----
        run_gemm(hxh, wff1h + (size_t)l*DM*FFN, ffb1 + (size_t)l*FFN,
                 hff, BN*QN, DM, FFN, true, true);
        run_gemm(hff, wff2h + (size_t)l*DM*FFN, ffb2 + (size_t)l*DM,
                 tmp, BN*QN, FFN, DM, false, false);
        ln_kernel<<<BN*QN, 256>>>(x, hxh, tmp, ln3g + (size_t)l*DM, ln3b + (size_t)l*DM);
    }

    // ---- output projection ----
    run_gemm(hxh, wouth, nullptr, out, BN*QN, DM, VN, false, false);
}